// round 9
// baseline (speedup 1.0000x reference)
#include <cuda_runtime.h>
#include <cstdint>

// Problem constants
#define B_    2
#define NSEQ  2048
#define DIM_  1024
#define H_    16
#define HD_   64
#define SCALE_F 0.125f   // HD^-0.5

// ---------------------------------------------------------------------------
// Packed split storage: uint32 = {bf16 elem k (low), bf16 elem k+1 (high)}.
// hi = top16 of fp32; lo = bf16(x - hi).  A*B ~= Ah*Bh + Ah*Bl + Al*Bh.
// ---------------------------------------------------------------------------
__device__ __align__(16) uint32_t g_xh [4096*512], g_xl [4096*512];
__device__ __align__(16) uint32_t g_Wqh[3072*512], g_Wql[3072*512];
__device__ __align__(16) uint32_t g_Wph[1024*512], g_Wpl[1024*512];
#define QKV_W (B_*H_*NSEQ*32)
__device__ __align__(16) uint32_t g_Qh[QKV_W], g_Ql[QKV_W];
__device__ __align__(16) uint32_t g_Kh[QKV_W], g_Kl[QKV_W];
__device__ __align__(16) uint32_t g_Vh[QKV_W], g_Vl[QKV_W];
__device__ __align__(16) uint32_t g_AOh[4096*512], g_AOl[4096*512];

// ---------------------------------------------------------------------------
__device__ __forceinline__ uint32_t packhi2(float x, float y) {
    return __byte_perm(__float_as_uint(x), __float_as_uint(y), 0x7632);
}
__device__ __forceinline__ uint32_t packlo2(float x, float y) {
    float lx = x - __uint_as_float(__float_as_uint(x) & 0xffff0000u);
    float ly = y - __uint_as_float(__float_as_uint(y) & 0xffff0000u);
    return __byte_perm(__float_as_uint(lx), __float_as_uint(ly), 0x7632);
}
__device__ __forceinline__ uint32_t smem_u32(const void* p) {
    uint32_t a;
    asm("{ .reg .u64 t; cvta.to.shared.u64 t, %1; cvt.u32.u64 %0, t; }" : "=r"(a) : "l"(p));
    return a;
}
__device__ __forceinline__ void cp16(uint32_t s, const void* g) {
    asm volatile("cp.async.cg.shared.global [%0], [%1], 16;" :: "r"(s), "l"(g));
}
#define CP_COMMIT() asm volatile("cp.async.commit_group;" ::: "memory")
#define CP_WAIT1()  asm volatile("cp.async.wait_group 1;" ::: "memory")
#define CP_WAIT0()  asm volatile("cp.async.wait_group 0;" ::: "memory")

__device__ __forceinline__ void mma16(float* c, const uint32_t* a, const uint32_t* b) {
    asm("mma.sync.aligned.m16n8k16.row.col.f32.bf16.bf16.f32 "
        "{%0,%1,%2,%3}, {%4,%5,%6,%7}, {%8,%9}, {%0,%1,%2,%3};"
        : "+f"(c[0]), "+f"(c[1]), "+f"(c[2]), "+f"(c[3])
        : "r"(a[0]), "r"(a[1]), "r"(a[2]), "r"(a[3]), "r"(b[0]), "r"(b[1]));
}
__device__ __forceinline__ void ldmx4(uint32_t* r, uint32_t a) {
    asm volatile("ldmatrix.sync.aligned.m8n8.x4.shared.b16 {%0,%1,%2,%3}, [%4];"
        : "=r"(r[0]), "=r"(r[1]), "=r"(r[2]), "=r"(r[3]) : "r"(a));
}
__device__ __forceinline__ void ldmx4t(uint32_t* r, uint32_t a) {
    asm volatile("ldmatrix.sync.aligned.m8n8.x4.trans.shared.b16 {%0,%1,%2,%3}, [%4];"
        : "=r"(r[0]), "=r"(r[1]), "=r"(r[2]), "=r"(r[3]) : "r"(a));
}
// XOR swizzles (word offsets). Conflict-free per ldmatrix 8-row phase.
__device__ __forceinline__ int sw16(int r, int c) { return r * 16 + 4 * (c ^ ((r >> 1) & 3)); }
__device__ __forceinline__ int sw32(int r, int c) { return r * 32 + 4 * (c ^ (r & 7)); }

// ---------------------------------------------------------------------------
// Prep: split fp32 tensor into packed hi/lo arrays. which: 0=x 1=Wqkv 2=Wproj.
// ---------------------------------------------------------------------------
__global__ __launch_bounds__(256)
void split_kernel(const float4* __restrict__ src, int which, int n4)
{
    uint2 *h, *l;
    if (which == 0)      { h = (uint2*)g_xh;  l = (uint2*)g_xl;  }
    else if (which == 1) { h = (uint2*)g_Wqh; l = (uint2*)g_Wql; }
    else                 { h = (uint2*)g_Wph; l = (uint2*)g_Wpl; }
    int i = blockIdx.x * 256 + threadIdx.x;
    if (i < n4) {
        float4 v = src[i];
        h[i] = make_uint2(packhi2(v.x, v.y), packhi2(v.z, v.w));
        l[i] = make_uint2(packlo2(v.x, v.y), packlo2(v.z, v.w));
    }
}

// ---------------------------------------------------------------------------
// Split-bf16 GEMM on pre-split packed inputs. All 12 fragment ldmatrix
// batched at the top of each ks block -> 48 uninterrupted mmas.
// ---------------------------------------------------------------------------
#define GARRW 2048
#define GBUFW (4*GARRW)
#define GEMM_SMEM (3*GBUFW*4)   // 98304 B

template<int MODE>
__global__ __launch_bounds__(256, 2)
void tc_gemm(const float* __restrict__ bias, float* __restrict__ C)
{
    extern __shared__ __align__(16) uint32_t smu[];
    const uint32_t sb = smem_u32(smu);

    const uint32_t *Ah, *Al, *Bh, *Bl;
    if (MODE == 0) { Ah = g_xh;  Al = g_xl;  Bh = g_Wqh; Bl = g_Wql; }
    else           { Ah = g_AOh; Al = g_AOl; Bh = g_Wph; Bl = g_Wpl; }

    const int tid = threadIdx.x, wid = tid >> 5, lane = tid & 31;
    const int g = lane >> 2, tg = lane & 3;
    const int wm = wid >> 2, wn = wid & 3;
    const int row0 = blockIdx.y * 128, col0 = blockIdx.x * 128;

    const int rA = wm * 64 + (lane & 15);
    const int selA = lane >> 4;
    const int rB = wn * 32 + (lane & 7) + ((lane >> 4) << 3);
    const int selB = (lane >> 3) & 1;

    float c[4][4][4];
#pragma unroll
    for (int mt = 0; mt < 4; mt++)
#pragma unroll
        for (int nt = 0; nt < 4; nt++) {
            c[mt][nt][0] = 0.f; c[mt][nt][1] = 0.f; c[mt][nt][2] = 0.f; c[mt][nt][3] = 0.f;
        }

    const int lr = tid >> 1, half = tid & 1;
    auto cpload = [&](int ch, int buf) {
        const uint32_t bo = (uint32_t)buf * GBUFW;
        const size_t aw = (size_t)(row0 + lr) * 512 + ch * 16 + half * 8;
        const size_t bw = (size_t)(col0 + lr) * 512 + ch * 16 + half * 8;
#pragma unroll
        for (int j = 0; j < 2; j++) {
            uint32_t d = bo + sw16(lr, half * 2 + j);
            cp16(sb + 4 * d,                Ah + aw + 4 * j);
            cp16(sb + 4 * (d + GARRW),      Al + aw + 4 * j);
            cp16(sb + 4 * (d + 2 * GARRW),  Bh + bw + 4 * j);
            cp16(sb + 4 * (d + 3 * GARRW),  Bl + bw + 4 * j);
        }
    };

    cpload(0, 0); CP_COMMIT();
    cpload(1, 1); CP_COMMIT();

    for (int ch = 0; ch < 32; ch++) {
        CP_WAIT1();
        __syncthreads();
        if (ch + 2 < 32) cpload(ch + 2, (ch + 2) % 3);
        CP_COMMIT();

        const uint32_t bufb = sb + 4u * (uint32_t)((ch % 3) * GBUFW);
#pragma unroll
        for (int ks = 0; ks < 2; ks++) {
            const int cA = 2 * ks + selA;
            const int cB = 2 * ks + selB;
            // ---- ALL fragment loads upfront (12 ldmx4) ----
            uint32_t ah[4][4], al[4][4], th[2][4], tl[2][4];
#pragma unroll
            for (int mt = 0; mt < 4; mt++) {
                ldmx4(ah[mt], bufb + 4u * (uint32_t)sw16(rA + mt * 16, cA));
                ldmx4(al[mt], bufb + 4u * (uint32_t)(GARRW + sw16(rA + mt * 16, cA)));
            }
#pragma unroll
            for (int ntp = 0; ntp < 2; ntp++) {
                ldmx4(th[ntp], bufb + 4u * (uint32_t)(2 * GARRW + sw16(rB + ntp * 16, cB)));
                ldmx4(tl[ntp], bufb + 4u * (uint32_t)(3 * GARRW + sw16(rB + ntp * 16, cB)));
            }
            // ---- 48 mmas, 16-deep accumulator independence per pass ----
#pragma unroll
            for (int ntp = 0; ntp < 2; ntp++)
#pragma unroll
                for (int mt = 0; mt < 4; mt++) {
                    mma16(c[mt][2*ntp],   ah[mt], &th[ntp][0]);
                    mma16(c[mt][2*ntp+1], ah[mt], &th[ntp][2]);
                }
#pragma unroll
            for (int ntp = 0; ntp < 2; ntp++)
#pragma unroll
                for (int mt = 0; mt < 4; mt++) {
                    mma16(c[mt][2*ntp],   ah[mt], &tl[ntp][0]);
                    mma16(c[mt][2*ntp+1], ah[mt], &tl[ntp][2]);
                }
#pragma unroll
            for (int ntp = 0; ntp < 2; ntp++)
#pragma unroll
                for (int mt = 0; mt < 4; mt++) {
                    mma16(c[mt][2*ntp],   al[mt], &th[ntp][0]);
                    mma16(c[mt][2*ntp+1], al[mt], &th[ntp][2]);
                }
        }
    }

    // Epilogue
#pragma unroll
    for (int mt = 0; mt < 4; mt++) {
#pragma unroll
        for (int hf = 0; hf < 2; hf++) {
            int row = row0 + wm * 64 + mt * 16 + g + hf * 8;
#pragma unroll
            for (int nt = 0; nt < 4; nt++) {
                int col = col0 + wn * 32 + nt * 8 + 2 * tg;
                float v0 = c[mt][nt][hf * 2 + 0] + bias[col];
                float v1 = c[mt][nt][hf * 2 + 1] + bias[col + 1];
                if (MODE == 1) {
                    *(float2*)&C[(size_t)row * DIM_ + col] = make_float2(v0, v1);
                } else {
                    int b = row >> 11, n = row & (NSEQ - 1);
                    int which = col >> 10, rem = col & 1023;
                    int h = rem >> 6, d = rem & 63;
                    size_t w = (((size_t)(b * H_ + h)) * NSEQ + n) * 32 + (d >> 1);
                    if (which == 0) {
                        v0 *= SCALE_F; v1 *= SCALE_F;
                        g_Qh[w] = packhi2(v0, v1); g_Ql[w] = packlo2(v0, v1);
                    } else if (which == 1) {
                        g_Kh[w] = packhi2(v0, v1); g_Kl[w] = packlo2(v0, v1);
                    } else {
                        g_Vh[w] = packhi2(v0, v1); g_Vl[w] = packlo2(v0, v1);
                    }
                }
            }
        }
    }
}

// ---------------------------------------------------------------------------
// Flash focal attention. Q FRAGMENTS HOISTED to registers (loop-invariant);
// P kept in registers; double-buffered K/V; 2 CTAs/SM.
// ---------------------------------------------------------------------------
#define FQH 0
#define FQL 4096
#define FKV 8192
#define FKVB 8192
#define FLASH_SMEM ((8192 + 2*FKVB)*4)   // 98304 B

__global__ __launch_bounds__(256, 2)
void flash_kernel(const float* __restrict__ falpha, const float* __restrict__ fgamma)
{
    extern __shared__ __align__(16) uint32_t smu[];
    const uint32_t sb = smem_u32(smu);
    const int tid = threadIdx.x, wid = tid >> 5, lane = tid & 31;
    const int g = lane >> 2, tg = lane & 3;
    const int bh = blockIdx.y, q0 = blockIdx.x * 128;
    const int qb = wid * 16;

    const float gam = fgamma[0], alpha = falpha[0];
    const bool g2 = (gam == 2.0f);

    const int r16 = lane & 15;
    const int sel = lane >> 4;
    const int rK  = (lane & 7) + ((lane >> 4) << 3);
    const int selB = (lane >> 3) & 1;

    auto cpQ = [&]() {
        int r = tid >> 1, hf = tid & 1;
        size_t src = ((size_t)bh * NSEQ + q0 + r) * 32 + hf * 16;
#pragma unroll
        for (int j = 0; j < 4; j++) {
            uint32_t d = (uint32_t)sw32(r, hf * 4 + j);
            cp16(sb + 4 * (FQH + d), g_Qh + src + 4 * j);
            cp16(sb + 4 * (FQL + d), g_Ql + src + 4 * j);
        }
    };
    auto cpKV = [&](int ch, int buf) {
        int r = tid >> 2, q4 = tid & 3;
        size_t src = ((size_t)bh * NSEQ + ch * 64 + r) * 32 + q4 * 8;
        uint32_t bo = FKV + (uint32_t)buf * FKVB;
#pragma unroll
        for (int j = 0; j < 2; j++) {
            uint32_t d = bo + (uint32_t)sw32(r, q4 * 2 + j);
            cp16(sb + 4 * d,           g_Kh + src + 4 * j);
            cp16(sb + 4 * (d + 2048),  g_Kl + src + 4 * j);
            cp16(sb + 4 * (d + 4096),  g_Vh + src + 4 * j);
            cp16(sb + 4 * (d + 6144),  g_Vl + src + 4 * j);
        }
    };

    cpQ(); cpKV(0, 0); CP_COMMIT();
    CP_WAIT0();
    __syncthreads();

    // ---- Hoist Q fragments (loop-invariant): 16 ldmx4, 32 regs ----
    uint32_t qh[4][4], ql[4][4];
#pragma unroll
    for (int ks = 0; ks < 4; ks++) {
        const int cA = 2 * ks + sel;
        ldmx4(qh[ks], sb + 4u * (uint32_t)(FQH + sw32(qb + r16, cA)));
        ldmx4(ql[ks], sb + 4u * (uint32_t)(FQL + sw32(qb + r16, cA)));
    }

    float o[8][4];
#pragma unroll
    for (int nt = 0; nt < 8; nt++) { o[nt][0] = o[nt][1] = o[nt][2] = o[nt][3] = 0.f; }
    float m0 = -1e30f, m1 = -1e30f, Z0 = 0.f, Z1 = 0.f, S20 = 0.f, S21 = 0.f;

    for (int ch = 0; ch < 32; ch++) {
        CP_WAIT0();
        __syncthreads();
        if (ch + 1 < 32) cpKV(ch + 1, (ch + 1) & 1);
        CP_COMMIT();

        const uint32_t kvb = FKV + (uint32_t)((ch & 1) * FKVB);

        // ---- S = Q K^T ----
        float s[8][4];
#pragma unroll
        for (int nt = 0; nt < 8; nt++) { s[nt][0] = s[nt][1] = s[nt][2] = s[nt][3] = 0.f; }
#pragma unroll
        for (int ks = 0; ks < 4; ks++) {
            const int cB = 2 * ks + selB;
#pragma unroll
            for (int np = 0; np < 2; np++) {
                const int n0 = np * 2;
                uint32_t th0[4], th1[4], tl0[4], tl1[4];
                ldmx4(th0, sb + 4u * (uint32_t)(kvb + sw32(rK + n0 * 16, cB)));
                ldmx4(th1, sb + 4u * (uint32_t)(kvb + sw32(rK + (n0 + 1) * 16, cB)));
                ldmx4(tl0, sb + 4u * (uint32_t)(kvb + 2048 + sw32(rK + n0 * 16, cB)));
                ldmx4(tl1, sb + 4u * (uint32_t)(kvb + 2048 + sw32(rK + (n0 + 1) * 16, cB)));
                mma16(s[2*n0],   qh[ks], &th0[0]); mma16(s[2*n0+1], qh[ks], &th0[2]);
                mma16(s[2*n0+2], qh[ks], &th1[0]); mma16(s[2*n0+3], qh[ks], &th1[2]);
                mma16(s[2*n0],   qh[ks], &tl0[0]); mma16(s[2*n0+1], qh[ks], &tl0[2]);
                mma16(s[2*n0+2], qh[ks], &tl1[0]); mma16(s[2*n0+3], qh[ks], &tl1[2]);
                mma16(s[2*n0],   ql[ks], &th0[0]); mma16(s[2*n0+1], ql[ks], &th0[2]);
                mma16(s[2*n0+2], ql[ks], &th1[0]); mma16(s[2*n0+3], ql[ks], &th1[2]);
            }
        }

        // ---- chunk max per row (quad reduce) ----
        float cm0 = -1e30f, cm1 = -1e30f;
#pragma unroll
        for (int nt = 0; nt < 8; nt++) {
            cm0 = fmaxf(cm0, fmaxf(s[nt][0], s[nt][1]));
            cm1 = fmaxf(cm1, fmaxf(s[nt][2], s[nt][3]));
        }
        cm0 = fmaxf(cm0, __shfl_xor_sync(0xffffffffu, cm0, 1));
        cm0 = fmaxf(cm0, __shfl_xor_sync(0xffffffffu, cm0, 2));
        cm1 = fmaxf(cm1, __shfl_xor_sync(0xffffffffu, cm1, 1));
        cm1 = fmaxf(cm1, __shfl_xor_sync(0xffffffffu, cm1, 2));

        // ---- online rescale ----
        float nm0 = fmaxf(m0, cm0), nm1 = fmaxf(m1, cm1);
        float cz0 = __expf(m0 - nm0), cz1 = __expf(m1 - nm1);
        float cw0 = g2 ? cz0 * cz0 : __expf(gam * (m0 - nm0));
        float cw1 = g2 ? cz1 * cz1 : __expf(gam * (m1 - nm1));
        Z0 *= cz0; Z1 *= cz1; S20 *= cw0; S21 *= cw1; m0 = nm0; m1 = nm1;
#pragma unroll
        for (int nt = 0; nt < 8; nt++) {
            o[nt][0] *= cw0; o[nt][1] *= cw0; o[nt][2] *= cw1; o[nt][3] *= cw1;
        }

        // ---- weights -> register A-frags for PV (C-frag layout == A-frag) ----
        uint32_t ph[4][4], pl[4][4];
        float zp0 = 0.f, zp1 = 0.f, wp0 = 0.f, wp1 = 0.f;
#pragma unroll
        for (int nt = 0; nt < 8; nt++) {
            float e0 = __expf(s[nt][0] - m0), e1 = __expf(s[nt][1] - m0);
            float e2 = __expf(s[nt][2] - m1), e3 = __expf(s[nt][3] - m1);
            zp0 += e0 + e1; zp1 += e2 + e3;
            float w0, w1, w2, w3;
            if (g2) { w0 = e0 * e0; w1 = e1 * e1; w2 = e2 * e2; w3 = e3 * e3; }
            else {
                w0 = __expf(gam * (s[nt][0] - m0)); w1 = __expf(gam * (s[nt][1] - m0));
                w2 = __expf(gam * (s[nt][2] - m1)); w3 = __expf(gam * (s[nt][3] - m1));
            }
            wp0 += w0 + w1; wp1 += w2 + w3;
            const int ks = nt >> 1, off = (nt & 1) * 2;
            ph[ks][off]     = packhi2(w0, w1);
            ph[ks][off + 1] = packhi2(w2, w3);
            pl[ks][off]     = packlo2(w0, w1);
            pl[ks][off + 1] = packlo2(w2, w3);
        }
        Z0 += zp0; Z1 += zp1; S20 += wp0; S21 += wp1;

        // ---- O += P V (P from registers) ----
#pragma unroll
        for (int ks = 0; ks < 4; ks++) {
            const int k0 = ks * 16;
#pragma unroll
            for (int dp2 = 0; dp2 < 2; dp2++) {
                const int d0 = dp2 * 2;
                uint32_t th0[4], th1[4], tl0[4], tl1[4];
                ldmx4t(th0, sb + 4u * (uint32_t)(kvb + 4096 + sw32(k0 + r16, d0 * 2 + sel)));
                ldmx4t(th1, sb + 4u * (uint32_t)(kvb + 4096 + sw32(k0 + r16, (d0 + 1) * 2 + sel)));
                ldmx4t(tl0, sb + 4u * (uint32_t)(kvb + 6144 + sw32(k0 + r16, d0 * 2 + sel)));
                ldmx4t(tl1, sb + 4u * (uint32_t)(kvb + 6144 + sw32(k0 + r16, (d0 + 1) * 2 + sel)));
                mma16(o[2*d0],   ph[ks], &th0[0]); mma16(o[2*d0+1], ph[ks], &th0[2]);
                mma16(o[2*d0+2], ph[ks], &th1[0]); mma16(o[2*d0+3], ph[ks], &th1[2]);
                mma16(o[2*d0],   ph[ks], &tl0[0]); mma16(o[2*d0+1], ph[ks], &tl0[2]);
                mma16(o[2*d0+2], ph[ks], &tl1[0]); mma16(o[2*d0+3], ph[ks], &tl1[2]);
                mma16(o[2*d0],   pl[ks], &th0[0]); mma16(o[2*d0+1], pl[ks], &th0[2]);
                mma16(o[2*d0+2], pl[ks], &th1[0]); mma16(o[2*d0+3], pl[ks], &th1[2]);
            }
        }
    }

    // ---- final reduce + packed split write of AO ----
    Z0  += __shfl_xor_sync(0xffffffffu, Z0, 1);  Z0  += __shfl_xor_sync(0xffffffffu, Z0, 2);
    Z1  += __shfl_xor_sync(0xffffffffu, Z1, 1);  Z1  += __shfl_xor_sync(0xffffffffu, Z1, 2);
    S20 += __shfl_xor_sync(0xffffffffu, S20, 1); S20 += __shfl_xor_sync(0xffffffffu, S20, 2);
    S21 += __shfl_xor_sync(0xffffffffu, S21, 1); S21 += __shfl_xor_sync(0xffffffffu, S21, 2);

    float Zg0 = g2 ? Z0 * Z0 : __powf(Z0, gam);
    float Zg1 = g2 ? Z1 * Z1 : __powf(Z1, gam);
    float sc0 = alpha / (alpha * S20 + 1e-6f * Zg0);
    float sc1 = alpha / (alpha * S21 + 1e-6f * Zg1);

    const int b = bh >> 4, h = bh & 15;
    const int qA = q0 + qb + g, qB = qA + 8;
#pragma unroll
    for (int nt = 0; nt < 8; nt++) {
        int d = nt * 8 + 2 * tg;
        size_t wA = ((size_t)b * NSEQ + qA) * 512 + ((h * HD_ + d) >> 1);
        size_t wB = ((size_t)b * NSEQ + qB) * 512 + ((h * HD_ + d) >> 1);
        float a0 = o[nt][0] * sc0, a1 = o[nt][1] * sc0;
        float b0 = o[nt][2] * sc1, b1 = o[nt][3] * sc1;
        g_AOh[wA] = packhi2(a0, a1); g_AOl[wA] = packlo2(a0, a1);
        g_AOh[wB] = packhi2(b0, b1); g_AOl[wB] = packlo2(b0, b1);
    }
}

// ---------------------------------------------------------------------------
extern "C" void kernel_launch(void* const* d_in, const int* in_sizes, int n_in,
                              void* d_out, int out_size)
{
    const float* x = nullptr, *Wqkv = nullptr, *bqkv = nullptr;
    const float* Wproj = nullptr, *bproj = nullptr, *fa = nullptr, *fg = nullptr;
    for (int i = 0; i < n_in; i++) {
        int sz = in_sizes[i];
        const float* p = (const float*)d_in[i];
        if      (sz == B_*NSEQ*DIM_)   x = p;
        else if (sz == 3*DIM_*DIM_)    Wqkv = p;
        else if (sz == 3*DIM_)         bqkv = p;
        else if (sz == DIM_*DIM_)      Wproj = p;
        else if (sz == DIM_)           bproj = p;
        else if (sz == 1)              { if (!fa) fa = p; else fg = p; }
    }
    float* out = (float*)d_out;

    cudaFuncSetAttribute(tc_gemm<0>,   cudaFuncAttributeMaxDynamicSharedMemorySize, GEMM_SMEM);
    cudaFuncSetAttribute(tc_gemm<1>,   cudaFuncAttributeMaxDynamicSharedMemorySize, GEMM_SMEM);
    cudaFuncSetAttribute(flash_kernel, cudaFuncAttributeMaxDynamicSharedMemorySize, FLASH_SMEM);

    // 0) Split inputs into packed bf16 hi/lo
    split_kernel<<<4096, 256>>>((const float4*)x,     0, 4096*256);
    split_kernel<<<3072, 256>>>((const float4*)Wqkv,  1, 3072*256);
    split_kernel<<<1024, 256>>>((const float4*)Wproj, 2, 1024*256);
    // 1) Fused QKV projection -> packed Q(scaled)/K/V
    tc_gemm<0><<<dim3(3*DIM_/128, (B_*NSEQ)/128), 256, GEMM_SMEM>>>(bqkv, nullptr);
    // 2) Focal flash attention -> packed AO
    flash_kernel<<<dim3(NSEQ/128, B_*H_), 256, FLASH_SMEM>>>(fa, fg);
    // 3) Output projection -> d_out
    tc_gemm<1><<<dim3(DIM_/128, (B_*NSEQ)/128), 256, GEMM_SMEM>>>(bproj, out);
}

// round 10
// speedup vs baseline: 1.1831x; 1.1831x over previous
#include <cuda_runtime.h>
#include <cuda.h>
#include <cstdint>

// Problem constants
#define B_    2
#define NSEQ  2048
#define DIM_  1024
#define H_    16
#define HD_   64
#define SCALE_F 0.125f   // HD^-0.5

// ---------------------------------------------------------------------------
// Packed split storage: uint32 = {bf16 elem k (low), bf16 elem k+1 (high)}.
// hi = top16 of fp32; lo = bf16(x - hi).  A*B ~= Ah*Bh + Ah*Bl + Al*Bh.
// Row layout: 512 words = 1024 bf16 = one 1024-col fp32 row.
// ---------------------------------------------------------------------------
__device__ __align__(1024) uint32_t g_xh [4096*512], g_xl [4096*512];
__device__ __align__(1024) uint32_t g_Wqh[3072*512], g_Wql[3072*512];
__device__ __align__(1024) uint32_t g_Wph[1024*512], g_Wpl[1024*512];
#define QKV_W (B_*H_*NSEQ*32)
__device__ __align__(16) uint32_t g_Qh[QKV_W], g_Ql[QKV_W];
__device__ __align__(16) uint32_t g_Kh[QKV_W], g_Kl[QKV_W];
__device__ __align__(16) uint32_t g_Vh[QKV_W], g_Vl[QKV_W];
__device__ __align__(1024) uint32_t g_AOh[4096*512], g_AOl[4096*512];

// ---------------------------------------------------------------------------
__device__ __forceinline__ uint32_t packhi2(float x, float y) {
    return __byte_perm(__float_as_uint(x), __float_as_uint(y), 0x7632);
}
__device__ __forceinline__ uint32_t packlo2(float x, float y) {
    float lx = x - __uint_as_float(__float_as_uint(x) & 0xffff0000u);
    float ly = y - __uint_as_float(__float_as_uint(y) & 0xffff0000u);
    return __byte_perm(__float_as_uint(lx), __float_as_uint(ly), 0x7632);
}
__device__ __forceinline__ uint32_t smem_u32(const void* p) {
    uint32_t a;
    asm("{ .reg .u64 t; cvta.to.shared.u64 t, %1; cvt.u32.u64 %0, t; }" : "=r"(a) : "l"(p));
    return a;
}
__device__ __forceinline__ void cp16(uint32_t s, const void* g) {
    asm volatile("cp.async.cg.shared.global [%0], [%1], 16;" :: "r"(s), "l"(g));
}
#define CP_COMMIT() asm volatile("cp.async.commit_group;" ::: "memory")
#define CP_WAIT0()  asm volatile("cp.async.wait_group 0;" ::: "memory")

__device__ __forceinline__ void mma16(float* c, const uint32_t* a, const uint32_t* b) {
    asm("mma.sync.aligned.m16n8k16.row.col.f32.bf16.bf16.f32 "
        "{%0,%1,%2,%3}, {%4,%5,%6,%7}, {%8,%9}, {%0,%1,%2,%3};"
        : "+f"(c[0]), "+f"(c[1]), "+f"(c[2]), "+f"(c[3])
        : "r"(a[0]), "r"(a[1]), "r"(a[2]), "r"(a[3]), "r"(b[0]), "r"(b[1]));
}
__device__ __forceinline__ void ldmx4(uint32_t* r, uint32_t a) {
    asm volatile("ldmatrix.sync.aligned.m8n8.x4.shared.b16 {%0,%1,%2,%3}, [%4];"
        : "=r"(r[0]), "=r"(r[1]), "=r"(r[2]), "=r"(r[3]) : "r"(a));
}
__device__ __forceinline__ void ldmx4t(uint32_t* r, uint32_t a) {
    asm volatile("ldmatrix.sync.aligned.m8n8.x4.trans.shared.b16 {%0,%1,%2,%3}, [%4];"
        : "=r"(r[0]), "=r"(r[1]), "=r"(r[2]), "=r"(r[3]) : "r"(a));
}
// Custom XOR swizzle for cp.async smem (flash kernel)
__device__ __forceinline__ int sw32(int r, int c) { return r * 32 + 4 * (c ^ (r & 7)); }
// TMA SWIZZLE_64B layout: tile rows of 64B; byte off = r*64+16*c -> xor bits[4:5] with [7:8]
__device__ __forceinline__ int swt(int r, int c) { return r * 64 + 16 * (c ^ ((r >> 1) & 3)); }

// mbarrier helpers
#define MBAR_INIT(mb, c)  asm volatile("mbarrier.init.shared.b64 [%0], %1;" :: "r"(mb), "r"(c) : "memory")
#define MBAR_EXPECT_TX(mb, n) asm volatile("mbarrier.arrive.expect_tx.shared.b64 _, [%0], %1;" :: "r"(mb), "r"(n) : "memory")
__device__ __forceinline__ void mbar_wait(uint32_t mb, uint32_t ph) {
    asm volatile(
        "{ .reg .pred P1;\n"
        "WL_%=: mbarrier.try_wait.parity.acquire.cta.shared::cta.b64 P1, [%0], %1, 0x989680;\n"
        "@P1 bra.uni WD_%=;\n"
        "bra.uni WL_%=;\n"
        "WD_%=: }"
        :: "r"(mb), "r"(ph) : "memory");
}
__device__ __forceinline__ void tma2d(uint32_t smem, const CUtensorMap* m, int x, int y, uint32_t mb) {
    asm volatile("cp.async.bulk.tensor.2d.shared::cta.global.tile.mbarrier::complete_tx::bytes "
                 "[%0], [%1, {%2, %3}], [%4];"
                 :: "r"(smem), "l"(m), "r"(x), "r"(y), "r"(mb) : "memory");
}

// ---------------------------------------------------------------------------
// Prep: split fp32 tensor into packed hi/lo arrays. which: 0=x 1=Wqkv 2=Wproj.
// ---------------------------------------------------------------------------
__global__ __launch_bounds__(256)
void split_kernel(const float4* __restrict__ src, int which, int n4)
{
    uint2 *h, *l;
    if (which == 0)      { h = (uint2*)g_xh;  l = (uint2*)g_xl;  }
    else if (which == 1) { h = (uint2*)g_Wqh; l = (uint2*)g_Wql; }
    else                 { h = (uint2*)g_Wph; l = (uint2*)g_Wpl; }
    int i = blockIdx.x * 256 + threadIdx.x;
    if (i < n4) {
        float4 v = src[i];
        h[i] = make_uint2(packhi2(v.x, v.y), packhi2(v.z, v.w));
        l[i] = make_uint2(packlo2(v.x, v.y), packlo2(v.z, v.w));
    }
}

// ---------------------------------------------------------------------------
// Split-bf16 GEMM, TMA-fed.  CTA 128x128, 8 warps (2x4, warp 64x32), BK=32.
// 3-stage TMA pipeline (stage = 4 tiles of 128x64B: Ah, Al, Bh, Bl = 32KB).
// One mbarrier per stage; one __syncthreads per chunk. 2 CTAs/SM.
// ---------------------------------------------------------------------------
#define STG_BYTES 32768
#define GEMM_SMEM (1024 + 3*STG_BYTES + 64)

template<int MODE>
__global__ __launch_bounds__(256, 2)
void tc_gemm(const __grid_constant__ CUtensorMap mAh,
             const __grid_constant__ CUtensorMap mAl,
             const __grid_constant__ CUtensorMap mBh,
             const __grid_constant__ CUtensorMap mBl,
             const float* __restrict__ bias, float* __restrict__ C)
{
    extern __shared__ __align__(16) uint32_t smu[];
    const uint32_t sbraw = smem_u32(smu);
    const uint32_t sb0 = (sbraw + 1023u) & ~1023u;     // aligned stage base
    const uint32_t mb0 = sb0 + 3 * STG_BYTES;          // 3 mbarriers

    const int tid = threadIdx.x, wid = tid >> 5, lane = tid & 31;
    const int g = lane >> 2, tg = lane & 3;
    const int wm = wid >> 2, wn = wid & 3;
    const int row0 = blockIdx.y * 128, col0 = blockIdx.x * 128;

    const int rA = wm * 64 + (lane & 15);
    const int selA = lane >> 4;
    const int rB = wn * 32 + (lane & 7) + ((lane >> 4) << 3);
    const int selB = (lane >> 3) & 1;

    if (tid == 0) {
        MBAR_INIT(mb0 + 0, 1);
        MBAR_INIT(mb0 + 8, 1);
        MBAR_INIT(mb0 + 16, 1);
    }
    __syncthreads();

    auto issue = [&](int ch, int st) {
        uint32_t base = sb0 + (uint32_t)st * STG_BYTES;
        uint32_t mb = mb0 + st * 8;
        MBAR_EXPECT_TX(mb, STG_BYTES);
        tma2d(base,         &mAh, ch * 64, row0, mb);
        tma2d(base + 8192,  &mAl, ch * 64, row0, mb);
        tma2d(base + 16384, &mBh, ch * 64, col0, mb);
        tma2d(base + 24576, &mBl, ch * 64, col0, mb);
    };
    if (tid == 0) { issue(0, 0); issue(1, 1); issue(2, 2); }

    float c[4][4][4];
#pragma unroll
    for (int mt = 0; mt < 4; mt++)
#pragma unroll
        for (int nt = 0; nt < 4; nt++) {
            c[mt][nt][0] = 0.f; c[mt][nt][1] = 0.f; c[mt][nt][2] = 0.f; c[mt][nt][3] = 0.f;
        }

    for (int ch = 0; ch < 32; ch++) {
        const int st = ch % 3;
        mbar_wait(mb0 + st * 8, (uint32_t)((ch / 3) & 1));
        const uint32_t base = sb0 + (uint32_t)st * STG_BYTES;

#pragma unroll
        for (int ks = 0; ks < 2; ks++) {
            const int cA = 2 * ks + selA;
            const int cB = 2 * ks + selB;
            uint32_t ah[4][4], al[4][4], th[2][4], tl[2][4];
#pragma unroll
            for (int mt = 0; mt < 4; mt++) {
                ldmx4(ah[mt], base + (uint32_t)swt(rA + mt * 16, cA));
                ldmx4(al[mt], base + 8192u + (uint32_t)swt(rA + mt * 16, cA));
            }
#pragma unroll
            for (int ntp = 0; ntp < 2; ntp++) {
                ldmx4(th[ntp], base + 16384u + (uint32_t)swt(rB + ntp * 16, cB));
                ldmx4(tl[ntp], base + 24576u + (uint32_t)swt(rB + ntp * 16, cB));
            }
#pragma unroll
            for (int ntp = 0; ntp < 2; ntp++)
#pragma unroll
                for (int mt = 0; mt < 4; mt++) {
                    mma16(c[mt][2*ntp],   ah[mt], &th[ntp][0]);
                    mma16(c[mt][2*ntp+1], ah[mt], &th[ntp][2]);
                }
#pragma unroll
            for (int ntp = 0; ntp < 2; ntp++)
#pragma unroll
                for (int mt = 0; mt < 4; mt++) {
                    mma16(c[mt][2*ntp],   ah[mt], &tl[ntp][0]);
                    mma16(c[mt][2*ntp+1], ah[mt], &tl[ntp][2]);
                }
#pragma unroll
            for (int ntp = 0; ntp < 2; ntp++)
#pragma unroll
                for (int mt = 0; mt < 4; mt++) {
                    mma16(c[mt][2*ntp],   al[mt], &th[ntp][0]);
                    mma16(c[mt][2*ntp+1], al[mt], &th[ntp][2]);
                }
        }
        __syncthreads();   // all warps done reading stage st
        if (tid == 0 && ch + 3 < 32) issue(ch + 3, st);
    }

    // Epilogue
#pragma unroll
    for (int mt = 0; mt < 4; mt++) {
#pragma unroll
        for (int hf = 0; hf < 2; hf++) {
            int row = row0 + wm * 64 + mt * 16 + g + hf * 8;
#pragma unroll
            for (int nt = 0; nt < 4; nt++) {
                int col = col0 + wn * 32 + nt * 8 + 2 * tg;
                float v0 = c[mt][nt][hf * 2 + 0] + bias[col];
                float v1 = c[mt][nt][hf * 2 + 1] + bias[col + 1];
                if (MODE == 1) {
                    *(float2*)&C[(size_t)row * DIM_ + col] = make_float2(v0, v1);
                } else {
                    int b = row >> 11, n = row & (NSEQ - 1);
                    int which = col >> 10, rem = col & 1023;
                    int h = rem >> 6, d = rem & 63;
                    size_t w = (((size_t)(b * H_ + h)) * NSEQ + n) * 32 + (d >> 1);
                    if (which == 0) {
                        v0 *= SCALE_F; v1 *= SCALE_F;
                        g_Qh[w] = packhi2(v0, v1); g_Ql[w] = packlo2(v0, v1);
                    } else if (which == 1) {
                        g_Kh[w] = packhi2(v0, v1); g_Kl[w] = packlo2(v0, v1);
                    } else {
                        g_Vh[w] = packhi2(v0, v1); g_Vl[w] = packlo2(v0, v1);
                    }
                }
            }
        }
    }
}

// ---------------------------------------------------------------------------
// Flash focal attention (R8 version: P in registers, double-buffered K/V,
// cp.async, 2 CTAs/SM).
// ---------------------------------------------------------------------------
#define FQH 0
#define FQL 4096
#define FKV 8192
#define FKVB 8192
#define FLASH_SMEM ((8192 + 2*FKVB)*4)   // 98304 B

__global__ __launch_bounds__(256, 2)
void flash_kernel(const float* __restrict__ falpha, const float* __restrict__ fgamma)
{
    extern __shared__ __align__(16) uint32_t smu[];
    const uint32_t sb = smem_u32(smu);
    const int tid = threadIdx.x, wid = tid >> 5, lane = tid & 31;
    const int g = lane >> 2, tg = lane & 3;
    const int bh = blockIdx.y, q0 = blockIdx.x * 128;
    const int qb = wid * 16;

    const float gam = fgamma[0], alpha = falpha[0];
    const bool g2 = (gam == 2.0f);

    const int r16 = lane & 15;
    const int sel = lane >> 4;
    const int rK  = (lane & 7) + ((lane >> 4) << 3);
    const int selB = (lane >> 3) & 1;

    auto cpQ = [&]() {
        int r = tid >> 1, hf = tid & 1;
        size_t src = ((size_t)bh * NSEQ + q0 + r) * 32 + hf * 16;
#pragma unroll
        for (int j = 0; j < 4; j++) {
            uint32_t d = (uint32_t)sw32(r, hf * 4 + j);
            cp16(sb + 4 * (FQH + d), g_Qh + src + 4 * j);
            cp16(sb + 4 * (FQL + d), g_Ql + src + 4 * j);
        }
    };
    auto cpKV = [&](int ch, int buf) {
        int r = tid >> 2, q4 = tid & 3;
        size_t src = ((size_t)bh * NSEQ + ch * 64 + r) * 32 + q4 * 8;
        uint32_t bo = FKV + (uint32_t)buf * FKVB;
#pragma unroll
        for (int j = 0; j < 2; j++) {
            uint32_t d = bo + (uint32_t)sw32(r, q4 * 2 + j);
            cp16(sb + 4 * d,           g_Kh + src + 4 * j);
            cp16(sb + 4 * (d + 2048),  g_Kl + src + 4 * j);
            cp16(sb + 4 * (d + 4096),  g_Vh + src + 4 * j);
            cp16(sb + 4 * (d + 6144),  g_Vl + src + 4 * j);
        }
    };

    cpQ(); cpKV(0, 0); CP_COMMIT();

    float o[8][4];
#pragma unroll
    for (int nt = 0; nt < 8; nt++) { o[nt][0] = o[nt][1] = o[nt][2] = o[nt][3] = 0.f; }
    float m0 = -1e30f, m1 = -1e30f, Z0 = 0.f, Z1 = 0.f, S20 = 0.f, S21 = 0.f;

    for (int ch = 0; ch < 32; ch++) {
        CP_WAIT0();
        __syncthreads();
        if (ch + 1 < 32) cpKV(ch + 1, (ch + 1) & 1);
        CP_COMMIT();

        const uint32_t kvb = FKV + (uint32_t)((ch & 1) * FKVB);

        // ---- S = Q K^T ----
        float s[8][4];
#pragma unroll
        for (int nt = 0; nt < 8; nt++) { s[nt][0] = s[nt][1] = s[nt][2] = s[nt][3] = 0.f; }
#pragma unroll
        for (int ks = 0; ks < 4; ks++) {
            const int cA = 2 * ks + sel;
            const int cB = 2 * ks + selB;
            uint32_t qh[4], ql[4];
            ldmx4(qh, sb + 4u * (uint32_t)(FQH + sw32(qb + r16, cA)));
            ldmx4(ql, sb + 4u * (uint32_t)(FQL + sw32(qb + r16, cA)));
#pragma unroll
            for (int np = 0; np < 2; np++) {
                const int n0 = np * 2;
                uint32_t th0[4], th1[4], tl0[4], tl1[4];
                ldmx4(th0, sb + 4u * (uint32_t)(kvb + sw32(rK + n0 * 16, cB)));
                ldmx4(th1, sb + 4u * (uint32_t)(kvb + sw32(rK + (n0 + 1) * 16, cB)));
                ldmx4(tl0, sb + 4u * (uint32_t)(kvb + 2048 + sw32(rK + n0 * 16, cB)));
                ldmx4(tl1, sb + 4u * (uint32_t)(kvb + 2048 + sw32(rK + (n0 + 1) * 16, cB)));
                mma16(s[2*n0],   qh, &th0[0]); mma16(s[2*n0+1], qh, &th0[2]);
                mma16(s[2*n0+2], qh, &th1[0]); mma16(s[2*n0+3], qh, &th1[2]);
                mma16(s[2*n0],   qh, &tl0[0]); mma16(s[2*n0+1], qh, &tl0[2]);
                mma16(s[2*n0+2], qh, &tl1[0]); mma16(s[2*n0+3], qh, &tl1[2]);
                mma16(s[2*n0],   ql, &th0[0]); mma16(s[2*n0+1], ql, &th0[2]);
                mma16(s[2*n0+2], ql, &th1[0]); mma16(s[2*n0+3], ql, &th1[2]);
            }
        }

        // ---- chunk max per row (quad reduce) ----
        float cm0 = -1e30f, cm1 = -1e30f;
#pragma unroll
        for (int nt = 0; nt < 8; nt++) {
            cm0 = fmaxf(cm0, fmaxf(s[nt][0], s[nt][1]));
            cm1 = fmaxf(cm1, fmaxf(s[nt][2], s[nt][3]));
        }
        cm0 = fmaxf(cm0, __shfl_xor_sync(0xffffffffu, cm0, 1));
        cm0 = fmaxf(cm0, __shfl_xor_sync(0xffffffffu, cm0, 2));
        cm1 = fmaxf(cm1, __shfl_xor_sync(0xffffffffu, cm1, 1));
        cm1 = fmaxf(cm1, __shfl_xor_sync(0xffffffffu, cm1, 2));

        // ---- online rescale ----
        float nm0 = fmaxf(m0, cm0), nm1 = fmaxf(m1, cm1);
        float cz0 = __expf(m0 - nm0), cz1 = __expf(m1 - nm1);
        float cw0 = g2 ? cz0 * cz0 : __expf(gam * (m0 - nm0));
        float cw1 = g2 ? cz1 * cz1 : __expf(gam * (m1 - nm1));
        Z0 *= cz0; Z1 *= cz1; S20 *= cw0; S21 *= cw1; m0 = nm0; m1 = nm1;
#pragma unroll
        for (int nt = 0; nt < 8; nt++) {
            o[nt][0] *= cw0; o[nt][1] *= cw0; o[nt][2] *= cw1; o[nt][3] *= cw1;
        }

        // ---- weights -> register A-frags for PV ----
        uint32_t ph[4][4], pl[4][4];
        float zp0 = 0.f, zp1 = 0.f, wp0 = 0.f, wp1 = 0.f;
#pragma unroll
        for (int nt = 0; nt < 8; nt++) {
            float e0 = __expf(s[nt][0] - m0), e1 = __expf(s[nt][1] - m0);
            float e2 = __expf(s[nt][2] - m1), e3 = __expf(s[nt][3] - m1);
            zp0 += e0 + e1; zp1 += e2 + e3;
            float w0, w1, w2, w3;
            if (g2) { w0 = e0 * e0; w1 = e1 * e1; w2 = e2 * e2; w3 = e3 * e3; }
            else {
                w0 = __expf(gam * (s[nt][0] - m0)); w1 = __expf(gam * (s[nt][1] - m0));
                w2 = __expf(gam * (s[nt][2] - m1)); w3 = __expf(gam * (s[nt][3] - m1));
            }
            wp0 += w0 + w1; wp1 += w2 + w3;
            const int ks = nt >> 1, off = (nt & 1) * 2;
            ph[ks][off]     = packhi2(w0, w1);
            ph[ks][off + 1] = packhi2(w2, w3);
            pl[ks][off]     = packlo2(w0, w1);
            pl[ks][off + 1] = packlo2(w2, w3);
        }
        Z0 += zp0; Z1 += zp1; S20 += wp0; S21 += wp1;

        // ---- O += P V ----
#pragma unroll
        for (int ks = 0; ks < 4; ks++) {
            const int k0 = ks * 16;
#pragma unroll
            for (int dp2 = 0; dp2 < 2; dp2++) {
                const int d0 = dp2 * 2;
                uint32_t th0[4], th1[4], tl0[4], tl1[4];
                ldmx4t(th0, sb + 4u * (uint32_t)(kvb + 4096 + sw32(k0 + r16, d0 * 2 + sel)));
                ldmx4t(th1, sb + 4u * (uint32_t)(kvb + 4096 + sw32(k0 + r16, (d0 + 1) * 2 + sel)));
                ldmx4t(tl0, sb + 4u * (uint32_t)(kvb + 6144 + sw32(k0 + r16, d0 * 2 + sel)));
                ldmx4t(tl1, sb + 4u * (uint32_t)(kvb + 6144 + sw32(k0 + r16, (d0 + 1) * 2 + sel)));
                mma16(o[2*d0],   ph[ks], &th0[0]); mma16(o[2*d0+1], ph[ks], &th0[2]);
                mma16(o[2*d0+2], ph[ks], &th1[0]); mma16(o[2*d0+3], ph[ks], &th1[2]);
                mma16(o[2*d0],   ph[ks], &tl0[0]); mma16(o[2*d0+1], ph[ks], &tl0[2]);
                mma16(o[2*d0+2], ph[ks], &tl1[0]); mma16(o[2*d0+3], ph[ks], &tl1[2]);
                mma16(o[2*d0],   pl[ks], &th0[0]); mma16(o[2*d0+1], pl[ks], &th0[2]);
                mma16(o[2*d0+2], pl[ks], &th1[0]); mma16(o[2*d0+3], pl[ks], &th1[2]);
            }
        }
    }

    // ---- final reduce + packed split write of AO ----
    Z0  += __shfl_xor_sync(0xffffffffu, Z0, 1);  Z0  += __shfl_xor_sync(0xffffffffu, Z0, 2);
    Z1  += __shfl_xor_sync(0xffffffffu, Z1, 1);  Z1  += __shfl_xor_sync(0xffffffffu, Z1, 2);
    S20 += __shfl_xor_sync(0xffffffffu, S20, 1); S20 += __shfl_xor_sync(0xffffffffu, S20, 2);
    S21 += __shfl_xor_sync(0xffffffffu, S21, 1); S21 += __shfl_xor_sync(0xffffffffu, S21, 2);

    float Zg0 = g2 ? Z0 * Z0 : __powf(Z0, gam);
    float Zg1 = g2 ? Z1 * Z1 : __powf(Z1, gam);
    float sc0 = alpha / (alpha * S20 + 1e-6f * Zg0);
    float sc1 = alpha / (alpha * S21 + 1e-6f * Zg1);

    const int b = bh >> 4, h = bh & 15;
    const int qA = q0 + qb + g, qB = qA + 8;
#pragma unroll
    for (int nt = 0; nt < 8; nt++) {
        int d = nt * 8 + 2 * tg;
        size_t wA = ((size_t)b * NSEQ + qA) * 512 + ((h * HD_ + d) >> 1);
        size_t wB = ((size_t)b * NSEQ + qB) * 512 + ((h * HD_ + d) >> 1);
        float a0 = o[nt][0] * sc0, a1 = o[nt][1] * sc0;
        float b0 = o[nt][2] * sc1, b1 = o[nt][3] * sc1;
        g_AOh[wA] = packhi2(a0, a1); g_AOl[wA] = packlo2(a0, a1);
        g_AOh[wB] = packhi2(b0, b1); g_AOl[wB] = packlo2(b0, b1);
    }
}

// ---------------------------------------------------------------------------
typedef CUresult (*EncodeFn)(CUtensorMap*, CUtensorMapDataType, cuuint32_t, void*,
                             const cuuint64_t*, const cuuint64_t*, const cuuint32_t*,
                             const cuuint32_t*, CUtensorMapInterleave, CUtensorMapSwizzle,
                             CUtensorMapL2promotion, CUtensorMapFloatOOBfill);

static void make_map(EncodeFn enc, CUtensorMap* m, void* ptr, unsigned long long rows) {
    cuuint64_t dims[2]    = {2048ull, rows};   // bytes per row, rows
    cuuint64_t strides[1] = {2048ull};
    cuuint32_t box[2]     = {64u, 128u};       // 64B x 128 rows
    cuuint32_t es[2]      = {1u, 1u};
    enc(m, CU_TENSOR_MAP_DATA_TYPE_UINT8, 2, ptr, dims, strides, box, es,
        CU_TENSOR_MAP_INTERLEAVE_NONE, CU_TENSOR_MAP_SWIZZLE_64B,
        CU_TENSOR_MAP_L2_PROMOTION_L2_128B, CU_TENSOR_MAP_FLOAT_OOB_FILL_NONE);
}

extern "C" void kernel_launch(void* const* d_in, const int* in_sizes, int n_in,
                              void* d_out, int out_size)
{
    const float* x = nullptr, *Wqkv = nullptr, *bqkv = nullptr;
    const float* Wproj = nullptr, *bproj = nullptr, *fa = nullptr, *fg = nullptr;
    for (int i = 0; i < n_in; i++) {
        int sz = in_sizes[i];
        const float* p = (const float*)d_in[i];
        if      (sz == B_*NSEQ*DIM_)   x = p;
        else if (sz == 3*DIM_*DIM_)    Wqkv = p;
        else if (sz == 3*DIM_)         bqkv = p;
        else if (sz == DIM_*DIM_)      Wproj = p;
        else if (sz == DIM_)           bproj = p;
        else if (sz == 1)              { if (!fa) fa = p; else fg = p; }
    }
    float* out = (float*)d_out;

    cudaFuncSetAttribute(tc_gemm<0>,   cudaFuncAttributeMaxDynamicSharedMemorySize, GEMM_SMEM);
    cudaFuncSetAttribute(tc_gemm<1>,   cudaFuncAttributeMaxDynamicSharedMemorySize, GEMM_SMEM);
    cudaFuncSetAttribute(flash_kernel, cudaFuncAttributeMaxDynamicSharedMemorySize, FLASH_SMEM);

    // Driver entry point for cuTensorMapEncodeTiled (no -lcuda needed)
    EncodeFn enc = nullptr;
#if CUDART_VERSION >= 12000
    {
        cudaDriverEntryPointQueryResult qr;
        cudaGetDriverEntryPoint("cuTensorMapEncodeTiled", (void**)&enc,
                                cudaEnableDefault, &qr);
    }
#else
    cudaGetDriverEntryPoint("cuTensorMapEncodeTiled", (void**)&enc, cudaEnableDefault);
#endif

    void *p_xh, *p_xl, *p_Wqh, *p_Wql, *p_Wph, *p_Wpl, *p_AOh, *p_AOl;
    cudaGetSymbolAddress(&p_xh,  g_xh);  cudaGetSymbolAddress(&p_xl,  g_xl);
    cudaGetSymbolAddress(&p_Wqh, g_Wqh); cudaGetSymbolAddress(&p_Wql, g_Wql);
    cudaGetSymbolAddress(&p_Wph, g_Wph); cudaGetSymbolAddress(&p_Wpl, g_Wpl);
    cudaGetSymbolAddress(&p_AOh, g_AOh); cudaGetSymbolAddress(&p_AOl, g_AOl);

    CUtensorMap m_xh, m_xl, m_Wqh, m_Wql, m_Wph, m_Wpl, m_AOh, m_AOl;
    make_map(enc, &m_xh,  p_xh,  4096); make_map(enc, &m_xl,  p_xl,  4096);
    make_map(enc, &m_Wqh, p_Wqh, 3072); make_map(enc, &m_Wql, p_Wql, 3072);
    make_map(enc, &m_Wph, p_Wph, 1024); make_map(enc, &m_Wpl, p_Wpl, 1024);
    make_map(enc, &m_AOh, p_AOh, 4096); make_map(enc, &m_AOl, p_AOl, 4096);

    // 0) Split inputs into packed bf16 hi/lo
    split_kernel<<<4096, 256>>>((const float4*)x,     0, 4096*256);
    split_kernel<<<3072, 256>>>((const float4*)Wqkv,  1, 3072*256);
    split_kernel<<<1024, 256>>>((const float4*)Wproj, 2, 1024*256);
    // 1) Fused QKV projection -> packed Q(scaled)/K/V
    tc_gemm<0><<<dim3(3*DIM_/128, (B_*NSEQ)/128), 256, GEMM_SMEM>>>(
        m_xh, m_xl, m_Wqh, m_Wql, bqkv, nullptr);
    // 2) Focal flash attention -> packed AO
    flash_kernel<<<dim3(NSEQ/128, B_*H_), 256, FLASH_SMEM>>>(fa, fg);
    // 3) Output projection -> d_out
    tc_gemm<1><<<dim3(DIM_/128, (B_*NSEQ)/128), 256, GEMM_SMEM>>>(
        m_AOh, m_AOl, m_Wph, m_Wpl, bproj, out);
}

// round 11
// speedup vs baseline: 1.2334x; 1.0425x over previous
#include <cuda_runtime.h>
#include <cuda.h>
#include <cstdint>

// Problem constants
#define B_    2
#define NSEQ  2048
#define DIM_  1024
#define H_    16
#define HD_   64
#define SCALE_F 0.125f   // HD^-0.5

// ---------------------------------------------------------------------------
// Packed split storage: uint32 = {bf16 elem k (low), bf16 elem k+1 (high)}.
// hi = top16 of fp32; lo = bf16(x - hi).  A*B ~= Ah*Bh + Ah*Bl + Al*Bh.
// ---------------------------------------------------------------------------
__device__ __align__(1024) uint32_t g_xh [4096*512], g_xl [4096*512];
__device__ __align__(1024) uint32_t g_Wqh[3072*512], g_Wql[3072*512];
__device__ __align__(1024) uint32_t g_Wph[1024*512], g_Wpl[1024*512];
#define QKV_W (B_*H_*NSEQ*32)
__device__ __align__(1024) uint32_t g_Qh[QKV_W], g_Ql[QKV_W];
__device__ __align__(1024) uint32_t g_Kh[QKV_W], g_Kl[QKV_W];
__device__ __align__(1024) uint32_t g_Vh[QKV_W], g_Vl[QKV_W];
__device__ __align__(1024) uint32_t g_AOh[4096*512], g_AOl[4096*512];

// ---------------------------------------------------------------------------
__device__ __forceinline__ uint32_t packhi2(float x, float y) {
    return __byte_perm(__float_as_uint(x), __float_as_uint(y), 0x7632);
}
__device__ __forceinline__ uint32_t packlo2(float x, float y) {
    float lx = x - __uint_as_float(__float_as_uint(x) & 0xffff0000u);
    float ly = y - __uint_as_float(__float_as_uint(y) & 0xffff0000u);
    return __byte_perm(__float_as_uint(lx), __float_as_uint(ly), 0x7632);
}
__device__ __forceinline__ uint32_t smem_u32(const void* p) {
    uint32_t a;
    asm("{ .reg .u64 t; cvta.to.shared.u64 t, %1; cvt.u32.u64 %0, t; }" : "=r"(a) : "l"(p));
    return a;
}
__device__ __forceinline__ void mma16(float* c, const uint32_t* a, const uint32_t* b) {
    asm("mma.sync.aligned.m16n8k16.row.col.f32.bf16.bf16.f32 "
        "{%0,%1,%2,%3}, {%4,%5,%6,%7}, {%8,%9}, {%0,%1,%2,%3};"
        : "+f"(c[0]), "+f"(c[1]), "+f"(c[2]), "+f"(c[3])
        : "r"(a[0]), "r"(a[1]), "r"(a[2]), "r"(a[3]), "r"(b[0]), "r"(b[1]));
}
__device__ __forceinline__ void ldmx4(uint32_t* r, uint32_t a) {
    asm volatile("ldmatrix.sync.aligned.m8n8.x4.shared.b16 {%0,%1,%2,%3}, [%4];"
        : "=r"(r[0]), "=r"(r[1]), "=r"(r[2]), "=r"(r[3]) : "r"(a));
}
__device__ __forceinline__ void ldmx4t(uint32_t* r, uint32_t a) {
    asm volatile("ldmatrix.sync.aligned.m8n8.x4.trans.shared.b16 {%0,%1,%2,%3}, [%4];"
        : "=r"(r[0]), "=r"(r[1]), "=r"(r[2]), "=r"(r[3]) : "r"(a));
}
// SW128 swizzle (word offsets), 128B rows: identical to CU_TENSOR_MAP_SWIZZLE_128B
__device__ __forceinline__ int sw32(int r, int c) { return r * 32 + 4 * (c ^ (r & 7)); }
// SW64 swizzle (byte offsets), 64B tile rows: for GEMM TMA staging
__device__ __forceinline__ int swt(int r, int c) { return r * 64 + 16 * (c ^ ((r >> 1) & 3)); }

// mbarrier helpers
#define MBAR_INIT(mb, c)  asm volatile("mbarrier.init.shared.b64 [%0], %1;" :: "r"(mb), "r"(c) : "memory")
#define MBAR_EXPECT_TX(mb, n) asm volatile("mbarrier.arrive.expect_tx.shared.b64 _, [%0], %1;" :: "r"(mb), "r"(n) : "memory")
__device__ __forceinline__ void mbar_wait(uint32_t mb, uint32_t ph) {
    asm volatile(
        "{ .reg .pred P1;\n"
        "WL_%=: mbarrier.try_wait.parity.acquire.cta.shared::cta.b64 P1, [%0], %1, 0x989680;\n"
        "@P1 bra.uni WD_%=;\n"
        "bra.uni WL_%=;\n"
        "WD_%=: }"
        :: "r"(mb), "r"(ph) : "memory");
}
__device__ __forceinline__ void tma2d(uint32_t smem, const CUtensorMap* m, int x, int y, uint32_t mb) {
    asm volatile("cp.async.bulk.tensor.2d.shared::cta.global.tile.mbarrier::complete_tx::bytes "
                 "[%0], [%1, {%2, %3}], [%4];"
                 :: "r"(smem), "l"(m), "r"(x), "r"(y), "r"(mb) : "memory");
}

// ---------------------------------------------------------------------------
// Prep: split fp32 tensor into packed hi/lo arrays. which: 0=x 1=Wqkv 2=Wproj.
// ---------------------------------------------------------------------------
__global__ __launch_bounds__(256)
void split_kernel(const float4* __restrict__ src, int which, int n4)
{
    uint2 *h, *l;
    if (which == 0)      { h = (uint2*)g_xh;  l = (uint2*)g_xl;  }
    else if (which == 1) { h = (uint2*)g_Wqh; l = (uint2*)g_Wql; }
    else                 { h = (uint2*)g_Wph; l = (uint2*)g_Wpl; }
    int i = blockIdx.x * 256 + threadIdx.x;
    if (i < n4) {
        float4 v = src[i];
        h[i] = make_uint2(packhi2(v.x, v.y), packhi2(v.z, v.w));
        l[i] = make_uint2(packlo2(v.x, v.y), packlo2(v.z, v.w));
    }
}

// ---------------------------------------------------------------------------
// Split-bf16 GEMM, TMA-fed (unchanged from R10). 3-stage pipeline, 2 CTAs/SM.
// ---------------------------------------------------------------------------
#define STG_BYTES 32768
#define GEMM_SMEM (1024 + 3*STG_BYTES + 64)

template<int MODE>
__global__ __launch_bounds__(256, 2)
void tc_gemm(const __grid_constant__ CUtensorMap mAh,
             const __grid_constant__ CUtensorMap mAl,
             const __grid_constant__ CUtensorMap mBh,
             const __grid_constant__ CUtensorMap mBl,
             const float* __restrict__ bias, float* __restrict__ C)
{
    extern __shared__ __align__(16) uint32_t smu[];
    const uint32_t sbraw = smem_u32(smu);
    const uint32_t sb0 = (sbraw + 1023u) & ~1023u;
    const uint32_t mb0 = sb0 + 3 * STG_BYTES;

    const int tid = threadIdx.x, wid = tid >> 5, lane = tid & 31;
    const int g = lane >> 2, tg = lane & 3;
    const int wm = wid >> 2, wn = wid & 3;
    const int row0 = blockIdx.y * 128, col0 = blockIdx.x * 128;

    const int rA = wm * 64 + (lane & 15);
    const int selA = lane >> 4;
    const int rB = wn * 32 + (lane & 7) + ((lane >> 4) << 3);
    const int selB = (lane >> 3) & 1;

    if (tid == 0) {
        MBAR_INIT(mb0 + 0, 1);
        MBAR_INIT(mb0 + 8, 1);
        MBAR_INIT(mb0 + 16, 1);
    }
    __syncthreads();

    auto issue = [&](int ch, int st) {
        uint32_t base = sb0 + (uint32_t)st * STG_BYTES;
        uint32_t mb = mb0 + st * 8;
        MBAR_EXPECT_TX(mb, STG_BYTES);
        tma2d(base,         &mAh, ch * 64, row0, mb);
        tma2d(base + 8192,  &mAl, ch * 64, row0, mb);
        tma2d(base + 16384, &mBh, ch * 64, col0, mb);
        tma2d(base + 24576, &mBl, ch * 64, col0, mb);
    };
    if (tid == 0) { issue(0, 0); issue(1, 1); issue(2, 2); }

    float c[4][4][4];
#pragma unroll
    for (int mt = 0; mt < 4; mt++)
#pragma unroll
        for (int nt = 0; nt < 4; nt++) {
            c[mt][nt][0] = 0.f; c[mt][nt][1] = 0.f; c[mt][nt][2] = 0.f; c[mt][nt][3] = 0.f;
        }

    for (int ch = 0; ch < 32; ch++) {
        const int st = ch % 3;
        mbar_wait(mb0 + st * 8, (uint32_t)((ch / 3) & 1));
        const uint32_t base = sb0 + (uint32_t)st * STG_BYTES;

#pragma unroll
        for (int ks = 0; ks < 2; ks++) {
            const int cA = 2 * ks + selA;
            const int cB = 2 * ks + selB;
            uint32_t ah[4][4], al[4][4], th[2][4], tl[2][4];
#pragma unroll
            for (int mt = 0; mt < 4; mt++) {
                ldmx4(ah[mt], base + (uint32_t)swt(rA + mt * 16, cA));
                ldmx4(al[mt], base + 8192u + (uint32_t)swt(rA + mt * 16, cA));
            }
#pragma unroll
            for (int ntp = 0; ntp < 2; ntp++) {
                ldmx4(th[ntp], base + 16384u + (uint32_t)swt(rB + ntp * 16, cB));
                ldmx4(tl[ntp], base + 24576u + (uint32_t)swt(rB + ntp * 16, cB));
            }
#pragma unroll
            for (int ntp = 0; ntp < 2; ntp++)
#pragma unroll
                for (int mt = 0; mt < 4; mt++) {
                    mma16(c[mt][2*ntp],   ah[mt], &th[ntp][0]);
                    mma16(c[mt][2*ntp+1], ah[mt], &th[ntp][2]);
                }
#pragma unroll
            for (int ntp = 0; ntp < 2; ntp++)
#pragma unroll
                for (int mt = 0; mt < 4; mt++) {
                    mma16(c[mt][2*ntp],   ah[mt], &tl[ntp][0]);
                    mma16(c[mt][2*ntp+1], ah[mt], &tl[ntp][2]);
                }
#pragma unroll
            for (int ntp = 0; ntp < 2; ntp++)
#pragma unroll
                for (int mt = 0; mt < 4; mt++) {
                    mma16(c[mt][2*ntp],   al[mt], &th[ntp][0]);
                    mma16(c[mt][2*ntp+1], al[mt], &th[ntp][2]);
                }
        }
        __syncthreads();
        if (tid == 0 && ch + 3 < 32) issue(ch + 3, st);
    }

    // Epilogue
#pragma unroll
    for (int mt = 0; mt < 4; mt++) {
#pragma unroll
        for (int hf = 0; hf < 2; hf++) {
            int row = row0 + wm * 64 + mt * 16 + g + hf * 8;
#pragma unroll
            for (int nt = 0; nt < 4; nt++) {
                int col = col0 + wn * 32 + nt * 8 + 2 * tg;
                float v0 = c[mt][nt][hf * 2 + 0] + bias[col];
                float v1 = c[mt][nt][hf * 2 + 1] + bias[col + 1];
                if (MODE == 1) {
                    *(float2*)&C[(size_t)row * DIM_ + col] = make_float2(v0, v1);
                } else {
                    int b = row >> 11, n = row & (NSEQ - 1);
                    int which = col >> 10, rem = col & 1023;
                    int h = rem >> 6, d = rem & 63;
                    size_t w = (((size_t)(b * H_ + h)) * NSEQ + n) * 32 + (d >> 1);
                    if (which == 0) {
                        v0 *= SCALE_F; v1 *= SCALE_F;
                        g_Qh[w] = packhi2(v0, v1); g_Ql[w] = packlo2(v0, v1);
                    } else if (which == 1) {
                        g_Kh[w] = packhi2(v0, v1); g_Kl[w] = packlo2(v0, v1);
                    } else {
                        g_Vh[w] = packhi2(v0, v1); g_Vl[w] = packlo2(v0, v1);
                    }
                }
            }
        }
    }
}

// ---------------------------------------------------------------------------
// Flash focal attention, TMA-fed. Smem word offsets (per R8 layout, unchanged
// ldmatrix addressing since SW128 == sw32): QH 0, QL 4096, KV 8192
// (per stage: KH+0, KL+2048, VH+4096, VL+6144 words; stage stride 8192 words).
// mbarriers at byte 98304: mbQ+0, mb0+8, mb1+16.
// ---------------------------------------------------------------------------
#define FQH 0
#define FQL 4096
#define FKV 8192
#define FKVB 8192
#define FSTG_BYTES 32768
#define FLASH_SMEM (98304 + 64)

__global__ __launch_bounds__(256, 2)
void flash_kernel(const __grid_constant__ CUtensorMap mQh,
                  const __grid_constant__ CUtensorMap mQl,
                  const __grid_constant__ CUtensorMap mKh,
                  const __grid_constant__ CUtensorMap mKl,
                  const __grid_constant__ CUtensorMap mVh,
                  const __grid_constant__ CUtensorMap mVl,
                  const float* __restrict__ falpha, const float* __restrict__ fgamma)
{
    extern __shared__ __align__(16) uint32_t smu[];
    const uint32_t sb = smem_u32(smu);
    const uint32_t mbQ = sb + 98304, mbKV = sb + 98312;
    const int tid = threadIdx.x, wid = tid >> 5, lane = tid & 31;
    const int g = lane >> 2, tg = lane & 3;
    const int bh = blockIdx.y, q0 = blockIdx.x * 128;
    const int qb = wid * 16;

    const float gam = fgamma[0], alpha = falpha[0];
    const bool g2 = (gam == 2.0f);

    const int r16 = lane & 15;
    const int sel = lane >> 4;
    const int rK  = (lane & 7) + ((lane >> 4) << 3);
    const int selB = (lane >> 3) & 1;

    if (tid == 0) {
        MBAR_INIT(mbQ, 1);
        MBAR_INIT(mbKV + 0, 1);
        MBAR_INIT(mbKV + 8, 1);
    }
    __syncthreads();

    auto issueKV = [&](int ch, int st) {
        uint32_t base = sb + 32768u + (uint32_t)st * FSTG_BYTES;
        uint32_t mb = mbKV + st * 8;
        int y = bh * NSEQ + ch * 64;
        MBAR_EXPECT_TX(mb, FSTG_BYTES);
        tma2d(base,          &mKh, 0, y, mb);
        tma2d(base + 8192,   &mKl, 0, y, mb);
        tma2d(base + 16384,  &mVh, 0, y, mb);
        tma2d(base + 24576,  &mVl, 0, y, mb);
    };
    if (tid == 0) {
        MBAR_EXPECT_TX(mbQ, 32768);
        tma2d(sb,          &mQh, 0, bh * NSEQ + q0, mbQ);
        tma2d(sb + 16384,  &mQl, 0, bh * NSEQ + q0, mbQ);
        issueKV(0, 0);
        issueKV(1, 1);
    }
    mbar_wait(mbQ, 0);

    float o[8][4];
#pragma unroll
    for (int nt = 0; nt < 8; nt++) { o[nt][0] = o[nt][1] = o[nt][2] = o[nt][3] = 0.f; }
    float m0 = -1e30f, m1 = -1e30f, Z0 = 0.f, Z1 = 0.f, S20 = 0.f, S21 = 0.f;

    for (int ch = 0; ch < 32; ch++) {
        const int st = ch & 1;
        mbar_wait(mbKV + st * 8, (uint32_t)((ch >> 1) & 1));
        const uint32_t kvb = FKV + (uint32_t)(st * FKVB);

        // ---- S = Q K^T ----
        float s[8][4];
#pragma unroll
        for (int nt = 0; nt < 8; nt++) { s[nt][0] = s[nt][1] = s[nt][2] = s[nt][3] = 0.f; }
#pragma unroll
        for (int ks = 0; ks < 4; ks++) {
            const int cA = 2 * ks + sel;
            const int cB = 2 * ks + selB;
            uint32_t qh[4], ql[4];
            ldmx4(qh, sb + 4u * (uint32_t)(FQH + sw32(qb + r16, cA)));
            ldmx4(ql, sb + 4u * (uint32_t)(FQL + sw32(qb + r16, cA)));
#pragma unroll
            for (int np = 0; np < 2; np++) {
                const int n0 = np * 2;
                uint32_t th0[4], th1[4], tl0[4], tl1[4];
                ldmx4(th0, sb + 4u * (uint32_t)(kvb + sw32(rK + n0 * 16, cB)));
                ldmx4(th1, sb + 4u * (uint32_t)(kvb + sw32(rK + (n0 + 1) * 16, cB)));
                ldmx4(tl0, sb + 4u * (uint32_t)(kvb + 2048 + sw32(rK + n0 * 16, cB)));
                ldmx4(tl1, sb + 4u * (uint32_t)(kvb + 2048 + sw32(rK + (n0 + 1) * 16, cB)));
                mma16(s[2*n0],   qh, &th0[0]); mma16(s[2*n0+1], qh, &th0[2]);
                mma16(s[2*n0+2], qh, &th1[0]); mma16(s[2*n0+3], qh, &th1[2]);
                mma16(s[2*n0],   qh, &tl0[0]); mma16(s[2*n0+1], qh, &tl0[2]);
                mma16(s[2*n0+2], qh, &tl1[0]); mma16(s[2*n0+3], qh, &tl1[2]);
                mma16(s[2*n0],   ql, &th0[0]); mma16(s[2*n0+1], ql, &th0[2]);
                mma16(s[2*n0+2], ql, &th1[0]); mma16(s[2*n0+3], ql, &th1[2]);
            }
        }

        // ---- chunk max per row (quad reduce) ----
        float cm0 = -1e30f, cm1 = -1e30f;
#pragma unroll
        for (int nt = 0; nt < 8; nt++) {
            cm0 = fmaxf(cm0, fmaxf(s[nt][0], s[nt][1]));
            cm1 = fmaxf(cm1, fmaxf(s[nt][2], s[nt][3]));
        }
        cm0 = fmaxf(cm0, __shfl_xor_sync(0xffffffffu, cm0, 1));
        cm0 = fmaxf(cm0, __shfl_xor_sync(0xffffffffu, cm0, 2));
        cm1 = fmaxf(cm1, __shfl_xor_sync(0xffffffffu, cm1, 1));
        cm1 = fmaxf(cm1, __shfl_xor_sync(0xffffffffu, cm1, 2));

        // ---- online rescale ----
        float nm0 = fmaxf(m0, cm0), nm1 = fmaxf(m1, cm1);
        float cz0 = __expf(m0 - nm0), cz1 = __expf(m1 - nm1);
        float cw0 = g2 ? cz0 * cz0 : __expf(gam * (m0 - nm0));
        float cw1 = g2 ? cz1 * cz1 : __expf(gam * (m1 - nm1));
        Z0 *= cz0; Z1 *= cz1; S20 *= cw0; S21 *= cw1; m0 = nm0; m1 = nm1;
#pragma unroll
        for (int nt = 0; nt < 8; nt++) {
            o[nt][0] *= cw0; o[nt][1] *= cw0; o[nt][2] *= cw1; o[nt][3] *= cw1;
        }

        // ---- weights -> register A-frags for PV ----
        uint32_t ph[4][4], pl[4][4];
        float zp0 = 0.f, zp1 = 0.f, wp0 = 0.f, wp1 = 0.f;
#pragma unroll
        for (int nt = 0; nt < 8; nt++) {
            float e0 = __expf(s[nt][0] - m0), e1 = __expf(s[nt][1] - m0);
            float e2 = __expf(s[nt][2] - m1), e3 = __expf(s[nt][3] - m1);
            zp0 += e0 + e1; zp1 += e2 + e3;
            float w0, w1, w2, w3;
            if (g2) { w0 = e0 * e0; w1 = e1 * e1; w2 = e2 * e2; w3 = e3 * e3; }
            else {
                w0 = __expf(gam * (s[nt][0] - m0)); w1 = __expf(gam * (s[nt][1] - m0));
                w2 = __expf(gam * (s[nt][2] - m1)); w3 = __expf(gam * (s[nt][3] - m1));
            }
            wp0 += w0 + w1; wp1 += w2 + w3;
            const int ks = nt >> 1, off = (nt & 1) * 2;
            ph[ks][off]     = packhi2(w0, w1);
            ph[ks][off + 1] = packhi2(w2, w3);
            pl[ks][off]     = packlo2(w0, w1);
            pl[ks][off + 1] = packlo2(w2, w3);
        }
        Z0 += zp0; Z1 += zp1; S20 += wp0; S21 += wp1;

        // ---- O += P V ----
#pragma unroll
        for (int ks = 0; ks < 4; ks++) {
            const int k0 = ks * 16;
#pragma unroll
            for (int dp2 = 0; dp2 < 2; dp2++) {
                const int d0 = dp2 * 2;
                uint32_t th0[4], th1[4], tl0[4], tl1[4];
                ldmx4t(th0, sb + 4u * (uint32_t)(kvb + 4096 + sw32(k0 + r16, d0 * 2 + sel)));
                ldmx4t(th1, sb + 4u * (uint32_t)(kvb + 4096 + sw32(k0 + r16, (d0 + 1) * 2 + sel)));
                ldmx4t(tl0, sb + 4u * (uint32_t)(kvb + 6144 + sw32(k0 + r16, d0 * 2 + sel)));
                ldmx4t(tl1, sb + 4u * (uint32_t)(kvb + 6144 + sw32(k0 + r16, (d0 + 1) * 2 + sel)));
                mma16(o[2*d0],   ph[ks], &th0[0]); mma16(o[2*d0+1], ph[ks], &th0[2]);
                mma16(o[2*d0+2], ph[ks], &th1[0]); mma16(o[2*d0+3], ph[ks], &th1[2]);
                mma16(o[2*d0],   ph[ks], &tl0[0]); mma16(o[2*d0+1], ph[ks], &tl0[2]);
                mma16(o[2*d0+2], ph[ks], &tl1[0]); mma16(o[2*d0+3], ph[ks], &tl1[2]);
                mma16(o[2*d0],   pl[ks], &th0[0]); mma16(o[2*d0+1], pl[ks], &th0[2]);
                mma16(o[2*d0+2], pl[ks], &th1[0]); mma16(o[2*d0+3], pl[ks], &th1[2]);
            }
        }

        __syncthreads();   // all warps done reading stage st
        if (tid == 0 && ch + 2 < 32) issueKV(ch + 2, st);
    }

    // ---- final reduce + packed split write of AO ----
    Z0  += __shfl_xor_sync(0xffffffffu, Z0, 1);  Z0  += __shfl_xor_sync(0xffffffffu, Z0, 2);
    Z1  += __shfl_xor_sync(0xffffffffu, Z1, 1);  Z1  += __shfl_xor_sync(0xffffffffu, Z1, 2);
    S20 += __shfl_xor_sync(0xffffffffu, S20, 1); S20 += __shfl_xor_sync(0xffffffffu, S20, 2);
    S21 += __shfl_xor_sync(0xffffffffu, S21, 1); S21 += __shfl_xor_sync(0xffffffffu, S21, 2);

    float Zg0 = g2 ? Z0 * Z0 : __powf(Z0, gam);
    float Zg1 = g2 ? Z1 * Z1 : __powf(Z1, gam);
    float sc0 = alpha / (alpha * S20 + 1e-6f * Zg0);
    float sc1 = alpha / (alpha * S21 + 1e-6f * Zg1);

    const int b = bh >> 4, h = bh & 15;
    const int qA = q0 + qb + g, qB = qA + 8;
#pragma unroll
    for (int nt = 0; nt < 8; nt++) {
        int d = nt * 8 + 2 * tg;
        size_t wA = ((size_t)b * NSEQ + qA) * 512 + ((h * HD_ + d) >> 1);
        size_t wB = ((size_t)b * NSEQ + qB) * 512 + ((h * HD_ + d) >> 1);
        float a0 = o[nt][0] * sc0, a1 = o[nt][1] * sc0;
        float b0 = o[nt][2] * sc1, b1 = o[nt][3] * sc1;
        g_AOh[wA] = packhi2(a0, a1); g_AOl[wA] = packlo2(a0, a1);
        g_AOh[wB] = packhi2(b0, b1); g_AOl[wB] = packlo2(b0, b1);
    }
}

// ---------------------------------------------------------------------------
typedef CUresult (*EncodeFn)(CUtensorMap*, CUtensorMapDataType, cuuint32_t, void*,
                             const cuuint64_t*, const cuuint64_t*, const cuuint32_t*,
                             const cuuint32_t*, CUtensorMapInterleave, CUtensorMapSwizzle,
                             CUtensorMapL2promotion, CUtensorMapFloatOOBfill);

static void make_map(EncodeFn enc, CUtensorMap* m, void* ptr,
                     unsigned long long rows, unsigned long long row_bytes,
                     unsigned box_w, unsigned box_h, CUtensorMapSwizzle sw) {
    cuuint64_t dims[2]    = {row_bytes, rows};
    cuuint64_t strides[1] = {row_bytes};
    cuuint32_t box[2]     = {box_w, box_h};
    cuuint32_t es[2]      = {1u, 1u};
    enc(m, CU_TENSOR_MAP_DATA_TYPE_UINT8, 2, ptr, dims, strides, box, es,
        CU_TENSOR_MAP_INTERLEAVE_NONE, sw,
        CU_TENSOR_MAP_L2_PROMOTION_L2_128B, CU_TENSOR_MAP_FLOAT_OOB_FILL_NONE);
}

extern "C" void kernel_launch(void* const* d_in, const int* in_sizes, int n_in,
                              void* d_out, int out_size)
{
    const float* x = nullptr, *Wqkv = nullptr, *bqkv = nullptr;
    const float* Wproj = nullptr, *bproj = nullptr, *fa = nullptr, *fg = nullptr;
    for (int i = 0; i < n_in; i++) {
        int sz = in_sizes[i];
        const float* p = (const float*)d_in[i];
        if      (sz == B_*NSEQ*DIM_)   x = p;
        else if (sz == 3*DIM_*DIM_)    Wqkv = p;
        else if (sz == 3*DIM_)         bqkv = p;
        else if (sz == DIM_*DIM_)      Wproj = p;
        else if (sz == DIM_)           bproj = p;
        else if (sz == 1)              { if (!fa) fa = p; else fg = p; }
    }
    float* out = (float*)d_out;

    cudaFuncSetAttribute(tc_gemm<0>,   cudaFuncAttributeMaxDynamicSharedMemorySize, GEMM_SMEM);
    cudaFuncSetAttribute(tc_gemm<1>,   cudaFuncAttributeMaxDynamicSharedMemorySize, GEMM_SMEM);
    cudaFuncSetAttribute(flash_kernel, cudaFuncAttributeMaxDynamicSharedMemorySize, FLASH_SMEM);

    EncodeFn enc = nullptr;
#if CUDART_VERSION >= 12000
    {
        cudaDriverEntryPointQueryResult qr;
        cudaGetDriverEntryPoint("cuTensorMapEncodeTiled", (void**)&enc,
                                cudaEnableDefault, &qr);
    }
#else
    cudaGetDriverEntryPoint("cuTensorMapEncodeTiled", (void**)&enc, cudaEnableDefault);
#endif

    void *p_xh, *p_xl, *p_Wqh, *p_Wql, *p_Wph, *p_Wpl, *p_AOh, *p_AOl;
    void *p_Qh, *p_Ql, *p_Kh, *p_Kl, *p_Vh, *p_Vl;
    cudaGetSymbolAddress(&p_xh,  g_xh);  cudaGetSymbolAddress(&p_xl,  g_xl);
    cudaGetSymbolAddress(&p_Wqh, g_Wqh); cudaGetSymbolAddress(&p_Wql, g_Wql);
    cudaGetSymbolAddress(&p_Wph, g_Wph); cudaGetSymbolAddress(&p_Wpl, g_Wpl);
    cudaGetSymbolAddress(&p_AOh, g_AOh); cudaGetSymbolAddress(&p_AOl, g_AOl);
    cudaGetSymbolAddress(&p_Qh,  g_Qh);  cudaGetSymbolAddress(&p_Ql,  g_Ql);
    cudaGetSymbolAddress(&p_Kh,  g_Kh);  cudaGetSymbolAddress(&p_Kl,  g_Kl);
    cudaGetSymbolAddress(&p_Vh,  g_Vh);  cudaGetSymbolAddress(&p_Vl,  g_Vl);

    const unsigned long long KVROWS = (unsigned long long)B_ * H_ * NSEQ;
    CUtensorMap m_xh, m_xl, m_Wqh, m_Wql, m_Wph, m_Wpl, m_AOh, m_AOl;
    CUtensorMap m_Qh, m_Ql, m_Kh, m_Kl, m_Vh, m_Vl;
    make_map(enc, &m_xh,  p_xh,  4096, 2048, 64, 128, CU_TENSOR_MAP_SWIZZLE_64B);
    make_map(enc, &m_xl,  p_xl,  4096, 2048, 64, 128, CU_TENSOR_MAP_SWIZZLE_64B);
    make_map(enc, &m_Wqh, p_Wqh, 3072, 2048, 64, 128, CU_TENSOR_MAP_SWIZZLE_64B);
    make_map(enc, &m_Wql, p_Wql, 3072, 2048, 64, 128, CU_TENSOR_MAP_SWIZZLE_64B);
    make_map(enc, &m_Wph, p_Wph, 1024, 2048, 64, 128, CU_TENSOR_MAP_SWIZZLE_64B);
    make_map(enc, &m_Wpl, p_Wpl, 1024, 2048, 64, 128, CU_TENSOR_MAP_SWIZZLE_64B);
    make_map(enc, &m_AOh, p_AOh, 4096, 2048, 64, 128, CU_TENSOR_MAP_SWIZZLE_64B);
    make_map(enc, &m_AOl, p_AOl, 4096, 2048, 64, 128, CU_TENSOR_MAP_SWIZZLE_64B);
    make_map(enc, &m_Qh,  p_Qh,  KVROWS, 128, 128, 128, CU_TENSOR_MAP_SWIZZLE_128B);
    make_map(enc, &m_Ql,  p_Ql,  KVROWS, 128, 128, 128, CU_TENSOR_MAP_SWIZZLE_128B);
    make_map(enc, &m_Kh,  p_Kh,  KVROWS, 128, 128, 64,  CU_TENSOR_MAP_SWIZZLE_128B);
    make_map(enc, &m_Kl,  p_Kl,  KVROWS, 128, 128, 64,  CU_TENSOR_MAP_SWIZZLE_128B);
    make_map(enc, &m_Vh,  p_Vh,  KVROWS, 128, 128, 64,  CU_TENSOR_MAP_SWIZZLE_128B);
    make_map(enc, &m_Vl,  p_Vl,  KVROWS, 128, 128, 64,  CU_TENSOR_MAP_SWIZZLE_128B);

    // 0) Split inputs into packed bf16 hi/lo
    split_kernel<<<4096, 256>>>((const float4*)x,     0, 4096*256);
    split_kernel<<<3072, 256>>>((const float4*)Wqkv,  1, 3072*256);
    split_kernel<<<1024, 256>>>((const float4*)Wproj, 2, 1024*256);
    // 1) Fused QKV projection -> packed Q(scaled)/K/V
    tc_gemm<0><<<dim3(3*DIM_/128, (B_*NSEQ)/128), 256, GEMM_SMEM>>>(
        m_xh, m_xl, m_Wqh, m_Wql, bqkv, nullptr);
    // 2) Focal flash attention -> packed AO
    flash_kernel<<<dim3(NSEQ/128, B_*H_), 256, FLASH_SMEM>>>(
        m_Qh, m_Ql, m_Kh, m_Kl, m_Vh, m_Vl, fa, fg);
    // 3) Output projection -> d_out
    tc_gemm<1><<<dim3(DIM_/128, (B_*NSEQ)/128), 256, GEMM_SMEM>>>(
        m_AOh, m_AOl, m_Wph, m_Wpl, bproj, out);
}

// round 12
// speedup vs baseline: 1.2599x; 1.0215x over previous
#include <cuda_runtime.h>
#include <cuda.h>
#include <cstdint>

// Problem constants
#define B_    2
#define NSEQ  2048
#define DIM_  1024
#define H_    16
#define HD_   64
#define SCALE_F 0.125f   // HD^-0.5

// ---------------------------------------------------------------------------
// Packed split storage: uint32 = {bf16 elem k (low), bf16 elem k+1 (high)}.
// hi = top16 of fp32; lo = bf16(x - hi).  A*B ~= Ah*Bh + Ah*Bl + Al*Bh.
// ---------------------------------------------------------------------------
__device__ __align__(1024) uint32_t g_xh [4096*512], g_xl [4096*512];
__device__ __align__(1024) uint32_t g_Wqh[3072*512], g_Wql[3072*512];
__device__ __align__(1024) uint32_t g_Wph[1024*512], g_Wpl[1024*512];
#define QKV_W (B_*H_*NSEQ*32)
__device__ __align__(1024) uint32_t g_Qh[QKV_W], g_Ql[QKV_W];
__device__ __align__(1024) uint32_t g_Kh[QKV_W], g_Kl[QKV_W];
__device__ __align__(1024) uint32_t g_Vh[QKV_W], g_Vl[QKV_W];
__device__ __align__(1024) uint32_t g_AOh[4096*512], g_AOl[4096*512];

// ---------------------------------------------------------------------------
__device__ __forceinline__ uint32_t packhi2(float x, float y) {
    return __byte_perm(__float_as_uint(x), __float_as_uint(y), 0x7632);
}
__device__ __forceinline__ uint32_t packlo2(float x, float y) {
    float lx = x - __uint_as_float(__float_as_uint(x) & 0xffff0000u);
    float ly = y - __uint_as_float(__float_as_uint(y) & 0xffff0000u);
    return __byte_perm(__float_as_uint(lx), __float_as_uint(ly), 0x7632);
}
__device__ __forceinline__ uint32_t smem_u32(const void* p) {
    uint32_t a;
    asm("{ .reg .u64 t; cvta.to.shared.u64 t, %1; cvt.u32.u64 %0, t; }" : "=r"(a) : "l"(p));
    return a;
}
__device__ __forceinline__ void mma16(float* c, const uint32_t* a, const uint32_t* b) {
    asm("mma.sync.aligned.m16n8k16.row.col.f32.bf16.bf16.f32 "
        "{%0,%1,%2,%3}, {%4,%5,%6,%7}, {%8,%9}, {%0,%1,%2,%3};"
        : "+f"(c[0]), "+f"(c[1]), "+f"(c[2]), "+f"(c[3])
        : "r"(a[0]), "r"(a[1]), "r"(a[2]), "r"(a[3]), "r"(b[0]), "r"(b[1]));
}
__device__ __forceinline__ void ldmx4(uint32_t* r, uint32_t a) {
    asm volatile("ldmatrix.sync.aligned.m8n8.x4.shared.b16 {%0,%1,%2,%3}, [%4];"
        : "=r"(r[0]), "=r"(r[1]), "=r"(r[2]), "=r"(r[3]) : "r"(a));
}
__device__ __forceinline__ void ldmx4t(uint32_t* r, uint32_t a) {
    asm volatile("ldmatrix.sync.aligned.m8n8.x4.trans.shared.b16 {%0,%1,%2,%3}, [%4];"
        : "=r"(r[0]), "=r"(r[1]), "=r"(r[2]), "=r"(r[3]) : "r"(a));
}
// SW128 swizzle (word offsets), 128B rows (== CU_TENSOR_MAP_SWIZZLE_128B)
__device__ __forceinline__ int sw32(int r, int c) { return r * 32 + 4 * (c ^ (r & 7)); }
// SW64 swizzle (byte offsets), 64B tile rows
__device__ __forceinline__ int swt(int r, int c) { return r * 64 + 16 * (c ^ ((r >> 1) & 3)); }

// mbarrier helpers
#define MBAR_INIT(mb, c)  asm volatile("mbarrier.init.shared.b64 [%0], %1;" :: "r"(mb), "r"(c) : "memory")
#define MBAR_EXPECT_TX(mb, n) asm volatile("mbarrier.arrive.expect_tx.shared.b64 _, [%0], %1;" :: "r"(mb), "r"(n) : "memory")
#define MBAR_ARRIVE(mb)   asm volatile("mbarrier.arrive.shared.b64 _, [%0];" :: "r"(mb) : "memory")
__device__ __forceinline__ void mbar_wait(uint32_t mb, uint32_t ph) {
    asm volatile(
        "{ .reg .pred P1;\n"
        "WL_%=: mbarrier.try_wait.parity.acquire.cta.shared::cta.b64 P1, [%0], %1, 0x989680;\n"
        "@P1 bra.uni WD_%=;\n"
        "bra.uni WL_%=;\n"
        "WD_%=: }"
        :: "r"(mb), "r"(ph) : "memory");
}
__device__ __forceinline__ void tma2d(uint32_t smem, const CUtensorMap* m, int x, int y, uint32_t mb) {
    asm volatile("cp.async.bulk.tensor.2d.shared::cta.global.tile.mbarrier::complete_tx::bytes "
                 "[%0], [%1, {%2, %3}], [%4];"
                 :: "r"(smem), "l"(m), "r"(x), "r"(y), "r"(mb) : "memory");
}

// ---------------------------------------------------------------------------
// Fused prep: split all three fp32 inputs into packed hi/lo arrays.
// blocks [0,4096): x   [4096,7168): Wqkv   [7168,8192): Wproj
// ---------------------------------------------------------------------------
__global__ __launch_bounds__(256)
void split_kernel(const float4* __restrict__ sx, const float4* __restrict__ swq,
                  const float4* __restrict__ swp)
{
    int bid = blockIdx.x;
    const float4* src; uint2 *h, *l; int base;
    if (bid < 4096)      { src = sx;  h = (uint2*)g_xh;  l = (uint2*)g_xl;  base = bid; }
    else if (bid < 7168) { src = swq; h = (uint2*)g_Wqh; l = (uint2*)g_Wql; base = bid - 4096; }
    else                 { src = swp; h = (uint2*)g_Wph; l = (uint2*)g_Wpl; base = bid - 7168; }
    int i = base * 256 + threadIdx.x;
    float4 v = src[i];
    h[i] = make_uint2(packhi2(v.x, v.y), packhi2(v.z, v.w));
    l[i] = make_uint2(packlo2(v.x, v.y), packlo2(v.z, v.w));
}

// ---------------------------------------------------------------------------
// Split-bf16 GEMM, TMA-fed, producer-consumer mbarriers (NO per-chunk
// __syncthreads). 3-stage pipeline; full[st] gates consumers, empty[st]
// (count 8: one arrive per warp) gates the producer's re-issue.
// ---------------------------------------------------------------------------
#define STG_BYTES 32768
#define GEMM_SMEM (1024 + 3*STG_BYTES + 64)

template<int MODE>
__global__ __launch_bounds__(256, 2)
void tc_gemm(const __grid_constant__ CUtensorMap mAh,
             const __grid_constant__ CUtensorMap mAl,
             const __grid_constant__ CUtensorMap mBh,
             const __grid_constant__ CUtensorMap mBl,
             const float* __restrict__ bias, float* __restrict__ C)
{
    extern __shared__ __align__(16) uint32_t smu[];
    const uint32_t sbraw = smem_u32(smu);
    const uint32_t sb0 = (sbraw + 1023u) & ~1023u;
    const uint32_t mbF = sb0 + 3 * STG_BYTES;        // full[3] at +0,+8,+16
    const uint32_t mbE = mbF + 24;                   // empty[3] at +0,+8,+16

    const int tid = threadIdx.x, wid = tid >> 5, lane = tid & 31;
    const int g = lane >> 2, tg = lane & 3;
    const int wm = wid >> 2, wn = wid & 3;
    const int row0 = blockIdx.y * 128, col0 = blockIdx.x * 128;

    const int rA = wm * 64 + (lane & 15);
    const int selA = lane >> 4;
    const int rB = wn * 32 + (lane & 7) + ((lane >> 4) << 3);
    const int selB = (lane >> 3) & 1;

    if (tid == 0) {
#pragma unroll
        for (int s = 0; s < 3; s++) { MBAR_INIT(mbF + s * 8, 1); MBAR_INIT(mbE + s * 8, 8); }
    }
    __syncthreads();

    auto issue = [&](int ch, int st) {
        uint32_t base = sb0 + (uint32_t)st * STG_BYTES;
        uint32_t mb = mbF + st * 8;
        MBAR_EXPECT_TX(mb, STG_BYTES);
        tma2d(base,         &mAh, ch * 64, row0, mb);
        tma2d(base + 8192,  &mAl, ch * 64, row0, mb);
        tma2d(base + 16384, &mBh, ch * 64, col0, mb);
        tma2d(base + 24576, &mBl, ch * 64, col0, mb);
    };
    if (tid == 0) { issue(0, 0); issue(1, 1); issue(2, 2); }

    float c[4][4][4];
#pragma unroll
    for (int mt = 0; mt < 4; mt++)
#pragma unroll
        for (int nt = 0; nt < 4; nt++) {
            c[mt][nt][0] = 0.f; c[mt][nt][1] = 0.f; c[mt][nt][2] = 0.f; c[mt][nt][3] = 0.f;
        }

    for (int ch = 0; ch < 32; ch++) {
        const int st = ch % 3;
        mbar_wait(mbF + st * 8, (uint32_t)((ch / 3) & 1));
        const uint32_t base = sb0 + (uint32_t)st * STG_BYTES;

#pragma unroll
        for (int ks = 0; ks < 2; ks++) {
            const int cA = 2 * ks + selA;
            const int cB = 2 * ks + selB;
            uint32_t ah[4][4], al[4][4], th[2][4], tl[2][4];
#pragma unroll
            for (int mt = 0; mt < 4; mt++) {
                ldmx4(ah[mt], base + (uint32_t)swt(rA + mt * 16, cA));
                ldmx4(al[mt], base + 8192u + (uint32_t)swt(rA + mt * 16, cA));
            }
#pragma unroll
            for (int ntp = 0; ntp < 2; ntp++) {
                ldmx4(th[ntp], base + 16384u + (uint32_t)swt(rB + ntp * 16, cB));
                ldmx4(tl[ntp], base + 24576u + (uint32_t)swt(rB + ntp * 16, cB));
            }
#pragma unroll
            for (int ntp = 0; ntp < 2; ntp++)
#pragma unroll
                for (int mt = 0; mt < 4; mt++) {
                    mma16(c[mt][2*ntp],   ah[mt], &th[ntp][0]);
                    mma16(c[mt][2*ntp+1], ah[mt], &th[ntp][2]);
                }
#pragma unroll
            for (int ntp = 0; ntp < 2; ntp++)
#pragma unroll
                for (int mt = 0; mt < 4; mt++) {
                    mma16(c[mt][2*ntp],   ah[mt], &tl[ntp][0]);
                    mma16(c[mt][2*ntp+1], ah[mt], &tl[ntp][2]);
                }
#pragma unroll
            for (int ntp = 0; ntp < 2; ntp++)
#pragma unroll
                for (int mt = 0; mt < 4; mt++) {
                    mma16(c[mt][2*ntp],   al[mt], &th[ntp][0]);
                    mma16(c[mt][2*ntp+1], al[mt], &th[ntp][2]);
                }
        }
        // this warp is done reading stage st (ldmatrix is warp-synchronous)
        if (lane == 0) MBAR_ARRIVE(mbE + st * 8);
        // producer: wait all 8 warps retired stage st, then refill it
        if (tid == 0 && ch + 3 < 32) {
            mbar_wait(mbE + st * 8, (uint32_t)((ch / 3) & 1));
            issue(ch + 3, st);
        }
    }

    // Epilogue
#pragma unroll
    for (int mt = 0; mt < 4; mt++) {
#pragma unroll
        for (int hf = 0; hf < 2; hf++) {
            int row = row0 + wm * 64 + mt * 16 + g + hf * 8;
#pragma unroll
            for (int nt = 0; nt < 4; nt++) {
                int col = col0 + wn * 32 + nt * 8 + 2 * tg;
                float v0 = c[mt][nt][hf * 2 + 0] + bias[col];
                float v1 = c[mt][nt][hf * 2 + 1] + bias[col + 1];
                if (MODE == 1) {
                    *(float2*)&C[(size_t)row * DIM_ + col] = make_float2(v0, v1);
                } else {
                    int b = row >> 11, n = row & (NSEQ - 1);
                    int which = col >> 10, rem = col & 1023;
                    int h = rem >> 6, d = rem & 63;
                    size_t w = (((size_t)(b * H_ + h)) * NSEQ + n) * 32 + (d >> 1);
                    if (which == 0) {
                        v0 *= SCALE_F; v1 *= SCALE_F;
                        g_Qh[w] = packhi2(v0, v1); g_Ql[w] = packlo2(v0, v1);
                    } else if (which == 1) {
                        g_Kh[w] = packhi2(v0, v1); g_Kl[w] = packlo2(v0, v1);
                    } else {
                        g_Vh[w] = packhi2(v0, v1); g_Vl[w] = packlo2(v0, v1);
                    }
                }
            }
        }
    }
}

// ---------------------------------------------------------------------------
// Flash focal attention, TMA-fed, producer-consumer mbarriers.
// Smem: QH 0, QL 4096, KV 8192 words (2 stages of 8192 words).
// mbarriers at byte 98304: mbQ+0; full[2] +8,+16; empty[2] +24,+32.
// ---------------------------------------------------------------------------
#define FQH 0
#define FQL 4096
#define FKV 8192
#define FKVB 8192
#define FSTG_BYTES 32768
#define FLASH_SMEM (98304 + 64)

__global__ __launch_bounds__(256, 2)
void flash_kernel(const __grid_constant__ CUtensorMap mQh,
                  const __grid_constant__ CUtensorMap mQl,
                  const __grid_constant__ CUtensorMap mKh,
                  const __grid_constant__ CUtensorMap mKl,
                  const __grid_constant__ CUtensorMap mVh,
                  const __grid_constant__ CUtensorMap mVl,
                  const float* __restrict__ falpha, const float* __restrict__ fgamma)
{
    extern __shared__ __align__(16) uint32_t smu[];
    const uint32_t sb = smem_u32(smu);
    const uint32_t mbQ = sb + 98304, mbF = sb + 98312, mbE = sb + 98328;
    const int tid = threadIdx.x, wid = tid >> 5, lane = tid & 31;
    const int g = lane >> 2, tg = lane & 3;
    const int bh = blockIdx.y, q0 = blockIdx.x * 128;
    const int qb = wid * 16;

    const float gam = fgamma[0], alpha = falpha[0];
    const bool g2 = (gam == 2.0f);

    const int r16 = lane & 15;
    const int sel = lane >> 4;
    const int rK  = (lane & 7) + ((lane >> 4) << 3);
    const int selB = (lane >> 3) & 1;

    if (tid == 0) {
        MBAR_INIT(mbQ, 1);
#pragma unroll
        for (int s = 0; s < 2; s++) { MBAR_INIT(mbF + s * 8, 1); MBAR_INIT(mbE + s * 8, 8); }
    }
    __syncthreads();

    auto issueKV = [&](int ch, int st) {
        uint32_t base = sb + 32768u + (uint32_t)st * FSTG_BYTES;
        uint32_t mb = mbF + st * 8;
        int y = bh * NSEQ + ch * 64;
        MBAR_EXPECT_TX(mb, FSTG_BYTES);
        tma2d(base,          &mKh, 0, y, mb);
        tma2d(base + 8192,   &mKl, 0, y, mb);
        tma2d(base + 16384,  &mVh, 0, y, mb);
        tma2d(base + 24576,  &mVl, 0, y, mb);
    };
    if (tid == 0) {
        MBAR_EXPECT_TX(mbQ, 32768);
        tma2d(sb,          &mQh, 0, bh * NSEQ + q0, mbQ);
        tma2d(sb + 16384,  &mQl, 0, bh * NSEQ + q0, mbQ);
        issueKV(0, 0);
        issueKV(1, 1);
    }
    mbar_wait(mbQ, 0);

    float o[8][4];
#pragma unroll
    for (int nt = 0; nt < 8; nt++) { o[nt][0] = o[nt][1] = o[nt][2] = o[nt][3] = 0.f; }
    float m0 = -1e30f, m1 = -1e30f, Z0 = 0.f, Z1 = 0.f, S20 = 0.f, S21 = 0.f;

    for (int ch = 0; ch < 32; ch++) {
        const int st = ch & 1;
        mbar_wait(mbF + st * 8, (uint32_t)((ch >> 1) & 1));
        const uint32_t kvb = FKV + (uint32_t)(st * FKVB);

        // ---- S = Q K^T ----
        float s[8][4];
#pragma unroll
        for (int nt = 0; nt < 8; nt++) { s[nt][0] = s[nt][1] = s[nt][2] = s[nt][3] = 0.f; }
#pragma unroll
        for (int ks = 0; ks < 4; ks++) {
            const int cA = 2 * ks + sel;
            const int cB = 2 * ks + selB;
            uint32_t qh[4], ql[4];
            ldmx4(qh, sb + 4u * (uint32_t)(FQH + sw32(qb + r16, cA)));
            ldmx4(ql, sb + 4u * (uint32_t)(FQL + sw32(qb + r16, cA)));
#pragma unroll
            for (int np = 0; np < 2; np++) {
                const int n0 = np * 2;
                uint32_t th0[4], th1[4], tl0[4], tl1[4];
                ldmx4(th0, sb + 4u * (uint32_t)(kvb + sw32(rK + n0 * 16, cB)));
                ldmx4(th1, sb + 4u * (uint32_t)(kvb + sw32(rK + (n0 + 1) * 16, cB)));
                ldmx4(tl0, sb + 4u * (uint32_t)(kvb + 2048 + sw32(rK + n0 * 16, cB)));
                ldmx4(tl1, sb + 4u * (uint32_t)(kvb + 2048 + sw32(rK + (n0 + 1) * 16, cB)));
                mma16(s[2*n0],   qh, &th0[0]); mma16(s[2*n0+1], qh, &th0[2]);
                mma16(s[2*n0+2], qh, &th1[0]); mma16(s[2*n0+3], qh, &th1[2]);
                mma16(s[2*n0],   qh, &tl0[0]); mma16(s[2*n0+1], qh, &tl0[2]);
                mma16(s[2*n0+2], qh, &tl1[0]); mma16(s[2*n0+3], qh, &tl1[2]);
                mma16(s[2*n0],   ql, &th0[0]); mma16(s[2*n0+1], ql, &th0[2]);
                mma16(s[2*n0+2], ql, &th1[0]); mma16(s[2*n0+3], ql, &th1[2]);
            }
        }

        // ---- chunk max per row (quad reduce) ----
        float cm0 = -1e30f, cm1 = -1e30f;
#pragma unroll
        for (int nt = 0; nt < 8; nt++) {
            cm0 = fmaxf(cm0, fmaxf(s[nt][0], s[nt][1]));
            cm1 = fmaxf(cm1, fmaxf(s[nt][2], s[nt][3]));
        }
        cm0 = fmaxf(cm0, __shfl_xor_sync(0xffffffffu, cm0, 1));
        cm0 = fmaxf(cm0, __shfl_xor_sync(0xffffffffu, cm0, 2));
        cm1 = fmaxf(cm1, __shfl_xor_sync(0xffffffffu, cm1, 1));
        cm1 = fmaxf(cm1, __shfl_xor_sync(0xffffffffu, cm1, 2));

        // ---- online rescale ----
        float nm0 = fmaxf(m0, cm0), nm1 = fmaxf(m1, cm1);
        float cz0 = __expf(m0 - nm0), cz1 = __expf(m1 - nm1);
        float cw0 = g2 ? cz0 * cz0 : __expf(gam * (m0 - nm0));
        float cw1 = g2 ? cz1 * cz1 : __expf(gam * (m1 - nm1));
        Z0 *= cz0; Z1 *= cz1; S20 *= cw0; S21 *= cw1; m0 = nm0; m1 = nm1;
#pragma unroll
        for (int nt = 0; nt < 8; nt++) {
            o[nt][0] *= cw0; o[nt][1] *= cw0; o[nt][2] *= cw1; o[nt][3] *= cw1;
        }

        // ---- weights -> register A-frags for PV ----
        uint32_t ph[4][4], pl[4][4];
        float zp0 = 0.f, zp1 = 0.f, wp0 = 0.f, wp1 = 0.f;
#pragma unroll
        for (int nt = 0; nt < 8; nt++) {
            float e0 = __expf(s[nt][0] - m0), e1 = __expf(s[nt][1] - m0);
            float e2 = __expf(s[nt][2] - m1), e3 = __expf(s[nt][3] - m1);
            zp0 += e0 + e1; zp1 += e2 + e3;
            float w0, w1, w2, w3;
            if (g2) { w0 = e0 * e0; w1 = e1 * e1; w2 = e2 * e2; w3 = e3 * e3; }
            else {
                w0 = __expf(gam * (s[nt][0] - m0)); w1 = __expf(gam * (s[nt][1] - m0));
                w2 = __expf(gam * (s[nt][2] - m1)); w3 = __expf(gam * (s[nt][3] - m1));
            }
            wp0 += w0 + w1; wp1 += w2 + w3;
            const int ks = nt >> 1, off = (nt & 1) * 2;
            ph[ks][off]     = packhi2(w0, w1);
            ph[ks][off + 1] = packhi2(w2, w3);
            pl[ks][off]     = packlo2(w0, w1);
            pl[ks][off + 1] = packlo2(w2, w3);
        }
        Z0 += zp0; Z1 += zp1; S20 += wp0; S21 += wp1;

        // ---- O += P V ----
#pragma unroll
        for (int ks = 0; ks < 4; ks++) {
            const int k0 = ks * 16;
#pragma unroll
            for (int dp2 = 0; dp2 < 2; dp2++) {
                const int d0 = dp2 * 2;
                uint32_t th0[4], th1[4], tl0[4], tl1[4];
                ldmx4t(th0, sb + 4u * (uint32_t)(kvb + 4096 + sw32(k0 + r16, d0 * 2 + sel)));
                ldmx4t(th1, sb + 4u * (uint32_t)(kvb + 4096 + sw32(k0 + r16, (d0 + 1) * 2 + sel)));
                ldmx4t(tl0, sb + 4u * (uint32_t)(kvb + 6144 + sw32(k0 + r16, d0 * 2 + sel)));
                ldmx4t(tl1, sb + 4u * (uint32_t)(kvb + 6144 + sw32(k0 + r16, (d0 + 1) * 2 + sel)));
                mma16(o[2*d0],   ph[ks], &th0[0]); mma16(o[2*d0+1], ph[ks], &th0[2]);
                mma16(o[2*d0+2], ph[ks], &th1[0]); mma16(o[2*d0+3], ph[ks], &th1[2]);
                mma16(o[2*d0],   ph[ks], &tl0[0]); mma16(o[2*d0+1], ph[ks], &tl0[2]);
                mma16(o[2*d0+2], ph[ks], &tl1[0]); mma16(o[2*d0+3], ph[ks], &tl1[2]);
                mma16(o[2*d0],   pl[ks], &th0[0]); mma16(o[2*d0+1], pl[ks], &th0[2]);
                mma16(o[2*d0+2], pl[ks], &th1[0]); mma16(o[2*d0+3], pl[ks], &th1[2]);
            }
        }

        // warp done with stage st; producer refills once all 8 arrive
        if (lane == 0) MBAR_ARRIVE(mbE + st * 8);
        if (tid == 0 && ch + 2 < 32) {
            mbar_wait(mbE + st * 8, (uint32_t)((ch >> 1) & 1));
            issueKV(ch + 2, st);
        }
    }

    // ---- final reduce + packed split write of AO ----
    Z0  += __shfl_xor_sync(0xffffffffu, Z0, 1);  Z0  += __shfl_xor_sync(0xffffffffu, Z0, 2);
    Z1  += __shfl_xor_sync(0xffffffffu, Z1, 1);  Z1  += __shfl_xor_sync(0xffffffffu, Z1, 2);
    S20 += __shfl_xor_sync(0xffffffffu, S20, 1); S20 += __shfl_xor_sync(0xffffffffu, S20, 2);
    S21 += __shfl_xor_sync(0xffffffffu, S21, 1); S21 += __shfl_xor_sync(0xffffffffu, S21, 2);

    float Zg0 = g2 ? Z0 * Z0 : __powf(Z0, gam);
    float Zg1 = g2 ? Z1 * Z1 : __powf(Z1, gam);
    float sc0 = alpha / (alpha * S20 + 1e-6f * Zg0);
    float sc1 = alpha / (alpha * S21 + 1e-6f * Zg1);

    const int b = bh >> 4, h = bh & 15;
    const int qA = q0 + qb + g, qB = qA + 8;
#pragma unroll
    for (int nt = 0; nt < 8; nt++) {
        int d = nt * 8 + 2 * tg;
        size_t wA = ((size_t)b * NSEQ + qA) * 512 + ((h * HD_ + d) >> 1);
        size_t wB = ((size_t)b * NSEQ + qB) * 512 + ((h * HD_ + d) >> 1);
        float a0 = o[nt][0] * sc0, a1 = o[nt][1] * sc0;
        float b0 = o[nt][2] * sc1, b1 = o[nt][3] * sc1;
        g_AOh[wA] = packhi2(a0, a1); g_AOl[wA] = packlo2(a0, a1);
        g_AOh[wB] = packhi2(b0, b1); g_AOl[wB] = packlo2(b0, b1);
    }
}

// ---------------------------------------------------------------------------
typedef CUresult (*EncodeFn)(CUtensorMap*, CUtensorMapDataType, cuuint32_t, void*,
                             const cuuint64_t*, const cuuint64_t*, const cuuint32_t*,
                             const cuuint32_t*, CUtensorMapInterleave, CUtensorMapSwizzle,
                             CUtensorMapL2promotion, CUtensorMapFloatOOBfill);

static void make_map(EncodeFn enc, CUtensorMap* m, void* ptr,
                     unsigned long long rows, unsigned long long row_bytes,
                     unsigned box_w, unsigned box_h, CUtensorMapSwizzle sw) {
    cuuint64_t dims[2]    = {row_bytes, rows};
    cuuint64_t strides[1] = {row_bytes};
    cuuint32_t box[2]     = {box_w, box_h};
    cuuint32_t es[2]      = {1u, 1u};
    enc(m, CU_TENSOR_MAP_DATA_TYPE_UINT8, 2, ptr, dims, strides, box, es,
        CU_TENSOR_MAP_INTERLEAVE_NONE, sw,
        CU_TENSOR_MAP_L2_PROMOTION_L2_128B, CU_TENSOR_MAP_FLOAT_OOB_FILL_NONE);
}

extern "C" void kernel_launch(void* const* d_in, const int* in_sizes, int n_in,
                              void* d_out, int out_size)
{
    const float* x = nullptr, *Wqkv = nullptr, *bqkv = nullptr;
    const float* Wproj = nullptr, *bproj = nullptr, *fa = nullptr, *fg = nullptr;
    for (int i = 0; i < n_in; i++) {
        int sz = in_sizes[i];
        const float* p = (const float*)d_in[i];
        if      (sz == B_*NSEQ*DIM_)   x = p;
        else if (sz == 3*DIM_*DIM_)    Wqkv = p;
        else if (sz == 3*DIM_)         bqkv = p;
        else if (sz == DIM_*DIM_)      Wproj = p;
        else if (sz == DIM_)           bproj = p;
        else if (sz == 1)              { if (!fa) fa = p; else fg = p; }
    }
    float* out = (float*)d_out;

    cudaFuncSetAttribute(tc_gemm<0>,   cudaFuncAttributeMaxDynamicSharedMemorySize, GEMM_SMEM);
    cudaFuncSetAttribute(tc_gemm<1>,   cudaFuncAttributeMaxDynamicSharedMemorySize, GEMM_SMEM);
    cudaFuncSetAttribute(flash_kernel, cudaFuncAttributeMaxDynamicSharedMemorySize, FLASH_SMEM);

    EncodeFn enc = nullptr;
#if CUDART_VERSION >= 12000
    {
        cudaDriverEntryPointQueryResult qr;
        cudaGetDriverEntryPoint("cuTensorMapEncodeTiled", (void**)&enc,
                                cudaEnableDefault, &qr);
    }
#else
    cudaGetDriverEntryPoint("cuTensorMapEncodeTiled", (void**)&enc, cudaEnableDefault);
#endif

    void *p_xh, *p_xl, *p_Wqh, *p_Wql, *p_Wph, *p_Wpl, *p_AOh, *p_AOl;
    void *p_Qh, *p_Ql, *p_Kh, *p_Kl, *p_Vh, *p_Vl;
    cudaGetSymbolAddress(&p_xh,  g_xh);  cudaGetSymbolAddress(&p_xl,  g_xl);
    cudaGetSymbolAddress(&p_Wqh, g_Wqh); cudaGetSymbolAddress(&p_Wql, g_Wql);
    cudaGetSymbolAddress(&p_Wph, g_Wph); cudaGetSymbolAddress(&p_Wpl, g_Wpl);
    cudaGetSymbolAddress(&p_AOh, g_AOh); cudaGetSymbolAddress(&p_AOl, g_AOl);
    cudaGetSymbolAddress(&p_Qh,  g_Qh);  cudaGetSymbolAddress(&p_Ql,  g_Ql);
    cudaGetSymbolAddress(&p_Kh,  g_Kh);  cudaGetSymbolAddress(&p_Kl,  g_Kl);
    cudaGetSymbolAddress(&p_Vh,  g_Vh);  cudaGetSymbolAddress(&p_Vl,  g_Vl);

    const unsigned long long KVROWS = (unsigned long long)B_ * H_ * NSEQ;
    CUtensorMap m_xh, m_xl, m_Wqh, m_Wql, m_Wph, m_Wpl, m_AOh, m_AOl;
    CUtensorMap m_Qh, m_Ql, m_Kh, m_Kl, m_Vh, m_Vl;
    make_map(enc, &m_xh,  p_xh,  4096, 2048, 64, 128, CU_TENSOR_MAP_SWIZZLE_64B);
    make_map(enc, &m_xl,  p_xl,  4096, 2048, 64, 128, CU_TENSOR_MAP_SWIZZLE_64B);
    make_map(enc, &m_Wqh, p_Wqh, 3072, 2048, 64, 128, CU_TENSOR_MAP_SWIZZLE_64B);
    make_map(enc, &m_Wql, p_Wql, 3072, 2048, 64, 128, CU_TENSOR_MAP_SWIZZLE_64B);
    make_map(enc, &m_Wph, p_Wph, 1024, 2048, 64, 128, CU_TENSOR_MAP_SWIZZLE_64B);
    make_map(enc, &m_Wpl, p_Wpl, 1024, 2048, 64, 128, CU_TENSOR_MAP_SWIZZLE_64B);
    make_map(enc, &m_AOh, p_AOh, 4096, 2048, 64, 128, CU_TENSOR_MAP_SWIZZLE_64B);
    make_map(enc, &m_AOl, p_AOl, 4096, 2048, 64, 128, CU_TENSOR_MAP_SWIZZLE_64B);
    make_map(enc, &m_Qh,  p_Qh,  KVROWS, 128, 128, 128, CU_TENSOR_MAP_SWIZZLE_128B);
    make_map(enc, &m_Ql,  p_Ql,  KVROWS, 128, 128, 128, CU_TENSOR_MAP_SWIZZLE_128B);
    make_map(enc, &m_Kh,  p_Kh,  KVROWS, 128, 128, 64,  CU_TENSOR_MAP_SWIZZLE_128B);
    make_map(enc, &m_Kl,  p_Kl,  KVROWS, 128, 128, 64,  CU_TENSOR_MAP_SWIZZLE_128B);
    make_map(enc, &m_Vh,  p_Vh,  KVROWS, 128, 128, 64,  CU_TENSOR_MAP_SWIZZLE_128B);
    make_map(enc, &m_Vl,  p_Vl,  KVROWS, 128, 128, 64,  CU_TENSOR_MAP_SWIZZLE_128B);

    // 0) Fused split of all inputs into packed bf16 hi/lo
    split_kernel<<<8192, 256>>>((const float4*)x, (const float4*)Wqkv, (const float4*)Wproj);
    // 1) Fused QKV projection -> packed Q(scaled)/K/V
    tc_gemm<0><<<dim3(3*DIM_/128, (B_*NSEQ)/128), 256, GEMM_SMEM>>>(
        m_xh, m_xl, m_Wqh, m_Wql, bqkv, nullptr);
    // 2) Focal flash attention -> packed AO
    flash_kernel<<<dim3(NSEQ/128, B_*H_), 256, FLASH_SMEM>>>(
        m_Qh, m_Ql, m_Kh, m_Kl, m_Vh, m_Vl, fa, fg);
    // 3) Output projection -> d_out
    tc_gemm<1><<<dim3(DIM_/128, (B_*NSEQ)/128), 256, GEMM_SMEM>>>(
        m_AOh, m_AOl, m_Wph, m_Wpl, bproj, out);
}

// round 13
// speedup vs baseline: 1.2909x; 1.0246x over previous
#include <cuda_runtime.h>
#include <cuda.h>
#include <cstdint>

// Problem constants
#define B_    2
#define NSEQ  2048
#define DIM_  1024
#define H_    16
#define HD_   64
#define SCALE_F 0.125f   // HD^-0.5

// ---------------------------------------------------------------------------
// Packed split storage: uint32 = {bf16 elem k (low), bf16 elem k+1 (high)}.
// hi = top16 of fp32; lo = bf16(x - hi).  A*B ~= Ah*Bh + Ah*Bl + Al*Bh.
// ---------------------------------------------------------------------------
__device__ __align__(1024) uint32_t g_xh [4096*512], g_xl [4096*512];
__device__ __align__(1024) uint32_t g_Wqh[3072*512], g_Wql[3072*512];
__device__ __align__(1024) uint32_t g_Wph[1024*512], g_Wpl[1024*512];
#define QKV_W (B_*H_*NSEQ*32)
__device__ __align__(1024) uint32_t g_Qh[QKV_W], g_Ql[QKV_W];
__device__ __align__(1024) uint32_t g_Kh[QKV_W], g_Kl[QKV_W];
__device__ __align__(1024) uint32_t g_Vh[QKV_W], g_Vl[QKV_W];
__device__ __align__(1024) uint32_t g_AOh[4096*512], g_AOl[4096*512];

// ---------------------------------------------------------------------------
__device__ __forceinline__ uint32_t packhi2(float x, float y) {
    return __byte_perm(__float_as_uint(x), __float_as_uint(y), 0x7632);
}
__device__ __forceinline__ uint32_t packlo2(float x, float y) {
    float lx = x - __uint_as_float(__float_as_uint(x) & 0xffff0000u);
    float ly = y - __uint_as_float(__float_as_uint(y) & 0xffff0000u);
    return __byte_perm(__float_as_uint(lx), __float_as_uint(ly), 0x7632);
}
__device__ __forceinline__ uint32_t smem_u32(const void* p) {
    uint32_t a;
    asm("{ .reg .u64 t; cvta.to.shared.u64 t, %1; cvt.u32.u64 %0, t; }" : "=r"(a) : "l"(p));
    return a;
}
__device__ __forceinline__ void mma16(float* c, const uint32_t* a, const uint32_t* b) {
    asm("mma.sync.aligned.m16n8k16.row.col.f32.bf16.bf16.f32 "
        "{%0,%1,%2,%3}, {%4,%5,%6,%7}, {%8,%9}, {%0,%1,%2,%3};"
        : "+f"(c[0]), "+f"(c[1]), "+f"(c[2]), "+f"(c[3])
        : "r"(a[0]), "r"(a[1]), "r"(a[2]), "r"(a[3]), "r"(b[0]), "r"(b[1]));
}
__device__ __forceinline__ void ldmx4(uint32_t* r, uint32_t a) {
    asm volatile("ldmatrix.sync.aligned.m8n8.x4.shared.b16 {%0,%1,%2,%3}, [%4];"
        : "=r"(r[0]), "=r"(r[1]), "=r"(r[2]), "=r"(r[3]) : "r"(a));
}
__device__ __forceinline__ void ldmx4t(uint32_t* r, uint32_t a) {
    asm volatile("ldmatrix.sync.aligned.m8n8.x4.trans.shared.b16 {%0,%1,%2,%3}, [%4];"
        : "=r"(r[0]), "=r"(r[1]), "=r"(r[2]), "=r"(r[3]) : "r"(a));
}
// SW128 swizzle (word offsets), 128B rows (== CU_TENSOR_MAP_SWIZZLE_128B)
__device__ __forceinline__ int sw32(int r, int c) { return r * 32 + 4 * (c ^ (r & 7)); }
// SW64 swizzle (byte offsets), 64B tile rows
__device__ __forceinline__ int swt(int r, int c) { return r * 64 + 16 * (c ^ ((r >> 1) & 3)); }

// mbarrier helpers
#define MBAR_INIT(mb, c)  asm volatile("mbarrier.init.shared.b64 [%0], %1;" :: "r"(mb), "r"(c) : "memory")
#define MBAR_EXPECT_TX(mb, n) asm volatile("mbarrier.arrive.expect_tx.shared.b64 _, [%0], %1;" :: "r"(mb), "r"(n) : "memory")
#define MBAR_ARRIVE(mb)   asm volatile("mbarrier.arrive.shared.b64 _, [%0];" :: "r"(mb) : "memory")
__device__ __forceinline__ void mbar_wait(uint32_t mb, uint32_t ph) {
    asm volatile(
        "{ .reg .pred P1;\n"
        "WL_%=: mbarrier.try_wait.parity.acquire.cta.shared::cta.b64 P1, [%0], %1, 0x989680;\n"
        "@P1 bra.uni WD_%=;\n"
        "bra.uni WL_%=;\n"
        "WD_%=: }"
        :: "r"(mb), "r"(ph) : "memory");
}
__device__ __forceinline__ void tma2d(uint32_t smem, const CUtensorMap* m, int x, int y, uint32_t mb) {
    asm volatile("cp.async.bulk.tensor.2d.shared::cta.global.tile.mbarrier::complete_tx::bytes "
                 "[%0], [%1, {%2, %3}], [%4];"
                 :: "r"(smem), "l"(m), "r"(x), "r"(y), "r"(mb) : "memory");
}

// ---------------------------------------------------------------------------
// Fused prep: split all three fp32 inputs into packed hi/lo arrays.
// ---------------------------------------------------------------------------
__global__ __launch_bounds__(256)
void split_kernel(const float4* __restrict__ sx, const float4* __restrict__ swq,
                  const float4* __restrict__ swp)
{
    int bid = blockIdx.x;
    const float4* src; uint2 *h, *l; int base;
    if (bid < 4096)      { src = sx;  h = (uint2*)g_xh;  l = (uint2*)g_xl;  base = bid; }
    else if (bid < 7168) { src = swq; h = (uint2*)g_Wqh; l = (uint2*)g_Wql; base = bid - 4096; }
    else                 { src = swp; h = (uint2*)g_Wph; l = (uint2*)g_Wpl; base = bid - 7168; }
    int i = base * 256 + threadIdx.x;
    float4 v = src[i];
    h[i] = make_uint2(packhi2(v.x, v.y), packhi2(v.z, v.w));
    l[i] = make_uint2(packlo2(v.x, v.y), packlo2(v.z, v.w));
}

// ---------------------------------------------------------------------------
// Split-bf16 GEMM, TMA-fed, producer-consumer mbarriers (unchanged from R12).
// ---------------------------------------------------------------------------
#define STG_BYTES 32768
#define GEMM_SMEM (1024 + 3*STG_BYTES + 64)

template<int MODE>
__global__ __launch_bounds__(256, 2)
void tc_gemm(const __grid_constant__ CUtensorMap mAh,
             const __grid_constant__ CUtensorMap mAl,
             const __grid_constant__ CUtensorMap mBh,
             const __grid_constant__ CUtensorMap mBl,
             const float* __restrict__ bias, float* __restrict__ C)
{
    extern __shared__ __align__(16) uint32_t smu[];
    const uint32_t sbraw = smem_u32(smu);
    const uint32_t sb0 = (sbraw + 1023u) & ~1023u;
    const uint32_t mbF = sb0 + 3 * STG_BYTES;
    const uint32_t mbE = mbF + 24;

    const int tid = threadIdx.x, wid = tid >> 5, lane = tid & 31;
    const int g = lane >> 2, tg = lane & 3;
    const int wm = wid >> 2, wn = wid & 3;
    const int row0 = blockIdx.y * 128, col0 = blockIdx.x * 128;

    const int rA = wm * 64 + (lane & 15);
    const int selA = lane >> 4;
    const int rB = wn * 32 + (lane & 7) + ((lane >> 4) << 3);
    const int selB = (lane >> 3) & 1;

    if (tid == 0) {
#pragma unroll
        for (int s = 0; s < 3; s++) { MBAR_INIT(mbF + s * 8, 1); MBAR_INIT(mbE + s * 8, 8); }
    }
    __syncthreads();

    auto issue = [&](int ch, int st) {
        uint32_t base = sb0 + (uint32_t)st * STG_BYTES;
        uint32_t mb = mbF + st * 8;
        MBAR_EXPECT_TX(mb, STG_BYTES);
        tma2d(base,         &mAh, ch * 64, row0, mb);
        tma2d(base + 8192,  &mAl, ch * 64, row0, mb);
        tma2d(base + 16384, &mBh, ch * 64, col0, mb);
        tma2d(base + 24576, &mBl, ch * 64, col0, mb);
    };
    if (tid == 0) { issue(0, 0); issue(1, 1); issue(2, 2); }

    float c[4][4][4];
#pragma unroll
    for (int mt = 0; mt < 4; mt++)
#pragma unroll
        for (int nt = 0; nt < 4; nt++) {
            c[mt][nt][0] = 0.f; c[mt][nt][1] = 0.f; c[mt][nt][2] = 0.f; c[mt][nt][3] = 0.f;
        }

    for (int ch = 0; ch < 32; ch++) {
        const int st = ch % 3;
        mbar_wait(mbF + st * 8, (uint32_t)((ch / 3) & 1));
        const uint32_t base = sb0 + (uint32_t)st * STG_BYTES;

#pragma unroll
        for (int ks = 0; ks < 2; ks++) {
            const int cA = 2 * ks + selA;
            const int cB = 2 * ks + selB;
            uint32_t ah[4][4], al[4][4], th[2][4], tl[2][4];
#pragma unroll
            for (int mt = 0; mt < 4; mt++) {
                ldmx4(ah[mt], base + (uint32_t)swt(rA + mt * 16, cA));
                ldmx4(al[mt], base + 8192u + (uint32_t)swt(rA + mt * 16, cA));
            }
#pragma unroll
            for (int ntp = 0; ntp < 2; ntp++) {
                ldmx4(th[ntp], base + 16384u + (uint32_t)swt(rB + ntp * 16, cB));
                ldmx4(tl[ntp], base + 24576u + (uint32_t)swt(rB + ntp * 16, cB));
            }
#pragma unroll
            for (int ntp = 0; ntp < 2; ntp++)
#pragma unroll
                for (int mt = 0; mt < 4; mt++) {
                    mma16(c[mt][2*ntp],   ah[mt], &th[ntp][0]);
                    mma16(c[mt][2*ntp+1], ah[mt], &th[ntp][2]);
                }
#pragma unroll
            for (int ntp = 0; ntp < 2; ntp++)
#pragma unroll
                for (int mt = 0; mt < 4; mt++) {
                    mma16(c[mt][2*ntp],   ah[mt], &tl[ntp][0]);
                    mma16(c[mt][2*ntp+1], ah[mt], &tl[ntp][2]);
                }
#pragma unroll
            for (int ntp = 0; ntp < 2; ntp++)
#pragma unroll
                for (int mt = 0; mt < 4; mt++) {
                    mma16(c[mt][2*ntp],   al[mt], &th[ntp][0]);
                    mma16(c[mt][2*ntp+1], al[mt], &th[ntp][2]);
                }
        }
        if (lane == 0) MBAR_ARRIVE(mbE + st * 8);
        if (tid == 0 && ch + 3 < 32) {
            mbar_wait(mbE + st * 8, (uint32_t)((ch / 3) & 1));
            issue(ch + 3, st);
        }
    }

    // Epilogue
#pragma unroll
    for (int mt = 0; mt < 4; mt++) {
#pragma unroll
        for (int hf = 0; hf < 2; hf++) {
            int row = row0 + wm * 64 + mt * 16 + g + hf * 8;
#pragma unroll
            for (int nt = 0; nt < 4; nt++) {
                int col = col0 + wn * 32 + nt * 8 + 2 * tg;
                float v0 = c[mt][nt][hf * 2 + 0] + bias[col];
                float v1 = c[mt][nt][hf * 2 + 1] + bias[col + 1];
                if (MODE == 1) {
                    *(float2*)&C[(size_t)row * DIM_ + col] = make_float2(v0, v1);
                } else {
                    int b = row >> 11, n = row & (NSEQ - 1);
                    int which = col >> 10, rem = col & 1023;
                    int h = rem >> 6, d = rem & 63;
                    size_t w = (((size_t)(b * H_ + h)) * NSEQ + n) * 32 + (d >> 1);
                    if (which == 0) {
                        v0 *= SCALE_F; v1 *= SCALE_F;
                        g_Qh[w] = packhi2(v0, v1); g_Ql[w] = packlo2(v0, v1);
                    } else if (which == 1) {
                        g_Kh[w] = packhi2(v0, v1); g_Kl[w] = packlo2(v0, v1);
                    } else {
                        g_Vh[w] = packhi2(v0, v1); g_Vl[w] = packlo2(v0, v1);
                    }
                }
            }
        }
    }
}

// ---------------------------------------------------------------------------
// Flash focal attention, TMA-fed, NO ONLINE MAX (scores bounded -> exp/sums
// fit fp32; formula out = a*sum(e^2 v)/(a*sum(e^2) + 1e-6*(sum e)^2) is
// invariant to max subtraction, so m==0 is exact).
// ---------------------------------------------------------------------------
#define FQH 0
#define FQL 4096
#define FKV 8192
#define FKVB 8192
#define FSTG_BYTES 32768
#define FLASH_SMEM (98304 + 64)

__global__ __launch_bounds__(256, 2)
void flash_kernel(const __grid_constant__ CUtensorMap mQh,
                  const __grid_constant__ CUtensorMap mQl,
                  const __grid_constant__ CUtensorMap mKh,
                  const __grid_constant__ CUtensorMap mKl,
                  const __grid_constant__ CUtensorMap mVh,
                  const __grid_constant__ CUtensorMap mVl,
                  const float* __restrict__ falpha, const float* __restrict__ fgamma)
{
    extern __shared__ __align__(16) uint32_t smu[];
    const uint32_t sb = smem_u32(smu);
    const uint32_t mbQ = sb + 98304, mbF = sb + 98312, mbE = sb + 98328;
    const int tid = threadIdx.x, wid = tid >> 5, lane = tid & 31;
    const int g = lane >> 2, tg = lane & 3;
    const int bh = blockIdx.y, q0 = blockIdx.x * 128;
    const int qb = wid * 16;

    const float gam = fgamma[0], alpha = falpha[0];
    const bool g2 = (gam == 2.0f);

    const int r16 = lane & 15;
    const int sel = lane >> 4;
    const int rK  = (lane & 7) + ((lane >> 4) << 3);
    const int selB = (lane >> 3) & 1;

    if (tid == 0) {
        MBAR_INIT(mbQ, 1);
#pragma unroll
        for (int s = 0; s < 2; s++) { MBAR_INIT(mbF + s * 8, 1); MBAR_INIT(mbE + s * 8, 8); }
    }
    __syncthreads();

    auto issueKV = [&](int ch, int st) {
        uint32_t base = sb + 32768u + (uint32_t)st * FSTG_BYTES;
        uint32_t mb = mbF + st * 8;
        int y = bh * NSEQ + ch * 64;
        MBAR_EXPECT_TX(mb, FSTG_BYTES);
        tma2d(base,          &mKh, 0, y, mb);
        tma2d(base + 8192,   &mKl, 0, y, mb);
        tma2d(base + 16384,  &mVh, 0, y, mb);
        tma2d(base + 24576,  &mVl, 0, y, mb);
    };
    if (tid == 0) {
        MBAR_EXPECT_TX(mbQ, 32768);
        tma2d(sb,          &mQh, 0, bh * NSEQ + q0, mbQ);
        tma2d(sb + 16384,  &mQl, 0, bh * NSEQ + q0, mbQ);
        issueKV(0, 0);
        issueKV(1, 1);
    }
    mbar_wait(mbQ, 0);

    float o[8][4];
#pragma unroll
    for (int nt = 0; nt < 8; nt++) { o[nt][0] = o[nt][1] = o[nt][2] = o[nt][3] = 0.f; }
    float Z0 = 0.f, Z1 = 0.f, S20 = 0.f, S21 = 0.f;

    for (int ch = 0; ch < 32; ch++) {
        const int st = ch & 1;
        mbar_wait(mbF + st * 8, (uint32_t)((ch >> 1) & 1));
        const uint32_t kvb = FKV + (uint32_t)(st * FKVB);

        // ---- S = Q K^T ----
        float s[8][4];
#pragma unroll
        for (int nt = 0; nt < 8; nt++) { s[nt][0] = s[nt][1] = s[nt][2] = s[nt][3] = 0.f; }
#pragma unroll
        for (int ks = 0; ks < 4; ks++) {
            const int cA = 2 * ks + sel;
            const int cB = 2 * ks + selB;
            uint32_t qh[4], ql[4];
            ldmx4(qh, sb + 4u * (uint32_t)(FQH + sw32(qb + r16, cA)));
            ldmx4(ql, sb + 4u * (uint32_t)(FQL + sw32(qb + r16, cA)));
#pragma unroll
            for (int np = 0; np < 2; np++) {
                const int n0 = np * 2;
                uint32_t th0[4], th1[4], tl0[4], tl1[4];
                ldmx4(th0, sb + 4u * (uint32_t)(kvb + sw32(rK + n0 * 16, cB)));
                ldmx4(th1, sb + 4u * (uint32_t)(kvb + sw32(rK + (n0 + 1) * 16, cB)));
                ldmx4(tl0, sb + 4u * (uint32_t)(kvb + 2048 + sw32(rK + n0 * 16, cB)));
                ldmx4(tl1, sb + 4u * (uint32_t)(kvb + 2048 + sw32(rK + (n0 + 1) * 16, cB)));
                mma16(s[2*n0],   qh, &th0[0]); mma16(s[2*n0+1], qh, &th0[2]);
                mma16(s[2*n0+2], qh, &th1[0]); mma16(s[2*n0+3], qh, &th1[2]);
                mma16(s[2*n0],   qh, &tl0[0]); mma16(s[2*n0+1], qh, &tl0[2]);
                mma16(s[2*n0+2], qh, &tl1[0]); mma16(s[2*n0+3], qh, &tl1[2]);
                mma16(s[2*n0],   ql, &th0[0]); mma16(s[2*n0+1], ql, &th0[2]);
                mma16(s[2*n0+2], ql, &th1[0]); mma16(s[2*n0+3], ql, &th1[2]);
            }
        }

        // ---- weights directly (no max subtraction) -> register A-frags ----
        uint32_t ph[4][4], pl[4][4];
        float zp0 = 0.f, zp1 = 0.f, wp0 = 0.f, wp1 = 0.f;
#pragma unroll
        for (int nt = 0; nt < 8; nt++) {
            float e0 = __expf(s[nt][0]), e1 = __expf(s[nt][1]);
            float e2 = __expf(s[nt][2]), e3 = __expf(s[nt][3]);
            zp0 += e0 + e1; zp1 += e2 + e3;
            float w0, w1, w2, w3;
            if (g2) { w0 = e0 * e0; w1 = e1 * e1; w2 = e2 * e2; w3 = e3 * e3; }
            else {
                w0 = __expf(gam * s[nt][0]); w1 = __expf(gam * s[nt][1]);
                w2 = __expf(gam * s[nt][2]); w3 = __expf(gam * s[nt][3]);
            }
            wp0 += w0 + w1; wp1 += w2 + w3;
            const int ks = nt >> 1, off = (nt & 1) * 2;
            ph[ks][off]     = packhi2(w0, w1);
            ph[ks][off + 1] = packhi2(w2, w3);
            pl[ks][off]     = packlo2(w0, w1);
            pl[ks][off + 1] = packlo2(w2, w3);
        }
        Z0 += zp0; Z1 += zp1; S20 += wp0; S21 += wp1;

        // ---- O += P V (pure accumulation, no rescale) ----
#pragma unroll
        for (int ks = 0; ks < 4; ks++) {
            const int k0 = ks * 16;
#pragma unroll
            for (int dp2 = 0; dp2 < 2; dp2++) {
                const int d0 = dp2 * 2;
                uint32_t th0[4], th1[4], tl0[4], tl1[4];
                ldmx4t(th0, sb + 4u * (uint32_t)(kvb + 4096 + sw32(k0 + r16, d0 * 2 + sel)));
                ldmx4t(th1, sb + 4u * (uint32_t)(kvb + 4096 + sw32(k0 + r16, (d0 + 1) * 2 + sel)));
                ldmx4t(tl0, sb + 4u * (uint32_t)(kvb + 6144 + sw32(k0 + r16, d0 * 2 + sel)));
                ldmx4t(tl1, sb + 4u * (uint32_t)(kvb + 6144 + sw32(k0 + r16, (d0 + 1) * 2 + sel)));
                mma16(o[2*d0],   ph[ks], &th0[0]); mma16(o[2*d0+1], ph[ks], &th0[2]);
                mma16(o[2*d0+2], ph[ks], &th1[0]); mma16(o[2*d0+3], ph[ks], &th1[2]);
                mma16(o[2*d0],   ph[ks], &tl0[0]); mma16(o[2*d0+1], ph[ks], &tl0[2]);
                mma16(o[2*d0+2], ph[ks], &tl1[0]); mma16(o[2*d0+3], ph[ks], &tl1[2]);
                mma16(o[2*d0],   pl[ks], &th0[0]); mma16(o[2*d0+1], pl[ks], &th0[2]);
                mma16(o[2*d0+2], pl[ks], &th1[0]); mma16(o[2*d0+3], pl[ks], &th1[2]);
            }
        }

        if (lane == 0) MBAR_ARRIVE(mbE + st * 8);
        if (tid == 0 && ch + 2 < 32) {
            mbar_wait(mbE + st * 8, (uint32_t)((ch >> 1) & 1));
            issueKV(ch + 2, st);
        }
    }

    // ---- final reduce (quad) + packed split write of AO ----
    Z0  += __shfl_xor_sync(0xffffffffu, Z0, 1);  Z0  += __shfl_xor_sync(0xffffffffu, Z0, 2);
    Z1  += __shfl_xor_sync(0xffffffffu, Z1, 1);  Z1  += __shfl_xor_sync(0xffffffffu, Z1, 2);
    S20 += __shfl_xor_sync(0xffffffffu, S20, 1); S20 += __shfl_xor_sync(0xffffffffu, S20, 2);
    S21 += __shfl_xor_sync(0xffffffffu, S21, 1); S21 += __shfl_xor_sync(0xffffffffu, S21, 2);

    float Zg0 = g2 ? Z0 * Z0 : __powf(Z0, gam);
    float Zg1 = g2 ? Z1 * Z1 : __powf(Z1, gam);
    float sc0 = alpha / (alpha * S20 + 1e-6f * Zg0);
    float sc1 = alpha / (alpha * S21 + 1e-6f * Zg1);

    const int b = bh >> 4, h = bh & 15;
    const int qA = q0 + qb + g, qB = qA + 8;
#pragma unroll
    for (int nt = 0; nt < 8; nt++) {
        int d = nt * 8 + 2 * tg;
        size_t wA = ((size_t)b * NSEQ + qA) * 512 + ((h * HD_ + d) >> 1);
        size_t wB = ((size_t)b * NSEQ + qB) * 512 + ((h * HD_ + d) >> 1);
        float a0 = o[nt][0] * sc0, a1 = o[nt][1] * sc0;
        float b0 = o[nt][2] * sc1, b1 = o[nt][3] * sc1;
        g_AOh[wA] = packhi2(a0, a1); g_AOl[wA] = packlo2(a0, a1);
        g_AOh[wB] = packhi2(b0, b1); g_AOl[wB] = packlo2(b0, b1);
    }
}

// ---------------------------------------------------------------------------
typedef CUresult (*EncodeFn)(CUtensorMap*, CUtensorMapDataType, cuuint32_t, void*,
                             const cuuint64_t*, const cuuint64_t*, const cuuint32_t*,
                             const cuuint32_t*, CUtensorMapInterleave, CUtensorMapSwizzle,
                             CUtensorMapL2promotion, CUtensorMapFloatOOBfill);

static void make_map(EncodeFn enc, CUtensorMap* m, void* ptr,
                     unsigned long long rows, unsigned long long row_bytes,
                     unsigned box_w, unsigned box_h, CUtensorMapSwizzle sw) {
    cuuint64_t dims[2]    = {row_bytes, rows};
    cuuint64_t strides[1] = {row_bytes};
    cuuint32_t box[2]     = {box_w, box_h};
    cuuint32_t es[2]      = {1u, 1u};
    enc(m, CU_TENSOR_MAP_DATA_TYPE_UINT8, 2, ptr, dims, strides, box, es,
        CU_TENSOR_MAP_INTERLEAVE_NONE, sw,
        CU_TENSOR_MAP_L2_PROMOTION_L2_128B, CU_TENSOR_MAP_FLOAT_OOB_FILL_NONE);
}

extern "C" void kernel_launch(void* const* d_in, const int* in_sizes, int n_in,
                              void* d_out, int out_size)
{
    const float* x = nullptr, *Wqkv = nullptr, *bqkv = nullptr;
    const float* Wproj = nullptr, *bproj = nullptr, *fa = nullptr, *fg = nullptr;
    for (int i = 0; i < n_in; i++) {
        int sz = in_sizes[i];
        const float* p = (const float*)d_in[i];
        if      (sz == B_*NSEQ*DIM_)   x = p;
        else if (sz == 3*DIM_*DIM_)    Wqkv = p;
        else if (sz == 3*DIM_)         bqkv = p;
        else if (sz == DIM_*DIM_)      Wproj = p;
        else if (sz == DIM_)           bproj = p;
        else if (sz == 1)              { if (!fa) fa = p; else fg = p; }
    }
    float* out = (float*)d_out;

    cudaFuncSetAttribute(tc_gemm<0>,   cudaFuncAttributeMaxDynamicSharedMemorySize, GEMM_SMEM);
    cudaFuncSetAttribute(tc_gemm<1>,   cudaFuncAttributeMaxDynamicSharedMemorySize, GEMM_SMEM);
    cudaFuncSetAttribute(flash_kernel, cudaFuncAttributeMaxDynamicSharedMemorySize, FLASH_SMEM);

    EncodeFn enc = nullptr;
#if CUDART_VERSION >= 12000
    {
        cudaDriverEntryPointQueryResult qr;
        cudaGetDriverEntryPoint("cuTensorMapEncodeTiled", (void**)&enc,
                                cudaEnableDefault, &qr);
    }
#else
    cudaGetDriverEntryPoint("cuTensorMapEncodeTiled", (void**)&enc, cudaEnableDefault);
#endif

    void *p_xh, *p_xl, *p_Wqh, *p_Wql, *p_Wph, *p_Wpl, *p_AOh, *p_AOl;
    void *p_Qh, *p_Ql, *p_Kh, *p_Kl, *p_Vh, *p_Vl;
    cudaGetSymbolAddress(&p_xh,  g_xh);  cudaGetSymbolAddress(&p_xl,  g_xl);
    cudaGetSymbolAddress(&p_Wqh, g_Wqh); cudaGetSymbolAddress(&p_Wql, g_Wql);
    cudaGetSymbolAddress(&p_Wph, g_Wph); cudaGetSymbolAddress(&p_Wpl, g_Wpl);
    cudaGetSymbolAddress(&p_AOh, g_AOh); cudaGetSymbolAddress(&p_AOl, g_AOl);
    cudaGetSymbolAddress(&p_Qh,  g_Qh);  cudaGetSymbolAddress(&p_Ql,  g_Ql);
    cudaGetSymbolAddress(&p_Kh,  g_Kh);  cudaGetSymbolAddress(&p_Kl,  g_Kl);
    cudaGetSymbolAddress(&p_Vh,  g_Vh);  cudaGetSymbolAddress(&p_Vl,  g_Vl);

    const unsigned long long KVROWS = (unsigned long long)B_ * H_ * NSEQ;
    CUtensorMap m_xh, m_xl, m_Wqh, m_Wql, m_Wph, m_Wpl, m_AOh, m_AOl;
    CUtensorMap m_Qh, m_Ql, m_Kh, m_Kl, m_Vh, m_Vl;
    make_map(enc, &m_xh,  p_xh,  4096, 2048, 64, 128, CU_TENSOR_MAP_SWIZZLE_64B);
    make_map(enc, &m_xl,  p_xl,  4096, 2048, 64, 128, CU_TENSOR_MAP_SWIZZLE_64B);
    make_map(enc, &m_Wqh, p_Wqh, 3072, 2048, 64, 128, CU_TENSOR_MAP_SWIZZLE_64B);
    make_map(enc, &m_Wql, p_Wql, 3072, 2048, 64, 128, CU_TENSOR_MAP_SWIZZLE_64B);
    make_map(enc, &m_Wph, p_Wph, 1024, 2048, 64, 128, CU_TENSOR_MAP_SWIZZLE_64B);
    make_map(enc, &m_Wpl, p_Wpl, 1024, 2048, 64, 128, CU_TENSOR_MAP_SWIZZLE_64B);
    make_map(enc, &m_AOh, p_AOh, 4096, 2048, 64, 128, CU_TENSOR_MAP_SWIZZLE_64B);
    make_map(enc, &m_AOl, p_AOl, 4096, 2048, 64, 128, CU_TENSOR_MAP_SWIZZLE_64B);
    make_map(enc, &m_Qh,  p_Qh,  KVROWS, 128, 128, 128, CU_TENSOR_MAP_SWIZZLE_128B);
    make_map(enc, &m_Ql,  p_Ql,  KVROWS, 128, 128, 128, CU_TENSOR_MAP_SWIZZLE_128B);
    make_map(enc, &m_Kh,  p_Kh,  KVROWS, 128, 128, 64,  CU_TENSOR_MAP_SWIZZLE_128B);
    make_map(enc, &m_Kl,  p_Kl,  KVROWS, 128, 128, 64,  CU_TENSOR_MAP_SWIZZLE_128B);
    make_map(enc, &m_Vh,  p_Vh,  KVROWS, 128, 128, 64,  CU_TENSOR_MAP_SWIZZLE_128B);
    make_map(enc, &m_Vl,  p_Vl,  KVROWS, 128, 128, 64,  CU_TENSOR_MAP_SWIZZLE_128B);

    // 0) Fused split of all inputs into packed bf16 hi/lo
    split_kernel<<<8192, 256>>>((const float4*)x, (const float4*)Wqkv, (const float4*)Wproj);
    // 1) Fused QKV projection -> packed Q(scaled)/K/V
    tc_gemm<0><<<dim3(3*DIM_/128, (B_*NSEQ)/128), 256, GEMM_SMEM>>>(
        m_xh, m_xl, m_Wqh, m_Wql, bqkv, nullptr);
    // 2) Focal flash attention -> packed AO
    flash_kernel<<<dim3(NSEQ/128, B_*H_), 256, FLASH_SMEM>>>(
        m_Qh, m_Ql, m_Kh, m_Kl, m_Vh, m_Vl, fa, fg);
    // 3) Output projection -> d_out
    tc_gemm<1><<<dim3(DIM_/128, (B_*NSEQ)/128), 256, GEMM_SMEM>>>(
        m_AOh, m_AOl, m_Wph, m_Wpl, bproj, out);
}

// round 14
// speedup vs baseline: 1.6128x; 1.2494x over previous
#include <cuda_runtime.h>
#include <cuda.h>
#include <cuda_fp16.h>
#include <cstdint>

// Problem constants
#define B_    2
#define NSEQ  2048
#define DIM_  1024
#define H_    16
#define HD_   64
#define SCALE_F 0.125f   // HD^-0.5
#define PSCALE (1.0f/4096.0f)   // P prescale (2^-12), undone in epilogue

// ---------------------------------------------------------------------------
// gemm0 inputs: bf16 hi/lo 3-term (unchanged). Flash/gemm1 path: fp16.
// Packed word = {elem k (low 16), elem k+1 (high 16)}.
// ---------------------------------------------------------------------------
__device__ __align__(1024) uint32_t g_xh [4096*512], g_xl [4096*512];
__device__ __align__(1024) uint32_t g_Wqh[3072*512], g_Wql[3072*512];
__device__ __align__(1024) uint32_t g_Wph[1024*512], g_Wpl[1024*512];   // fp16
#define QKV_W (B_*H_*NSEQ*32)
__device__ __align__(1024) uint32_t g_Qh[QKV_W];                         // fp16 hi only
__device__ __align__(1024) uint32_t g_Kh[QKV_W], g_Kl[QKV_W];            // fp16
__device__ __align__(1024) uint32_t g_Vh[QKV_W], g_Vl[QKV_W];            // fp16
__device__ __align__(1024) uint32_t g_AOh[4096*512];                     // fp16 hi only

// ---------------------------------------------------------------------------
__device__ __forceinline__ uint32_t packhi2(float x, float y) {          // bf16 hi
    return __byte_perm(__float_as_uint(x), __float_as_uint(y), 0x7632);
}
__device__ __forceinline__ uint32_t packlo2(float x, float y) {          // bf16 lo
    float lx = x - __uint_as_float(__float_as_uint(x) & 0xffff0000u);
    float ly = y - __uint_as_float(__float_as_uint(y) & 0xffff0000u);
    return __byte_perm(__float_as_uint(lx), __float_as_uint(ly), 0x7632);
}
__device__ __forceinline__ uint32_t f16pack2(float x, float y) {
    __half2 h = __float22half2_rn(make_float2(x, y));
    return *(uint32_t*)&h;
}
__device__ __forceinline__ void f16split2(float x, float y, uint32_t& hi, uint32_t& lo) {
    __half2 h = __float22half2_rn(make_float2(x, y));
    float2 b = __half22float2(h);
    __half2 l = __float22half2_rn(make_float2(x - b.x, y - b.y));
    hi = *(uint32_t*)&h; lo = *(uint32_t*)&l;
}
__device__ __forceinline__ uint32_t smem_u32(const void* p) {
    uint32_t a;
    asm("{ .reg .u64 t; cvta.to.shared.u64 t, %1; cvt.u32.u64 %0, t; }" : "=r"(a) : "l"(p));
    return a;
}
__device__ __forceinline__ void mma16(float* c, const uint32_t* a, const uint32_t* b) {
    asm("mma.sync.aligned.m16n8k16.row.col.f32.bf16.bf16.f32 "
        "{%0,%1,%2,%3}, {%4,%5,%6,%7}, {%8,%9}, {%0,%1,%2,%3};"
        : "+f"(c[0]), "+f"(c[1]), "+f"(c[2]), "+f"(c[3])
        : "r"(a[0]), "r"(a[1]), "r"(a[2]), "r"(a[3]), "r"(b[0]), "r"(b[1]));
}
__device__ __forceinline__ void mma16f(float* c, const uint32_t* a, const uint32_t* b) {
    asm("mma.sync.aligned.m16n8k16.row.col.f32.f16.f16.f32 "
        "{%0,%1,%2,%3}, {%4,%5,%6,%7}, {%8,%9}, {%0,%1,%2,%3};"
        : "+f"(c[0]), "+f"(c[1]), "+f"(c[2]), "+f"(c[3])
        : "r"(a[0]), "r"(a[1]), "r"(a[2]), "r"(a[3]), "r"(b[0]), "r"(b[1]));
}
__device__ __forceinline__ void ldmx4(uint32_t* r, uint32_t a) {
    asm volatile("ldmatrix.sync.aligned.m8n8.x4.shared.b16 {%0,%1,%2,%3}, [%4];"
        : "=r"(r[0]), "=r"(r[1]), "=r"(r[2]), "=r"(r[3]) : "r"(a));
}
__device__ __forceinline__ void ldmx4t(uint32_t* r, uint32_t a) {
    asm volatile("ldmatrix.sync.aligned.m8n8.x4.trans.shared.b16 {%0,%1,%2,%3}, [%4];"
        : "=r"(r[0]), "=r"(r[1]), "=r"(r[2]), "=r"(r[3]) : "r"(a));
}
// SW128 swizzle (word offsets), 128B rows (== CU_TENSOR_MAP_SWIZZLE_128B)
__device__ __forceinline__ int sw32(int r, int c) { return r * 32 + 4 * (c ^ (r & 7)); }
// SW64 swizzle (byte offsets), 64B tile rows
__device__ __forceinline__ int swt(int r, int c) { return r * 64 + 16 * (c ^ ((r >> 1) & 3)); }

#define MBAR_INIT(mb, c)  asm volatile("mbarrier.init.shared.b64 [%0], %1;" :: "r"(mb), "r"(c) : "memory")
#define MBAR_EXPECT_TX(mb, n) asm volatile("mbarrier.arrive.expect_tx.shared.b64 _, [%0], %1;" :: "r"(mb), "r"(n) : "memory")
#define MBAR_ARRIVE(mb)   asm volatile("mbarrier.arrive.shared.b64 _, [%0];" :: "r"(mb) : "memory")
__device__ __forceinline__ void mbar_wait(uint32_t mb, uint32_t ph) {
    asm volatile(
        "{ .reg .pred P1;\n"
        "WL_%=: mbarrier.try_wait.parity.acquire.cta.shared::cta.b64 P1, [%0], %1, 0x989680;\n"
        "@P1 bra.uni WD_%=;\n"
        "bra.uni WL_%=;\n"
        "WD_%=: }"
        :: "r"(mb), "r"(ph) : "memory");
}
__device__ __forceinline__ void tma2d(uint32_t smem, const CUtensorMap* m, int x, int y, uint32_t mb) {
    asm volatile("cp.async.bulk.tensor.2d.shared::cta.global.tile.mbarrier::complete_tx::bytes "
                 "[%0], [%1, {%2, %3}], [%4];"
                 :: "r"(smem), "l"(m), "r"(x), "r"(y), "r"(mb) : "memory");
}

// ---------------------------------------------------------------------------
// Fused prep: x, Wqkv -> bf16 hi/lo; Wproj -> fp16 hi/lo.
// ---------------------------------------------------------------------------
__global__ __launch_bounds__(256)
void split_kernel(const float4* __restrict__ sx, const float4* __restrict__ swq,
                  const float4* __restrict__ swp)
{
    int bid = blockIdx.x;
    if (bid < 7168) {
        const float4* src; uint2 *h, *l; int base;
        if (bid < 4096) { src = sx;  h = (uint2*)g_xh;  l = (uint2*)g_xl;  base = bid; }
        else            { src = swq; h = (uint2*)g_Wqh; l = (uint2*)g_Wql; base = bid - 4096; }
        int i = base * 256 + threadIdx.x;
        float4 v = src[i];
        h[i] = make_uint2(packhi2(v.x, v.y), packhi2(v.z, v.w));
        l[i] = make_uint2(packlo2(v.x, v.y), packlo2(v.z, v.w));
    } else {
        int i = (bid - 7168) * 256 + threadIdx.x;
        float4 v = swp[i];
        uint32_t h0, l0, h1, l1;
        f16split2(v.x, v.y, h0, l0);
        f16split2(v.z, v.w, h1, l1);
        ((uint2*)g_Wph)[i] = make_uint2(h0, h1);
        ((uint2*)g_Wpl)[i] = make_uint2(l0, l1);
    }
}

// ---------------------------------------------------------------------------
// gemm0: bf16 3-term, TMA-fed, producer-consumer (mainloop unchanged from R12).
// Epilogue writes fp16 Q(hi, scaled) / K(hi,lo) / V(hi,lo).
// ---------------------------------------------------------------------------
#define STG_BYTES 32768
#define GEMM_SMEM (1024 + 3*STG_BYTES + 64)

__global__ __launch_bounds__(256, 2)
void tc_gemm0(const __grid_constant__ CUtensorMap mAh,
              const __grid_constant__ CUtensorMap mAl,
              const __grid_constant__ CUtensorMap mBh,
              const __grid_constant__ CUtensorMap mBl,
              const float* __restrict__ bias)
{
    extern __shared__ __align__(16) uint32_t smu[];
    const uint32_t sbraw = smem_u32(smu);
    const uint32_t sb0 = (sbraw + 1023u) & ~1023u;
    const uint32_t mbF = sb0 + 3 * STG_BYTES;
    const uint32_t mbE = mbF + 24;

    const int tid = threadIdx.x, wid = tid >> 5, lane = tid & 31;
    const int g = lane >> 2, tg = lane & 3;
    const int wm = wid >> 2, wn = wid & 3;
    const int row0 = blockIdx.y * 128, col0 = blockIdx.x * 128;

    const int rA = wm * 64 + (lane & 15);
    const int selA = lane >> 4;
    const int rB = wn * 32 + (lane & 7) + ((lane >> 4) << 3);
    const int selB = (lane >> 3) & 1;

    if (tid == 0) {
#pragma unroll
        for (int s = 0; s < 3; s++) { MBAR_INIT(mbF + s * 8, 1); MBAR_INIT(mbE + s * 8, 8); }
    }
    __syncthreads();

    auto issue = [&](int ch, int st) {
        uint32_t base = sb0 + (uint32_t)st * STG_BYTES;
        uint32_t mb = mbF + st * 8;
        MBAR_EXPECT_TX(mb, STG_BYTES);
        tma2d(base,         &mAh, ch * 64, row0, mb);
        tma2d(base + 8192,  &mAl, ch * 64, row0, mb);
        tma2d(base + 16384, &mBh, ch * 64, col0, mb);
        tma2d(base + 24576, &mBl, ch * 64, col0, mb);
    };
    if (tid == 0) { issue(0, 0); issue(1, 1); issue(2, 2); }

    float c[4][4][4];
#pragma unroll
    for (int mt = 0; mt < 4; mt++)
#pragma unroll
        for (int nt = 0; nt < 4; nt++) {
            c[mt][nt][0] = 0.f; c[mt][nt][1] = 0.f; c[mt][nt][2] = 0.f; c[mt][nt][3] = 0.f;
        }

    for (int ch = 0; ch < 32; ch++) {
        const int st = ch % 3;
        mbar_wait(mbF + st * 8, (uint32_t)((ch / 3) & 1));
        const uint32_t base = sb0 + (uint32_t)st * STG_BYTES;

#pragma unroll
        for (int ks = 0; ks < 2; ks++) {
            const int cA = 2 * ks + selA;
            const int cB = 2 * ks + selB;
            uint32_t ah[4][4], al[4][4], th[2][4], tl[2][4];
#pragma unroll
            for (int mt = 0; mt < 4; mt++) {
                ldmx4(ah[mt], base + (uint32_t)swt(rA + mt * 16, cA));
                ldmx4(al[mt], base + 8192u + (uint32_t)swt(rA + mt * 16, cA));
            }
#pragma unroll
            for (int ntp = 0; ntp < 2; ntp++) {
                ldmx4(th[ntp], base + 16384u + (uint32_t)swt(rB + ntp * 16, cB));
                ldmx4(tl[ntp], base + 24576u + (uint32_t)swt(rB + ntp * 16, cB));
            }
#pragma unroll
            for (int ntp = 0; ntp < 2; ntp++)
#pragma unroll
                for (int mt = 0; mt < 4; mt++) {
                    mma16(c[mt][2*ntp],   ah[mt], &th[ntp][0]);
                    mma16(c[mt][2*ntp+1], ah[mt], &th[ntp][2]);
                }
#pragma unroll
            for (int ntp = 0; ntp < 2; ntp++)
#pragma unroll
                for (int mt = 0; mt < 4; mt++) {
                    mma16(c[mt][2*ntp],   ah[mt], &tl[ntp][0]);
                    mma16(c[mt][2*ntp+1], ah[mt], &tl[ntp][2]);
                }
#pragma unroll
            for (int ntp = 0; ntp < 2; ntp++)
#pragma unroll
                for (int mt = 0; mt < 4; mt++) {
                    mma16(c[mt][2*ntp],   al[mt], &th[ntp][0]);
                    mma16(c[mt][2*ntp+1], al[mt], &th[ntp][2]);
                }
        }
        if (lane == 0) MBAR_ARRIVE(mbE + st * 8);
        if (tid == 0 && ch + 3 < 32) {
            mbar_wait(mbE + st * 8, (uint32_t)((ch / 3) & 1));
            issue(ch + 3, st);
        }
    }

    // Epilogue: fp16 packed QKV
#pragma unroll
    for (int mt = 0; mt < 4; mt++) {
#pragma unroll
        for (int hf = 0; hf < 2; hf++) {
            int row = row0 + wm * 64 + mt * 16 + g + hf * 8;
#pragma unroll
            for (int nt = 0; nt < 4; nt++) {
                int col = col0 + wn * 32 + nt * 8 + 2 * tg;
                float v0 = c[mt][nt][hf * 2 + 0] + bias[col];
                float v1 = c[mt][nt][hf * 2 + 1] + bias[col + 1];
                int b = row >> 11, n = row & (NSEQ - 1);
                int which = col >> 10, rem = col & 1023;
                int h = rem >> 6, d = rem & 63;
                size_t w = (((size_t)(b * H_ + h)) * NSEQ + n) * 32 + (d >> 1);
                if (which == 0) {
                    g_Qh[w] = f16pack2(v0 * SCALE_F, v1 * SCALE_F);
                } else if (which == 1) {
                    f16split2(v0, v1, g_Kh[w], g_Kl[w]);
                } else {
                    f16split2(v0, v1, g_Vh[w], g_Vl[w]);
                }
            }
        }
    }
}

// ---------------------------------------------------------------------------
// gemm1: fp16 2-term (C = Ah*(Bh+Bl)), TMA-fed, producer-consumer.
// Stage = Ah(8KB) + Bh(8KB) + Bl(8KB) = 24KB. 3 stages.
// ---------------------------------------------------------------------------
#define STG1_BYTES 24576
#define GEMM1_SMEM (1024 + 3*STG1_BYTES + 64)

__global__ __launch_bounds__(256, 2)
void tc_gemm1(const __grid_constant__ CUtensorMap mAh,
              const __grid_constant__ CUtensorMap mBh,
              const __grid_constant__ CUtensorMap mBl,
              const float* __restrict__ bias, float* __restrict__ C)
{
    extern __shared__ __align__(16) uint32_t smu[];
    const uint32_t sbraw = smem_u32(smu);
    const uint32_t sb0 = (sbraw + 1023u) & ~1023u;
    const uint32_t mbF = sb0 + 3 * STG1_BYTES;
    const uint32_t mbE = mbF + 24;

    const int tid = threadIdx.x, wid = tid >> 5, lane = tid & 31;
    const int g = lane >> 2, tg = lane & 3;
    const int wm = wid >> 2, wn = wid & 3;
    const int row0 = blockIdx.y * 128, col0 = blockIdx.x * 128;

    const int rA = wm * 64 + (lane & 15);
    const int selA = lane >> 4;
    const int rB = wn * 32 + (lane & 7) + ((lane >> 4) << 3);
    const int selB = (lane >> 3) & 1;

    if (tid == 0) {
#pragma unroll
        for (int s = 0; s < 3; s++) { MBAR_INIT(mbF + s * 8, 1); MBAR_INIT(mbE + s * 8, 8); }
    }
    __syncthreads();

    auto issue = [&](int ch, int st) {
        uint32_t base = sb0 + (uint32_t)st * STG1_BYTES;
        uint32_t mb = mbF + st * 8;
        MBAR_EXPECT_TX(mb, STG1_BYTES);
        tma2d(base,         &mAh, ch * 64, row0, mb);
        tma2d(base + 8192,  &mBh, ch * 64, col0, mb);
        tma2d(base + 16384, &mBl, ch * 64, col0, mb);
    };
    if (tid == 0) { issue(0, 0); issue(1, 1); issue(2, 2); }

    float c[4][4][4];
#pragma unroll
    for (int mt = 0; mt < 4; mt++)
#pragma unroll
        for (int nt = 0; nt < 4; nt++) {
            c[mt][nt][0] = 0.f; c[mt][nt][1] = 0.f; c[mt][nt][2] = 0.f; c[mt][nt][3] = 0.f;
        }

    for (int ch = 0; ch < 32; ch++) {
        const int st = ch % 3;
        mbar_wait(mbF + st * 8, (uint32_t)((ch / 3) & 1));
        const uint32_t base = sb0 + (uint32_t)st * STG1_BYTES;

#pragma unroll
        for (int ks = 0; ks < 2; ks++) {
            const int cA = 2 * ks + selA;
            const int cB = 2 * ks + selB;
            uint32_t ah[4][4], th[2][4], tl[2][4];
#pragma unroll
            for (int mt = 0; mt < 4; mt++)
                ldmx4(ah[mt], base + (uint32_t)swt(rA + mt * 16, cA));
#pragma unroll
            for (int ntp = 0; ntp < 2; ntp++) {
                ldmx4(th[ntp], base + 8192u  + (uint32_t)swt(rB + ntp * 16, cB));
                ldmx4(tl[ntp], base + 16384u + (uint32_t)swt(rB + ntp * 16, cB));
            }
#pragma unroll
            for (int ntp = 0; ntp < 2; ntp++)
#pragma unroll
                for (int mt = 0; mt < 4; mt++) {
                    mma16f(c[mt][2*ntp],   ah[mt], &th[ntp][0]);
                    mma16f(c[mt][2*ntp+1], ah[mt], &th[ntp][2]);
                }
#pragma unroll
            for (int ntp = 0; ntp < 2; ntp++)
#pragma unroll
                for (int mt = 0; mt < 4; mt++) {
                    mma16f(c[mt][2*ntp],   ah[mt], &tl[ntp][0]);
                    mma16f(c[mt][2*ntp+1], ah[mt], &tl[ntp][2]);
                }
        }
        if (lane == 0) MBAR_ARRIVE(mbE + st * 8);
        if (tid == 0 && ch + 3 < 32) {
            mbar_wait(mbE + st * 8, (uint32_t)((ch / 3) & 1));
            issue(ch + 3, st);
        }
    }

#pragma unroll
    for (int mt = 0; mt < 4; mt++) {
#pragma unroll
        for (int hf = 0; hf < 2; hf++) {
            int row = row0 + wm * 64 + mt * 16 + g + hf * 8;
#pragma unroll
            for (int nt = 0; nt < 4; nt++) {
                int col = col0 + wn * 32 + nt * 8 + 2 * tg;
                float v0 = c[mt][nt][hf * 2 + 0] + bias[col];
                float v1 = c[mt][nt][hf * 2 + 1] + bias[col + 1];
                *(float2*)&C[(size_t)row * DIM_ + col] = make_float2(v0, v1);
            }
        }
    }
}

// ---------------------------------------------------------------------------
// Flash focal attention: fp16, QK 2-term (Qh only), PV 2-term (P hi with
// 2^-12 prescale; V hi+lo), no online max (exact; scores bounded).
// Smem words: QH [0,4096); KV stages at 4096 + st*8192
//   (KH+0, KL+2048, VH+4096, VL+6144). Barriers at byte 81920.
// ---------------------------------------------------------------------------
#define FQH 0
#define FKV 4096
#define FKVB 8192
#define FSTG_BYTES 32768
#define FLASH_SMEM (81920 + 64)

__global__ __launch_bounds__(256, 2)
void flash_kernel(const __grid_constant__ CUtensorMap mQh,
                  const __grid_constant__ CUtensorMap mKh,
                  const __grid_constant__ CUtensorMap mKl,
                  const __grid_constant__ CUtensorMap mVh,
                  const __grid_constant__ CUtensorMap mVl,
                  const float* __restrict__ falpha, const float* __restrict__ fgamma)
{
    extern __shared__ __align__(16) uint32_t smu[];
    const uint32_t sb = smem_u32(smu);
    const uint32_t mbQ = sb + 81920, mbF = sb + 81928, mbE = sb + 81944;
    const int tid = threadIdx.x, wid = tid >> 5, lane = tid & 31;
    const int g = lane >> 2, tg = lane & 3;
    const int bh = blockIdx.y, q0 = blockIdx.x * 128;
    const int qb = wid * 16;

    const float gam = fgamma[0], alpha = falpha[0];
    const bool g2 = (gam == 2.0f);

    const int r16 = lane & 15;
    const int sel = lane >> 4;
    const int rK  = (lane & 7) + ((lane >> 4) << 3);
    const int selB = (lane >> 3) & 1;

    if (tid == 0) {
        MBAR_INIT(mbQ, 1);
#pragma unroll
        for (int s = 0; s < 2; s++) { MBAR_INIT(mbF + s * 8, 1); MBAR_INIT(mbE + s * 8, 8); }
    }
    __syncthreads();

    auto issueKV = [&](int ch, int st) {
        uint32_t base = sb + 16384u + (uint32_t)st * FSTG_BYTES;
        uint32_t mb = mbF + st * 8;
        int y = bh * NSEQ + ch * 64;
        MBAR_EXPECT_TX(mb, FSTG_BYTES);
        tma2d(base,          &mKh, 0, y, mb);
        tma2d(base + 8192,   &mKl, 0, y, mb);
        tma2d(base + 16384,  &mVh, 0, y, mb);
        tma2d(base + 24576,  &mVl, 0, y, mb);
    };
    if (tid == 0) {
        MBAR_EXPECT_TX(mbQ, 16384);
        tma2d(sb, &mQh, 0, bh * NSEQ + q0, mbQ);
        issueKV(0, 0);
        issueKV(1, 1);
    }
    mbar_wait(mbQ, 0);

    float o[8][4];
#pragma unroll
    for (int nt = 0; nt < 8; nt++) { o[nt][0] = o[nt][1] = o[nt][2] = o[nt][3] = 0.f; }
    float Z0 = 0.f, Z1 = 0.f, S20 = 0.f, S21 = 0.f;

    for (int ch = 0; ch < 32; ch++) {
        const int st = ch & 1;
        mbar_wait(mbF + st * 8, (uint32_t)((ch >> 1) & 1));
        const uint32_t kvb = FKV + (uint32_t)(st * FKVB);

        // ---- S = Qh (Kh + Kl) ----
        float s[8][4];
#pragma unroll
        for (int nt = 0; nt < 8; nt++) { s[nt][0] = s[nt][1] = s[nt][2] = s[nt][3] = 0.f; }
#pragma unroll
        for (int ks = 0; ks < 4; ks++) {
            const int cA = 2 * ks + sel;
            const int cB = 2 * ks + selB;
            uint32_t qh[4];
            ldmx4(qh, sb + 4u * (uint32_t)(FQH + sw32(qb + r16, cA)));
#pragma unroll
            for (int np = 0; np < 2; np++) {
                const int n0 = np * 2;
                uint32_t th0[4], th1[4], tl0[4], tl1[4];
                ldmx4(th0, sb + 4u * (uint32_t)(kvb + sw32(rK + n0 * 16, cB)));
                ldmx4(th1, sb + 4u * (uint32_t)(kvb + sw32(rK + (n0 + 1) * 16, cB)));
                ldmx4(tl0, sb + 4u * (uint32_t)(kvb + 2048 + sw32(rK + n0 * 16, cB)));
                ldmx4(tl1, sb + 4u * (uint32_t)(kvb + 2048 + sw32(rK + (n0 + 1) * 16, cB)));
                mma16f(s[2*n0],   qh, &th0[0]); mma16f(s[2*n0+1], qh, &th0[2]);
                mma16f(s[2*n0+2], qh, &th1[0]); mma16f(s[2*n0+3], qh, &th1[2]);
                mma16f(s[2*n0],   qh, &tl0[0]); mma16f(s[2*n0+1], qh, &tl0[2]);
                mma16f(s[2*n0+2], qh, &tl1[0]); mma16f(s[2*n0+3], qh, &tl1[2]);
            }
        }

        // ---- weights (no max subtraction; P prescaled by 2^-12) ----
        uint32_t ph[4][4];
        float zp0 = 0.f, zp1 = 0.f, wp0 = 0.f, wp1 = 0.f;
#pragma unroll
        for (int nt = 0; nt < 8; nt++) {
            float e0 = __expf(s[nt][0]), e1 = __expf(s[nt][1]);
            float e2 = __expf(s[nt][2]), e3 = __expf(s[nt][3]);
            zp0 += e0 + e1; zp1 += e2 + e3;
            float w0, w1, w2, w3;
            if (g2) { w0 = e0 * e0; w1 = e1 * e1; w2 = e2 * e2; w3 = e3 * e3; }
            else {
                w0 = __expf(gam * s[nt][0]); w1 = __expf(gam * s[nt][1]);
                w2 = __expf(gam * s[nt][2]); w3 = __expf(gam * s[nt][3]);
            }
            wp0 += w0 + w1; wp1 += w2 + w3;
            const int ks = nt >> 1, off = (nt & 1) * 2;
            ph[ks][off]     = f16pack2(w0 * PSCALE, w1 * PSCALE);
            ph[ks][off + 1] = f16pack2(w2 * PSCALE, w3 * PSCALE);
        }
        Z0 += zp0; Z1 += zp1; S20 += wp0; S21 += wp1;

        // ---- O += Ph (Vh + Vl) ----
#pragma unroll
        for (int ks = 0; ks < 4; ks++) {
            const int k0 = ks * 16;
#pragma unroll
            for (int dp2 = 0; dp2 < 2; dp2++) {
                const int d0 = dp2 * 2;
                uint32_t th0[4], th1[4], tl0[4], tl1[4];
                ldmx4t(th0, sb + 4u * (uint32_t)(kvb + 4096 + sw32(k0 + r16, d0 * 2 + sel)));
                ldmx4t(th1, sb + 4u * (uint32_t)(kvb + 4096 + sw32(k0 + r16, (d0 + 1) * 2 + sel)));
                ldmx4t(tl0, sb + 4u * (uint32_t)(kvb + 6144 + sw32(k0 + r16, d0 * 2 + sel)));
                ldmx4t(tl1, sb + 4u * (uint32_t)(kvb + 6144 + sw32(k0 + r16, (d0 + 1) * 2 + sel)));
                mma16f(o[2*d0],   ph[ks], &th0[0]); mma16f(o[2*d0+1], ph[ks], &th0[2]);
                mma16f(o[2*d0+2], ph[ks], &th1[0]); mma16f(o[2*d0+3], ph[ks], &th1[2]);
                mma16f(o[2*d0],   ph[ks], &tl0[0]); mma16f(o[2*d0+1], ph[ks], &tl0[2]);
                mma16f(o[2*d0+2], ph[ks], &tl1[0]); mma16f(o[2*d0+3], ph[ks], &tl1[2]);
            }
        }

        if (lane == 0) MBAR_ARRIVE(mbE + st * 8);
        if (tid == 0 && ch + 2 < 32) {
            mbar_wait(mbE + st * 8, (uint32_t)((ch >> 1) & 1));
            issueKV(ch + 2, st);
        }
    }

    // ---- final reduce + fp16 AO write (undo 2^-12 prescale via sc) ----
    Z0  += __shfl_xor_sync(0xffffffffu, Z0, 1);  Z0  += __shfl_xor_sync(0xffffffffu, Z0, 2);
    Z1  += __shfl_xor_sync(0xffffffffu, Z1, 1);  Z1  += __shfl_xor_sync(0xffffffffu, Z1, 2);
    S20 += __shfl_xor_sync(0xffffffffu, S20, 1); S20 += __shfl_xor_sync(0xffffffffu, S20, 2);
    S21 += __shfl_xor_sync(0xffffffffu, S21, 1); S21 += __shfl_xor_sync(0xffffffffu, S21, 2);

    float Zg0 = g2 ? Z0 * Z0 : __powf(Z0, gam);
    float Zg1 = g2 ? Z1 * Z1 : __powf(Z1, gam);
    float sc0 = alpha * 4096.0f / (alpha * S20 + 1e-6f * Zg0);
    float sc1 = alpha * 4096.0f / (alpha * S21 + 1e-6f * Zg1);

    const int b = bh >> 4, h = bh & 15;
    const int qA = q0 + qb + g, qB = qA + 8;
#pragma unroll
    for (int nt = 0; nt < 8; nt++) {
        int d = nt * 8 + 2 * tg;
        size_t wA = ((size_t)b * NSEQ + qA) * 512 + ((h * HD_ + d) >> 1);
        size_t wB = ((size_t)b * NSEQ + qB) * 512 + ((h * HD_ + d) >> 1);
        g_AOh[wA] = f16pack2(o[nt][0] * sc0, o[nt][1] * sc0);
        g_AOh[wB] = f16pack2(o[nt][2] * sc1, o[nt][3] * sc1);
    }
}

// ---------------------------------------------------------------------------
typedef CUresult (*EncodeFn)(CUtensorMap*, CUtensorMapDataType, cuuint32_t, void*,
                             const cuuint64_t*, const cuuint64_t*, const cuuint32_t*,
                             const cuuint32_t*, CUtensorMapInterleave, CUtensorMapSwizzle,
                             CUtensorMapL2promotion, CUtensorMapFloatOOBfill);

static void make_map(EncodeFn enc, CUtensorMap* m, void* ptr,
                     unsigned long long rows, unsigned long long row_bytes,
                     unsigned box_w, unsigned box_h, CUtensorMapSwizzle sw) {
    cuuint64_t dims[2]    = {row_bytes, rows};
    cuuint64_t strides[1] = {row_bytes};
    cuuint32_t box[2]     = {box_w, box_h};
    cuuint32_t es[2]      = {1u, 1u};
    enc(m, CU_TENSOR_MAP_DATA_TYPE_UINT8, 2, ptr, dims, strides, box, es,
        CU_TENSOR_MAP_INTERLEAVE_NONE, sw,
        CU_TENSOR_MAP_L2_PROMOTION_L2_128B, CU_TENSOR_MAP_FLOAT_OOB_FILL_NONE);
}

extern "C" void kernel_launch(void* const* d_in, const int* in_sizes, int n_in,
                              void* d_out, int out_size)
{
    const float* x = nullptr, *Wqkv = nullptr, *bqkv = nullptr;
    const float* Wproj = nullptr, *bproj = nullptr, *fa = nullptr, *fg = nullptr;
    for (int i = 0; i < n_in; i++) {
        int sz = in_sizes[i];
        const float* p = (const float*)d_in[i];
        if      (sz == B_*NSEQ*DIM_)   x = p;
        else if (sz == 3*DIM_*DIM_)    Wqkv = p;
        else if (sz == 3*DIM_)         bqkv = p;
        else if (sz == DIM_*DIM_)      Wproj = p;
        else if (sz == DIM_)           bproj = p;
        else if (sz == 1)              { if (!fa) fa = p; else fg = p; }
    }
    float* out = (float*)d_out;

    cudaFuncSetAttribute(tc_gemm0,     cudaFuncAttributeMaxDynamicSharedMemorySize, GEMM_SMEM);
    cudaFuncSetAttribute(tc_gemm1,     cudaFuncAttributeMaxDynamicSharedMemorySize, GEMM1_SMEM);
    cudaFuncSetAttribute(flash_kernel, cudaFuncAttributeMaxDynamicSharedMemorySize, FLASH_SMEM);

    EncodeFn enc = nullptr;
#if CUDART_VERSION >= 12000
    {
        cudaDriverEntryPointQueryResult qr;
        cudaGetDriverEntryPoint("cuTensorMapEncodeTiled", (void**)&enc,
                                cudaEnableDefault, &qr);
    }
#else
    cudaGetDriverEntryPoint("cuTensorMapEncodeTiled", (void**)&enc, cudaEnableDefault);
#endif

    void *p_xh, *p_xl, *p_Wqh, *p_Wql, *p_Wph, *p_Wpl, *p_AOh;
    void *p_Qh, *p_Kh, *p_Kl, *p_Vh, *p_Vl;
    cudaGetSymbolAddress(&p_xh,  g_xh);  cudaGetSymbolAddress(&p_xl,  g_xl);
    cudaGetSymbolAddress(&p_Wqh, g_Wqh); cudaGetSymbolAddress(&p_Wql, g_Wql);
    cudaGetSymbolAddress(&p_Wph, g_Wph); cudaGetSymbolAddress(&p_Wpl, g_Wpl);
    cudaGetSymbolAddress(&p_AOh, g_AOh);
    cudaGetSymbolAddress(&p_Qh,  g_Qh);
    cudaGetSymbolAddress(&p_Kh,  g_Kh);  cudaGetSymbolAddress(&p_Kl,  g_Kl);
    cudaGetSymbolAddress(&p_Vh,  g_Vh);  cudaGetSymbolAddress(&p_Vl,  g_Vl);

    const unsigned long long KVROWS = (unsigned long long)B_ * H_ * NSEQ;
    CUtensorMap m_xh, m_xl, m_Wqh, m_Wql, m_Wph, m_Wpl, m_AOh;
    CUtensorMap m_Qh, m_Kh, m_Kl, m_Vh, m_Vl;
    make_map(enc, &m_xh,  p_xh,  4096, 2048, 64, 128, CU_TENSOR_MAP_SWIZZLE_64B);
    make_map(enc, &m_xl,  p_xl,  4096, 2048, 64, 128, CU_TENSOR_MAP_SWIZZLE_64B);
    make_map(enc, &m_Wqh, p_Wqh, 3072, 2048, 64, 128, CU_TENSOR_MAP_SWIZZLE_64B);
    make_map(enc, &m_Wql, p_Wql, 3072, 2048, 64, 128, CU_TENSOR_MAP_SWIZZLE_64B);
    make_map(enc, &m_Wph, p_Wph, 1024, 2048, 64, 128, CU_TENSOR_MAP_SWIZZLE_64B);
    make_map(enc, &m_Wpl, p_Wpl, 1024, 2048, 64, 128, CU_TENSOR_MAP_SWIZZLE_64B);
    make_map(enc, &m_AOh, p_AOh, 4096, 2048, 64, 128, CU_TENSOR_MAP_SWIZZLE_64B);
    make_map(enc, &m_Qh,  p_Qh,  KVROWS, 128, 128, 128, CU_TENSOR_MAP_SWIZZLE_128B);
    make_map(enc, &m_Kh,  p_Kh,  KVROWS, 128, 128, 64,  CU_TENSOR_MAP_SWIZZLE_128B);
    make_map(enc, &m_Kl,  p_Kl,  KVROWS, 128, 128, 64,  CU_TENSOR_MAP_SWIZZLE_128B);
    make_map(enc, &m_Vh,  p_Vh,  KVROWS, 128, 128, 64,  CU_TENSOR_MAP_SWIZZLE_128B);
    make_map(enc, &m_Vl,  p_Vl,  KVROWS, 128, 128, 64,  CU_TENSOR_MAP_SWIZZLE_128B);

    // 0) Fused split (x/Wqkv bf16, Wproj fp16)
    split_kernel<<<8192, 256>>>((const float4*)x, (const float4*)Wqkv, (const float4*)Wproj);
    // 1) QKV projection (bf16 3-term) -> fp16 Q(hi,scaled)/K/V
    tc_gemm0<<<dim3(3*DIM_/128, (B_*NSEQ)/128), 256, GEMM_SMEM>>>(
        m_xh, m_xl, m_Wqh, m_Wql, bqkv);
    // 2) Focal flash attention (fp16 2-term) -> fp16 AO
    flash_kernel<<<dim3(NSEQ/128, B_*H_), 256, FLASH_SMEM>>>(
        m_Qh, m_Kh, m_Kl, m_Vh, m_Vl, fa, fg);
    // 3) Output projection (fp16 2-term) -> d_out
    tc_gemm1<<<dim3(DIM_/128, (B_*NSEQ)/128), 256, GEMM1_SMEM>>>(
        m_AOh, m_Wph, m_Wpl, bproj, out);
}

// round 15
// speedup vs baseline: 1.8546x; 1.1499x over previous
#include <cuda_runtime.h>
#include <cuda.h>
#include <cuda_fp16.h>
#include <cstdint>

// Problem constants
#define B_    2
#define NSEQ  2048
#define DIM_  1024
#define H_    16
#define HD_   64
#define SCALE_F 0.125f   // HD^-0.5
#define PSCALE (1.0f/4096.0f)   // P prescale (2^-12), undone in epilogue

// ---------------------------------------------------------------------------
// Everything fp16 now. Packed word = {elem k (low 16), elem k+1 (high 16)}.
// 2-term scheme: C ~= Ah*(Bh+Bl); A stored hi-only.
// ---------------------------------------------------------------------------
__device__ __align__(1024) uint32_t g_xh [4096*512];                     // fp16 hi
__device__ __align__(1024) uint32_t g_Wqh[3072*512], g_Wql[3072*512];    // fp16 hi/lo
__device__ __align__(1024) uint32_t g_Wph[1024*512], g_Wpl[1024*512];    // fp16 hi/lo
#define QKV_W (B_*H_*NSEQ*32)
__device__ __align__(1024) uint32_t g_Qh[QKV_W];                         // fp16 hi
__device__ __align__(1024) uint32_t g_Kh[QKV_W], g_Kl[QKV_W];            // fp16 hi/lo
__device__ __align__(1024) uint32_t g_Vh[QKV_W], g_Vl[QKV_W];            // fp16 hi/lo
__device__ __align__(1024) uint32_t g_AOh[4096*512];                     // fp16 hi

// ---------------------------------------------------------------------------
__device__ __forceinline__ uint32_t f16pack2(float x, float y) {
    __half2 h = __float22half2_rn(make_float2(x, y));
    return *(uint32_t*)&h;
}
__device__ __forceinline__ void f16split2(float x, float y, uint32_t& hi, uint32_t& lo) {
    __half2 h = __float22half2_rn(make_float2(x, y));
    float2 b = __half22float2(h);
    __half2 l = __float22half2_rn(make_float2(x - b.x, y - b.y));
    hi = *(uint32_t*)&h; lo = *(uint32_t*)&l;
}
__device__ __forceinline__ uint32_t smem_u32(const void* p) {
    uint32_t a;
    asm("{ .reg .u64 t; cvta.to.shared.u64 t, %1; cvt.u32.u64 %0, t; }" : "=r"(a) : "l"(p));
    return a;
}
__device__ __forceinline__ void mma16f(float* c, const uint32_t* a, const uint32_t* b) {
    asm("mma.sync.aligned.m16n8k16.row.col.f32.f16.f16.f32 "
        "{%0,%1,%2,%3}, {%4,%5,%6,%7}, {%8,%9}, {%0,%1,%2,%3};"
        : "+f"(c[0]), "+f"(c[1]), "+f"(c[2]), "+f"(c[3])
        : "r"(a[0]), "r"(a[1]), "r"(a[2]), "r"(a[3]), "r"(b[0]), "r"(b[1]));
}
__device__ __forceinline__ void ldmx4(uint32_t* r, uint32_t a) {
    asm volatile("ldmatrix.sync.aligned.m8n8.x4.shared.b16 {%0,%1,%2,%3}, [%4];"
        : "=r"(r[0]), "=r"(r[1]), "=r"(r[2]), "=r"(r[3]) : "r"(a));
}
__device__ __forceinline__ void ldmx4t(uint32_t* r, uint32_t a) {
    asm volatile("ldmatrix.sync.aligned.m8n8.x4.trans.shared.b16 {%0,%1,%2,%3}, [%4];"
        : "=r"(r[0]), "=r"(r[1]), "=r"(r[2]), "=r"(r[3]) : "r"(a));
}
// SW128 swizzle (word offsets), 128B rows (== CU_TENSOR_MAP_SWIZZLE_128B)
__device__ __forceinline__ int sw32(int r, int c) { return r * 32 + 4 * (c ^ (r & 7)); }
// SW64 swizzle (byte offsets), 64B tile rows
__device__ __forceinline__ int swt(int r, int c) { return r * 64 + 16 * (c ^ ((r >> 1) & 3)); }

#define MBAR_INIT(mb, c)  asm volatile("mbarrier.init.shared.b64 [%0], %1;" :: "r"(mb), "r"(c) : "memory")
#define MBAR_EXPECT_TX(mb, n) asm volatile("mbarrier.arrive.expect_tx.shared.b64 _, [%0], %1;" :: "r"(mb), "r"(n) : "memory")
#define MBAR_ARRIVE(mb)   asm volatile("mbarrier.arrive.shared.b64 _, [%0];" :: "r"(mb) : "memory")
__device__ __forceinline__ void mbar_wait(uint32_t mb, uint32_t ph) {
    asm volatile(
        "{ .reg .pred P1;\n"
        "WL_%=: mbarrier.try_wait.parity.acquire.cta.shared::cta.b64 P1, [%0], %1, 0x989680;\n"
        "@P1 bra.uni WD_%=;\n"
        "bra.uni WL_%=;\n"
        "WD_%=: }"
        :: "r"(mb), "r"(ph) : "memory");
}
__device__ __forceinline__ void tma2d(uint32_t smem, const CUtensorMap* m, int x, int y, uint32_t mb) {
    asm volatile("cp.async.bulk.tensor.2d.shared::cta.global.tile.mbarrier::complete_tx::bytes "
                 "[%0], [%1, {%2, %3}], [%4];"
                 :: "r"(smem), "l"(m), "r"(x), "r"(y), "r"(mb) : "memory");
}

// ---------------------------------------------------------------------------
// Fused prep: x -> fp16 hi; Wqkv, Wproj -> fp16 hi/lo.
// blocks [0,4096): x   [4096,7168): Wqkv   [7168,8192): Wproj
// ---------------------------------------------------------------------------
__global__ __launch_bounds__(256)
void split_kernel(const float4* __restrict__ sx, const float4* __restrict__ swq,
                  const float4* __restrict__ swp)
{
    int bid = blockIdx.x;
    if (bid < 4096) {
        int i = bid * 256 + threadIdx.x;
        float4 v = sx[i];
        ((uint2*)g_xh)[i] = make_uint2(f16pack2(v.x, v.y), f16pack2(v.z, v.w));
    } else {
        const float4* src; uint2 *h, *l; int base;
        if (bid < 7168) { src = swq; h = (uint2*)g_Wqh; l = (uint2*)g_Wql; base = bid - 4096; }
        else            { src = swp; h = (uint2*)g_Wph; l = (uint2*)g_Wpl; base = bid - 7168; }
        int i = base * 256 + threadIdx.x;
        float4 v = src[i];
        uint32_t h0, l0, h1, l1;
        f16split2(v.x, v.y, h0, l0);
        f16split2(v.z, v.w, h1, l1);
        h[i] = make_uint2(h0, h1);
        l[i] = make_uint2(l0, l1);
    }
}

// ---------------------------------------------------------------------------
// fp16 2-term GEMM (C = Ah*(Bh+Bl)), TMA-fed, producer-consumer.
// Stage = Ah(8KB) + Bh(8KB) + Bl(8KB) = 24KB, 3 stages.
// MODE 0: epilogue scatters fp16 Q(hi,scaled)/K(hi,lo)/V(hi,lo).
// MODE 1: plain fp32 store to C.
// ---------------------------------------------------------------------------
#define STG_BYTES 24576
#define GEMM_SMEM (1024 + 3*STG_BYTES + 64)

template<int MODE>
__global__ __launch_bounds__(256, 2)
void tc_gemm(const __grid_constant__ CUtensorMap mAh,
             const __grid_constant__ CUtensorMap mBh,
             const __grid_constant__ CUtensorMap mBl,
             const float* __restrict__ bias, float* __restrict__ C)
{
    extern __shared__ __align__(16) uint32_t smu[];
    const uint32_t sbraw = smem_u32(smu);
    const uint32_t sb0 = (sbraw + 1023u) & ~1023u;
    const uint32_t mbF = sb0 + 3 * STG_BYTES;
    const uint32_t mbE = mbF + 24;

    const int tid = threadIdx.x, wid = tid >> 5, lane = tid & 31;
    const int g = lane >> 2, tg = lane & 3;
    const int wm = wid >> 2, wn = wid & 3;
    const int row0 = blockIdx.y * 128, col0 = blockIdx.x * 128;

    const int rA = wm * 64 + (lane & 15);
    const int selA = lane >> 4;
    const int rB = wn * 32 + (lane & 7) + ((lane >> 4) << 3);
    const int selB = (lane >> 3) & 1;

    if (tid == 0) {
#pragma unroll
        for (int s = 0; s < 3; s++) { MBAR_INIT(mbF + s * 8, 1); MBAR_INIT(mbE + s * 8, 8); }
    }
    __syncthreads();

    auto issue = [&](int ch, int st) {
        uint32_t base = sb0 + (uint32_t)st * STG_BYTES;
        uint32_t mb = mbF + st * 8;
        MBAR_EXPECT_TX(mb, STG_BYTES);
        tma2d(base,         &mAh, ch * 64, row0, mb);
        tma2d(base + 8192,  &mBh, ch * 64, col0, mb);
        tma2d(base + 16384, &mBl, ch * 64, col0, mb);
    };
    if (tid == 0) { issue(0, 0); issue(1, 1); issue(2, 2); }

    float c[4][4][4];
#pragma unroll
    for (int mt = 0; mt < 4; mt++)
#pragma unroll
        for (int nt = 0; nt < 4; nt++) {
            c[mt][nt][0] = 0.f; c[mt][nt][1] = 0.f; c[mt][nt][2] = 0.f; c[mt][nt][3] = 0.f;
        }

    for (int ch = 0; ch < 32; ch++) {
        const int st = ch % 3;
        mbar_wait(mbF + st * 8, (uint32_t)((ch / 3) & 1));
        const uint32_t base = sb0 + (uint32_t)st * STG_BYTES;

#pragma unroll
        for (int ks = 0; ks < 2; ks++) {
            const int cA = 2 * ks + selA;
            const int cB = 2 * ks + selB;
            uint32_t ah[4][4], th[2][4], tl[2][4];
#pragma unroll
            for (int mt = 0; mt < 4; mt++)
                ldmx4(ah[mt], base + (uint32_t)swt(rA + mt * 16, cA));
#pragma unroll
            for (int ntp = 0; ntp < 2; ntp++) {
                ldmx4(th[ntp], base + 8192u  + (uint32_t)swt(rB + ntp * 16, cB));
                ldmx4(tl[ntp], base + 16384u + (uint32_t)swt(rB + ntp * 16, cB));
            }
#pragma unroll
            for (int ntp = 0; ntp < 2; ntp++)
#pragma unroll
                for (int mt = 0; mt < 4; mt++) {
                    mma16f(c[mt][2*ntp],   ah[mt], &th[ntp][0]);
                    mma16f(c[mt][2*ntp+1], ah[mt], &th[ntp][2]);
                }
#pragma unroll
            for (int ntp = 0; ntp < 2; ntp++)
#pragma unroll
                for (int mt = 0; mt < 4; mt++) {
                    mma16f(c[mt][2*ntp],   ah[mt], &tl[ntp][0]);
                    mma16f(c[mt][2*ntp+1], ah[mt], &tl[ntp][2]);
                }
        }
        if (lane == 0) MBAR_ARRIVE(mbE + st * 8);
        if (tid == 0 && ch + 3 < 32) {
            mbar_wait(mbE + st * 8, (uint32_t)((ch / 3) & 1));
            issue(ch + 3, st);
        }
    }

    // Epilogue
#pragma unroll
    for (int mt = 0; mt < 4; mt++) {
#pragma unroll
        for (int hf = 0; hf < 2; hf++) {
            int row = row0 + wm * 64 + mt * 16 + g + hf * 8;
#pragma unroll
            for (int nt = 0; nt < 4; nt++) {
                int col = col0 + wn * 32 + nt * 8 + 2 * tg;
                float v0 = c[mt][nt][hf * 2 + 0] + bias[col];
                float v1 = c[mt][nt][hf * 2 + 1] + bias[col + 1];
                if (MODE == 1) {
                    *(float2*)&C[(size_t)row * DIM_ + col] = make_float2(v0, v1);
                } else {
                    int b = row >> 11, n = row & (NSEQ - 1);
                    int which = col >> 10, rem = col & 1023;
                    int h = rem >> 6, d = rem & 63;
                    size_t w = (((size_t)(b * H_ + h)) * NSEQ + n) * 32 + (d >> 1);
                    if (which == 0) {
                        g_Qh[w] = f16pack2(v0 * SCALE_F, v1 * SCALE_F);
                    } else if (which == 1) {
                        f16split2(v0, v1, g_Kh[w], g_Kl[w]);
                    } else {
                        f16split2(v0, v1, g_Vh[w], g_Vl[w]);
                    }
                }
            }
        }
    }
}

// ---------------------------------------------------------------------------
// Flash focal attention: fp16, QK 2-term (Qh only), PV 2-term (P hi with
// 2^-12 prescale; V hi+lo), no online max (unchanged from R14).
// ---------------------------------------------------------------------------
#define FQH 0
#define FKV 4096
#define FKVB 8192
#define FSTG_BYTES 32768
#define FLASH_SMEM (81920 + 64)

__global__ __launch_bounds__(256, 2)
void flash_kernel(const __grid_constant__ CUtensorMap mQh,
                  const __grid_constant__ CUtensorMap mKh,
                  const __grid_constant__ CUtensorMap mKl,
                  const __grid_constant__ CUtensorMap mVh,
                  const __grid_constant__ CUtensorMap mVl,
                  const float* __restrict__ falpha, const float* __restrict__ fgamma)
{
    extern __shared__ __align__(16) uint32_t smu[];
    const uint32_t sb = smem_u32(smu);
    const uint32_t mbQ = sb + 81920, mbF = sb + 81928, mbE = sb + 81944;
    const int tid = threadIdx.x, wid = tid >> 5, lane = tid & 31;
    const int g = lane >> 2, tg = lane & 3;
    const int bh = blockIdx.y, q0 = blockIdx.x * 128;
    const int qb = wid * 16;

    const float gam = fgamma[0], alpha = falpha[0];
    const bool g2 = (gam == 2.0f);

    const int r16 = lane & 15;
    const int sel = lane >> 4;
    const int rK  = (lane & 7) + ((lane >> 4) << 3);
    const int selB = (lane >> 3) & 1;

    if (tid == 0) {
        MBAR_INIT(mbQ, 1);
#pragma unroll
        for (int s = 0; s < 2; s++) { MBAR_INIT(mbF + s * 8, 1); MBAR_INIT(mbE + s * 8, 8); }
    }
    __syncthreads();

    auto issueKV = [&](int ch, int st) {
        uint32_t base = sb + 16384u + (uint32_t)st * FSTG_BYTES;
        uint32_t mb = mbF + st * 8;
        int y = bh * NSEQ + ch * 64;
        MBAR_EXPECT_TX(mb, FSTG_BYTES);
        tma2d(base,          &mKh, 0, y, mb);
        tma2d(base + 8192,   &mKl, 0, y, mb);
        tma2d(base + 16384,  &mVh, 0, y, mb);
        tma2d(base + 24576,  &mVl, 0, y, mb);
    };
    if (tid == 0) {
        MBAR_EXPECT_TX(mbQ, 16384);
        tma2d(sb, &mQh, 0, bh * NSEQ + q0, mbQ);
        issueKV(0, 0);
        issueKV(1, 1);
    }
    mbar_wait(mbQ, 0);

    float o[8][4];
#pragma unroll
    for (int nt = 0; nt < 8; nt++) { o[nt][0] = o[nt][1] = o[nt][2] = o[nt][3] = 0.f; }
    float Z0 = 0.f, Z1 = 0.f, S20 = 0.f, S21 = 0.f;

    for (int ch = 0; ch < 32; ch++) {
        const int st = ch & 1;
        mbar_wait(mbF + st * 8, (uint32_t)((ch >> 1) & 1));
        const uint32_t kvb = FKV + (uint32_t)(st * FKVB);

        // ---- S = Qh (Kh + Kl) ----
        float s[8][4];
#pragma unroll
        for (int nt = 0; nt < 8; nt++) { s[nt][0] = s[nt][1] = s[nt][2] = s[nt][3] = 0.f; }
#pragma unroll
        for (int ks = 0; ks < 4; ks++) {
            const int cA = 2 * ks + sel;
            const int cB = 2 * ks + selB;
            uint32_t qh[4];
            ldmx4(qh, sb + 4u * (uint32_t)(FQH + sw32(qb + r16, cA)));
#pragma unroll
            for (int np = 0; np < 2; np++) {
                const int n0 = np * 2;
                uint32_t th0[4], th1[4], tl0[4], tl1[4];
                ldmx4(th0, sb + 4u * (uint32_t)(kvb + sw32(rK + n0 * 16, cB)));
                ldmx4(th1, sb + 4u * (uint32_t)(kvb + sw32(rK + (n0 + 1) * 16, cB)));
                ldmx4(tl0, sb + 4u * (uint32_t)(kvb + 2048 + sw32(rK + n0 * 16, cB)));
                ldmx4(tl1, sb + 4u * (uint32_t)(kvb + 2048 + sw32(rK + (n0 + 1) * 16, cB)));
                mma16f(s[2*n0],   qh, &th0[0]); mma16f(s[2*n0+1], qh, &th0[2]);
                mma16f(s[2*n0+2], qh, &th1[0]); mma16f(s[2*n0+3], qh, &th1[2]);
                mma16f(s[2*n0],   qh, &tl0[0]); mma16f(s[2*n0+1], qh, &tl0[2]);
                mma16f(s[2*n0+2], qh, &tl1[0]); mma16f(s[2*n0+3], qh, &tl1[2]);
            }
        }

        // ---- weights (no max subtraction; P prescaled by 2^-12) ----
        uint32_t ph[4][4];
        float zp0 = 0.f, zp1 = 0.f, wp0 = 0.f, wp1 = 0.f;
#pragma unroll
        for (int nt = 0; nt < 8; nt++) {
            float e0 = __expf(s[nt][0]), e1 = __expf(s[nt][1]);
            float e2 = __expf(s[nt][2]), e3 = __expf(s[nt][3]);
            zp0 += e0 + e1; zp1 += e2 + e3;
            float w0, w1, w2, w3;
            if (g2) { w0 = e0 * e0; w1 = e1 * e1; w2 = e2 * e2; w3 = e3 * e3; }
            else {
                w0 = __expf(gam * s[nt][0]); w1 = __expf(gam * s[nt][1]);
                w2 = __expf(gam * s[nt][2]); w3 = __expf(gam * s[nt][3]);
            }
            wp0 += w0 + w1; wp1 += w2 + w3;
            const int ks = nt >> 1, off = (nt & 1) * 2;
            ph[ks][off]     = f16pack2(w0 * PSCALE, w1 * PSCALE);
            ph[ks][off + 1] = f16pack2(w2 * PSCALE, w3 * PSCALE);
        }
        Z0 += zp0; Z1 += zp1; S20 += wp0; S21 += wp1;

        // ---- O += Ph (Vh + Vl) ----
#pragma unroll
        for (int ks = 0; ks < 4; ks++) {
            const int k0 = ks * 16;
#pragma unroll
            for (int dp2 = 0; dp2 < 2; dp2++) {
                const int d0 = dp2 * 2;
                uint32_t th0[4], th1[4], tl0[4], tl1[4];
                ldmx4t(th0, sb + 4u * (uint32_t)(kvb + 4096 + sw32(k0 + r16, d0 * 2 + sel)));
                ldmx4t(th1, sb + 4u * (uint32_t)(kvb + 4096 + sw32(k0 + r16, (d0 + 1) * 2 + sel)));
                ldmx4t(tl0, sb + 4u * (uint32_t)(kvb + 6144 + sw32(k0 + r16, d0 * 2 + sel)));
                ldmx4t(tl1, sb + 4u * (uint32_t)(kvb + 6144 + sw32(k0 + r16, (d0 + 1) * 2 + sel)));
                mma16f(o[2*d0],   ph[ks], &th0[0]); mma16f(o[2*d0+1], ph[ks], &th0[2]);
                mma16f(o[2*d0+2], ph[ks], &th1[0]); mma16f(o[2*d0+3], ph[ks], &th1[2]);
                mma16f(o[2*d0],   ph[ks], &tl0[0]); mma16f(o[2*d0+1], ph[ks], &tl0[2]);
                mma16f(o[2*d0+2], ph[ks], &tl1[0]); mma16f(o[2*d0+3], ph[ks], &tl1[2]);
            }
        }

        if (lane == 0) MBAR_ARRIVE(mbE + st * 8);
        if (tid == 0 && ch + 2 < 32) {
            mbar_wait(mbE + st * 8, (uint32_t)((ch >> 1) & 1));
            issueKV(ch + 2, st);
        }
    }

    // ---- final reduce + fp16 AO write (undo 2^-12 prescale via sc) ----
    Z0  += __shfl_xor_sync(0xffffffffu, Z0, 1);  Z0  += __shfl_xor_sync(0xffffffffu, Z0, 2);
    Z1  += __shfl_xor_sync(0xffffffffu, Z1, 1);  Z1  += __shfl_xor_sync(0xffffffffu, Z1, 2);
    S20 += __shfl_xor_sync(0xffffffffu, S20, 1); S20 += __shfl_xor_sync(0xffffffffu, S20, 2);
    S21 += __shfl_xor_sync(0xffffffffu, S21, 1); S21 += __shfl_xor_sync(0xffffffffu, S21, 2);

    float Zg0 = g2 ? Z0 * Z0 : __powf(Z0, gam);
    float Zg1 = g2 ? Z1 * Z1 : __powf(Z1, gam);
    float sc0 = alpha * 4096.0f / (alpha * S20 + 1e-6f * Zg0);
    float sc1 = alpha * 4096.0f / (alpha * S21 + 1e-6f * Zg1);

    const int b = bh >> 4, h = bh & 15;
    const int qA = q0 + qb + g, qB = qA + 8;
#pragma unroll
    for (int nt = 0; nt < 8; nt++) {
        int d = nt * 8 + 2 * tg;
        size_t wA = ((size_t)b * NSEQ + qA) * 512 + ((h * HD_ + d) >> 1);
        size_t wB = ((size_t)b * NSEQ + qB) * 512 + ((h * HD_ + d) >> 1);
        g_AOh[wA] = f16pack2(o[nt][0] * sc0, o[nt][1] * sc0);
        g_AOh[wB] = f16pack2(o[nt][2] * sc1, o[nt][3] * sc1);
    }
}

// ---------------------------------------------------------------------------
typedef CUresult (*EncodeFn)(CUtensorMap*, CUtensorMapDataType, cuuint32_t, void*,
                             const cuuint64_t*, const cuuint64_t*, const cuuint32_t*,
                             const cuuint32_t*, CUtensorMapInterleave, CUtensorMapSwizzle,
                             CUtensorMapL2promotion, CUtensorMapFloatOOBfill);

static void make_map(EncodeFn enc, CUtensorMap* m, void* ptr,
                     unsigned long long rows, unsigned long long row_bytes,
                     unsigned box_w, unsigned box_h, CUtensorMapSwizzle sw) {
    cuuint64_t dims[2]    = {row_bytes, rows};
    cuuint64_t strides[1] = {row_bytes};
    cuuint32_t box[2]     = {box_w, box_h};
    cuuint32_t es[2]      = {1u, 1u};
    enc(m, CU_TENSOR_MAP_DATA_TYPE_UINT8, 2, ptr, dims, strides, box, es,
        CU_TENSOR_MAP_INTERLEAVE_NONE, sw,
        CU_TENSOR_MAP_L2_PROMOTION_L2_128B, CU_TENSOR_MAP_FLOAT_OOB_FILL_NONE);
}

extern "C" void kernel_launch(void* const* d_in, const int* in_sizes, int n_in,
                              void* d_out, int out_size)
{
    const float* x = nullptr, *Wqkv = nullptr, *bqkv = nullptr;
    const float* Wproj = nullptr, *bproj = nullptr, *fa = nullptr, *fg = nullptr;
    for (int i = 0; i < n_in; i++) {
        int sz = in_sizes[i];
        const float* p = (const float*)d_in[i];
        if      (sz == B_*NSEQ*DIM_)   x = p;
        else if (sz == 3*DIM_*DIM_)    Wqkv = p;
        else if (sz == 3*DIM_)         bqkv = p;
        else if (sz == DIM_*DIM_)      Wproj = p;
        else if (sz == DIM_)           bproj = p;
        else if (sz == 1)              { if (!fa) fa = p; else fg = p; }
    }
    float* out = (float*)d_out;

    cudaFuncSetAttribute(tc_gemm<0>,   cudaFuncAttributeMaxDynamicSharedMemorySize, GEMM_SMEM);
    cudaFuncSetAttribute(tc_gemm<1>,   cudaFuncAttributeMaxDynamicSharedMemorySize, GEMM_SMEM);
    cudaFuncSetAttribute(flash_kernel, cudaFuncAttributeMaxDynamicSharedMemorySize, FLASH_SMEM);

    EncodeFn enc = nullptr;
#if CUDART_VERSION >= 12000
    {
        cudaDriverEntryPointQueryResult qr;
        cudaGetDriverEntryPoint("cuTensorMapEncodeTiled", (void**)&enc,
                                cudaEnableDefault, &qr);
    }
#else
    cudaGetDriverEntryPoint("cuTensorMapEncodeTiled", (void**)&enc, cudaEnableDefault);
#endif

    void *p_xh, *p_Wqh, *p_Wql, *p_Wph, *p_Wpl, *p_AOh;
    void *p_Qh, *p_Kh, *p_Kl, *p_Vh, *p_Vl;
    cudaGetSymbolAddress(&p_xh,  g_xh);
    cudaGetSymbolAddress(&p_Wqh, g_Wqh); cudaGetSymbolAddress(&p_Wql, g_Wql);
    cudaGetSymbolAddress(&p_Wph, g_Wph); cudaGetSymbolAddress(&p_Wpl, g_Wpl);
    cudaGetSymbolAddress(&p_AOh, g_AOh);
    cudaGetSymbolAddress(&p_Qh,  g_Qh);
    cudaGetSymbolAddress(&p_Kh,  g_Kh);  cudaGetSymbolAddress(&p_Kl,  g_Kl);
    cudaGetSymbolAddress(&p_Vh,  g_Vh);  cudaGetSymbolAddress(&p_Vl,  g_Vl);

    const unsigned long long KVROWS = (unsigned long long)B_ * H_ * NSEQ;
    CUtensorMap m_xh, m_Wqh, m_Wql, m_Wph, m_Wpl, m_AOh;
    CUtensorMap m_Qh, m_Kh, m_Kl, m_Vh, m_Vl;
    make_map(enc, &m_xh,  p_xh,  4096, 2048, 64, 128, CU_TENSOR_MAP_SWIZZLE_64B);
    make_map(enc, &m_Wqh, p_Wqh, 3072, 2048, 64, 128, CU_TENSOR_MAP_SWIZZLE_64B);
    make_map(enc, &m_Wql, p_Wql, 3072, 2048, 64, 128, CU_TENSOR_MAP_SWIZZLE_64B);
    make_map(enc, &m_Wph, p_Wph, 1024, 2048, 64, 128, CU_TENSOR_MAP_SWIZZLE_64B);
    make_map(enc, &m_Wpl, p_Wpl, 1024, 2048, 64, 128, CU_TENSOR_MAP_SWIZZLE_64B);
    make_map(enc, &m_AOh, p_AOh, 4096, 2048, 64, 128, CU_TENSOR_MAP_SWIZZLE_64B);
    make_map(enc, &m_Qh,  p_Qh,  KVROWS, 128, 128, 128, CU_TENSOR_MAP_SWIZZLE_128B);
    make_map(enc, &m_Kh,  p_Kh,  KVROWS, 128, 128, 64,  CU_TENSOR_MAP_SWIZZLE_128B);
    make_map(enc, &m_Kl,  p_Kl,  KVROWS, 128, 128, 64,  CU_TENSOR_MAP_SWIZZLE_128B);
    make_map(enc, &m_Vh,  p_Vh,  KVROWS, 128, 128, 64,  CU_TENSOR_MAP_SWIZZLE_128B);
    make_map(enc, &m_Vl,  p_Vl,  KVROWS, 128, 128, 64,  CU_TENSOR_MAP_SWIZZLE_128B);

    // 0) Fused split (all fp16)
    split_kernel<<<8192, 256>>>((const float4*)x, (const float4*)Wqkv, (const float4*)Wproj);
    // 1) QKV projection (fp16 2-term) -> fp16 Q(hi,scaled)/K/V
    tc_gemm<0><<<dim3(3*DIM_/128, (B_*NSEQ)/128), 256, GEMM_SMEM>>>(
        m_xh, m_Wqh, m_Wql, bqkv, nullptr);
    // 2) Focal flash attention (fp16 2-term) -> fp16 AO
    flash_kernel<<<dim3(NSEQ/128, B_*H_), 256, FLASH_SMEM>>>(
        m_Qh, m_Kh, m_Kl, m_Vh, m_Vl, fa, fg);
    // 3) Output projection (fp16 2-term) -> d_out
    tc_gemm<1><<<dim3(DIM_/128, (B_*NSEQ)/128), 256, GEMM_SMEM>>>(
        m_AOh, m_Wph, m_Wpl, bproj, out);
}